// round 7
// baseline (speedup 1.0000x reference)
#include <cuda_runtime.h>
#include <cuda_bf16.h>
#include <math.h>

#define S   512
#define B   128
#define D   300
#define H   512
#define V   50257
#define NBLK 128
#define GNT  512   // GRU threads (16 warps)

// ---------------- device scratch ----------------
__device__ float    g_xn[(size_t)B * S * D];
__device__ float    g_feats[S * B];     // (s, b)
__device__ float    g_ha[H * B];        // dim-major h[d][b]
__device__ float    g_hb[H * B];
__device__ unsigned g_flag[2 * 64 * 8]; // per-(bt,ktg) flag, stride 8 u32

__global__ void reset_flags_kernel() {
    int i = threadIdx.x;
    if (i < 2 * 64 * 8) g_flag[i] = 0u;
}
__global__ void zero_h_kernel() {
    int i = blockIdx.x * blockDim.x + threadIdx.x;
    if (i < H * B) g_ha[i] = 0.0f;
}

// ---------------- helpers ----------------
__device__ __forceinline__ void ffma2(unsigned long long& a,
                                      unsigned long long w,
                                      unsigned long long h) {
    asm("fma.rn.f32x2 %0, %1, %2, %0;" : "+l"(a) : "l"(w), "l"(h));
}
__device__ __forceinline__ unsigned long long dup2(float v) {
    unsigned long long r; unsigned u = __float_as_uint(v);
    asm("mov.b64 %0, {%1, %1};" : "=l"(r) : "r"(u));
    return r;
}
__device__ __forceinline__ float2 unpk(unsigned long long v) {
    unsigned lo, hi;
    asm("mov.b64 {%0, %1}, %2;" : "=r"(lo), "=r"(hi) : "l"(v));
    return make_float2(__uint_as_float(lo), __uint_as_float(hi));
}
__device__ __forceinline__ float sigmoidf_(float x) { return 1.0f / (1.0f + expf(-x)); }

// ---------------- kernel 1: gather + normalize ----------------
__global__ void gather_kernel(const int* __restrict__ ends,
                              const float* __restrict__ emb) {
    int w    = (blockIdx.x * blockDim.x + threadIdx.x) >> 5;
    int lane = threadIdx.x & 31;
    if (w >= S * B) return;
    int s = w >> 7, b = w & 127;
    const float* row = emb + (size_t)ends[s * B + b] * D;
    float v[10]; float ss = 0.0f;
#pragma unroll
    for (int i = 0; i < 10; ++i) {
        int d = lane + 32 * i;
        v[i] = (d < D) ? row[d] : 0.0f;
        ss += v[i] * v[i];
    }
#pragma unroll
    for (int m = 16; m; m >>= 1) ss += __shfl_xor_sync(0xffffffffu, ss, m);
    float inv = 1.0f / fmaxf(sqrtf(ss), 1e-8f);
    float* dst = g_xn + ((size_t)b * S + s) * D;
#pragma unroll
    for (int i = 0; i < 10; ++i) {
        int d = lane + 32 * i;
        if (d < D) dst[d] = v[i] * inv;
    }
}

// ---------------- kernel 2: causal max cosine sims ----------------
#define FP 68
#define FEATS_F (12 * 25 * FP + 2 * 25 * FP)
#define FEATS_SMEM (FEATS_F * 4)

__global__ void feats_kernel() {
    extern __shared__ float fsm[];
    float* At = fsm;
    float* Bt = fsm + 12 * 25 * FP;

    const int it = blockIdx.x, b = blockIdx.y;
    const float* Xb = g_xn + (size_t)b * S * D;
    const int tid = threadIdx.x, tx = tid & 15, ty = tid >> 4;
    const int wa = tid >> 5, lane = tid & 31;
    const int i0 = it * 64;

    if (lane < 25) {
        for (int kc = 0; kc < 12; ++kc)
#pragma unroll
            for (int i = 0; i < 8; ++i) {
                int row = wa * 8 + i;
                At[(kc * 25 + lane) * FP + row] =
                    Xb[(size_t)(i0 + row) * D + kc * 25 + lane];
            }
    }
    float rowmax[4] = { -INFINITY, -INFINITY, -INFINITY, -INFINITY };
    __syncthreads();

    for (int jt = 0; jt <= it; ++jt) {
        const int j0 = jt * 64;
        unsigned long long acc2[4][2];
#pragma unroll
        for (int r = 0; r < 4; ++r) { acc2[r][0] = 0ull; acc2[r][1] = 0ull; }

        if (lane < 25) {
#pragma unroll
            for (int i = 0; i < 8; ++i) {
                int row = wa * 8 + i;
                Bt[lane * FP + row] = Xb[(size_t)(j0 + row) * D + lane];
            }
        }
        __syncthreads();

        for (int kc = 0; kc < 12; ++kc) {
            const float* Bc = Bt + (kc & 1) * (25 * FP);
            if (kc < 11 && lane < 25) {
                float* Bn = Bt + ((kc + 1) & 1) * (25 * FP);
#pragma unroll
                for (int i = 0; i < 8; ++i) {
                    int row = wa * 8 + i;
                    Bn[lane * FP + row] =
                        Xb[(size_t)(j0 + row) * D + (kc + 1) * 25 + lane];
                }
            }
            const float* Ac = At + kc * 25 * FP;
#pragma unroll
            for (int kk = 0; kk < 25; ++kk) {
                const float4 a4 = *(const float4*)(Ac + kk * FP + ty * 4);
                const ulonglong2 cp = *(const ulonglong2*)(Bc + kk * FP + tx * 4);
                const unsigned long long a0 = dup2(a4.x), a1 = dup2(a4.y);
                const unsigned long long a2 = dup2(a4.z), a3 = dup2(a4.w);
                ffma2(acc2[0][0], a0, cp.x); ffma2(acc2[0][1], a0, cp.y);
                ffma2(acc2[1][0], a1, cp.x); ffma2(acc2[1][1], a1, cp.y);
                ffma2(acc2[2][0], a2, cp.x); ffma2(acc2[2][1], a2, cp.y);
                ffma2(acc2[3][0], a3, cp.x); ffma2(acc2[3][1], a3, cp.y);
            }
            __syncthreads();
        }
#pragma unroll
        for (int r = 0; r < 4; ++r) {
            int i = i0 + ty * 4 + r;
            float2 v01 = unpk(acc2[r][0]);
            float2 v23 = unpk(acc2[r][1]);
            int j = j0 + tx * 4;
            if (j + 0 < i) rowmax[r] = fmaxf(rowmax[r], v01.x);
            if (j + 1 < i) rowmax[r] = fmaxf(rowmax[r], v01.y);
            if (j + 2 < i) rowmax[r] = fmaxf(rowmax[r], v23.x);
            if (j + 3 < i) rowmax[r] = fmaxf(rowmax[r], v23.y);
        }
    }
#pragma unroll
    for (int m = 8; m; m >>= 1)
#pragma unroll
        for (int r = 0; r < 4; ++r)
            rowmax[r] = fmaxf(rowmax[r], __shfl_xor_sync(0xffffffffu, rowmax[r], m));
    if (tx == 0)
#pragma unroll
        for (int r = 0; r < 4; ++r) {
            int i = i0 + ty * 4 + r;
            g_feats[i * B + b] = (i == 0) ? 0.0f : rowmax[r];
        }
}

// ---------------- kernel 3: persistent GRU ----------------
// 128 blocks = 64 ktg (8 k) x 2 bt (64 b); 512 threads = 16 warps x 32 dims.
// Producer-consumer flags replace the global barrier: block bumps its flag
// after storing its h slice; each warp polls the 4 flags covering its dims.
#define WS_U64   (512 * 16)
#define PART_U64 (16 * 3 * 4 * 4 * 16)
#define GRU_SMEM ((WS_U64 + PART_U64) * 8)

__global__ void __launch_bounds__(GNT, 1)
gru_persist_kernel(const float* __restrict__ w_hh,
                   const float* __restrict__ w_ih,
                   const float* __restrict__ b_ih,
                   const float* __restrict__ b_hh) {
    extern __shared__ unsigned long long sm64[];
    unsigned long long* ws64 = sm64;            // [d*16 + g*4 + kpg]
    unsigned long long* part = sm64 + WS_U64;

    const int tid  = threadIdx.x;
    const int lane = tid & 31;
    const int w    = tid >> 5;           // warp 0..15 owns dims [w*32, w*32+32)
    const int ktg  = blockIdx.x >> 1;    // 0..63, owns k in [ktg*8, ktg*8+8)
    const int bt   = blockIdx.x & 1;
    const int kh   = lane >> 4;          // k-half 0/1
    const int bq   = lane & 15;          // batch quad

    // ---- one-time: pack W as k-pair f32x2 ----
    for (int i = tid; i < 12 * 512; i += GNT) {
        int gk = i >> 9, d = i & 511;        // gk = g*4 + kpg
        int g = gk >> 2, kpg = gk & 3;
        int k0 = ktg * 8 + kpg * 2;
        float lo = w_hh[((size_t)(g * H + k0)) * H + d];
        float hi = w_hh[((size_t)(g * H + k0 + 1)) * H + d];
        unsigned long long v;
        asm("mov.b64 %0, {%1, %2};" : "=l"(v)
            : "r"(__float_as_uint(lo)), "r"(__float_as_uint(hi)));
        ws64[d * 16 + gk] = v;
    }

    // ---- epilogue constants (tid<256: thread owns k-pair kpl, batch be) ----
    const int kpl  = (tid >> 6) & 3;
    const int bl   = tid & 63;
    const int k0   = ktg * 8 + kpl * 2, k1 = k0 + 1;
    const int be   = bt * 64 + bl;
    const int bi_e = bl & 3, bq_e = bl >> 2;
    const float wir0 = w_ih[k0],         wir1 = w_ih[k1];
    const float wiz0 = w_ih[H + k0],     wiz1 = w_ih[H + k1];
    const float win0 = w_ih[2*H + k0],   win1 = w_ih[2*H + k1];
    const float brr0 = b_ih[k0] + b_hh[k0],         brr1 = b_ih[k1] + b_hh[k1];
    const float bzz0 = b_ih[H + k0] + b_hh[H + k0], bzz1 = b_ih[H + k1] + b_hh[H + k1];
    const float bin0 = b_ih[2*H + k0],   bin1 = b_ih[2*H + k1];
    const float bhn0 = b_hh[2*H + k0],   bhn1 = b_hh[2*H + k1];

    // flags: this block's flag + the 4 this warp consumes
    unsigned* myflag = &g_flag[(bt * 64 + ktg) * 8];
    const unsigned* pollflag =
        &g_flag[(bt * 64 + (w * 4 + (lane & 3))) * 8];

    float o0p = 0.0f, o1p = 0.0f;   // register-held previous outputs (h(t-1))

    __syncthreads();

    for (int t = 0; t < S; ++t) {
        const float* __restrict__ h_in  = (t & 1) ? g_hb : g_ha;
        float*       __restrict__ h_out = (t & 1) ? g_ha : g_hb;

        // prefetch x for this step (independent of flags)
        float x = 0.0f;
        if (tid < 256) x = __ldcg(&g_feats[t * B + be]);

        // ---- wait for this warp's 4 producers to finish step t-1 ----
        if (t > 0) {
            unsigned v;
            do {
                asm volatile("ld.acquire.gpu.global.u32 %0, [%1];"
                             : "=r"(v) : "l"(pollflag) : "memory");
            } while (__any_sync(0xffffffffu, v < (unsigned)t));
        }

        unsigned long long acc[3][2][4];
#pragma unroll
        for (int g = 0; g < 3; ++g)
#pragma unroll
            for (int kp = 0; kp < 2; ++kp)
#pragma unroll
                for (int bi = 0; bi < 4; ++bi) acc[g][kp][bi] = 0ull;

        // ---- main loop: 8 chunks of 4 dims, double-buffered float4 loads ----
        const float* __restrict__ hrow =
            h_in + (size_t)(w * 32) * B + bt * 64 + bq * 4;
        float4 buf[2][4];
#pragma unroll
        for (int j = 0; j < 4; ++j)
            buf[0][j] = __ldcg((const float4*)(hrow + (size_t)j * B));

#pragma unroll
        for (int c = 0; c < 8; ++c) {
            const float4* cur = buf[c & 1];
            float4*       nxt = buf[(c + 1) & 1];
            if (c < 7) {
#pragma unroll
                for (int j = 0; j < 4; ++j)
                    nxt[j] = __ldcg((const float4*)(hrow + (size_t)((c + 1) * 4 + j) * B));
            }
#pragma unroll
            for (int j = 0; j < 4; ++j) {
                const int d = w * 32 + c * 4 + j;
                const unsigned long long h0 = dup2(cur[j].x);
                const unsigned long long h1 = dup2(cur[j].y);
                const unsigned long long h2 = dup2(cur[j].z);
                const unsigned long long h3 = dup2(cur[j].w);
                const ulonglong2* wp = (const ulonglong2*)(ws64 + d * 16 + kh * 2);
#pragma unroll
                for (int g = 0; g < 3; ++g) {
                    const ulonglong2 wv = wp[g * 2];
                    ffma2(acc[g][0][0], wv.x, h0); ffma2(acc[g][0][1], wv.x, h1);
                    ffma2(acc[g][0][2], wv.x, h2); ffma2(acc[g][0][3], wv.x, h3);
                    ffma2(acc[g][1][0], wv.y, h0); ffma2(acc[g][1][1], wv.y, h1);
                    ffma2(acc[g][1][2], wv.y, h2); ffma2(acc[g][1][3], wv.y, h3);
                }
            }
        }

        // ---- partials ----
#pragma unroll
        for (int g = 0; g < 3; ++g)
#pragma unroll
            for (int kp = 0; kp < 2; ++kp)
#pragma unroll
                for (int bi = 0; bi < 4; ++bi)
                    part[(((w * 3 + g) * 4 + (kh * 2 + kp)) * 4 + bi) * 16 + bq] =
                        acc[g][kp][bi];
        __syncthreads();

        if (tid < 256) {
            // ---- reduce across 16 warps with add.f32x2 ----
            unsigned long long ga2[3];
#pragma unroll
            for (int g = 0; g < 3; ++g) {
                unsigned long long s = part[((g * 4 + kpl) * 4 + bi_e) * 16 + bq_e];
#pragma unroll
                for (int ww = 1; ww < 16; ++ww) {
                    unsigned long long p =
                        part[(((ww * 3 + g) * 4 + kpl) * 4 + bi_e) * 16 + bq_e];
                    asm("add.rn.f32x2 %0, %0, %1;" : "+l"(s) : "l"(p));
                }
                ga2[g] = s;
            }
            const float2 gr = unpk(ga2[0]);
            const float2 gz = unpk(ga2[1]);
            const float2 gn = unpk(ga2[2]);

            // ---- epilogue (hold comes from registers) ----
            {
                float r = sigmoidf_(fmaf(x, wir0, brr0) + gr.x);
                float z = sigmoidf_(fmaf(x, wiz0, bzz0) + gz.x);
                float n = tanhf(fmaf(x, win0, bin0) + r * (gn.x + bhn0));
                o0p = (1.0f - z) * n + z * o0p;
                h_out[(size_t)k0 * B + be] = o0p;
            }
            {
                float r = sigmoidf_(fmaf(x, wir1, brr1) + gr.y);
                float z = sigmoidf_(fmaf(x, wiz1, bzz1) + gz.y);
                float n = tanhf(fmaf(x, win1, bin1) + r * (gn.y + bhn1));
                o1p = (1.0f - z) * n + z * o1p;
                h_out[(size_t)k1 * B + be] = o1p;
            }
        }

        // ---- publish this block's slice ----
        if (t < S - 1) {
            __syncthreads();
            if (tid == 0) {
                unsigned one = 1u;
                asm volatile("red.release.gpu.global.add.u32 [%0], %1;"
                             :: "l"(myflag), "r"(one) : "memory");
            }
        }
    }
}

// ---------------- kernel 4: FC head ----------------
__global__ void final_kernel(const float* __restrict__ fcw,
                             const float* __restrict__ fcb,
                             float* __restrict__ out) {
    const float* __restrict__ h = g_ha;   // 512 steps -> last write in g_ha
    int b = threadIdx.x;
    float s = 0.0f;
#pragma unroll 8
    for (int d = 0; d < H; ++d) s += h[d * B + b] * fcw[d];
    out[b] = s + fcb[0];
}

// ---------------- launcher ----------------
extern "C" void kernel_launch(void* const* d_in, const int* in_sizes, int n_in,
                              void* d_out, int out_size) {
    const int*   ends = (const int*)  d_in[1];
    const float* emb  = (const float*)d_in[3];
    const float* w_ih = (const float*)d_in[4];
    const float* w_hh = (const float*)d_in[5];
    const float* b_ih = (const float*)d_in[6];
    const float* b_hh = (const float*)d_in[7];
    const float* fc_w = (const float*)d_in[8];
    const float* fc_b = (const float*)d_in[9];
    float* out = (float*)d_out;

    cudaFuncSetAttribute(gru_persist_kernel,
                         cudaFuncAttributeMaxDynamicSharedMemorySize, GRU_SMEM);
    cudaFuncSetAttribute(feats_kernel,
                         cudaFuncAttributeMaxDynamicSharedMemorySize, FEATS_SMEM);

    reset_flags_kernel<<<1, 1024>>>();
    zero_h_kernel<<<(H * B + 1023) / 1024, 1024>>>();
    gather_kernel<<<(S * B) / 8, 256>>>(ends, emb);
    feats_kernel<<<dim3(8, 128), 256, FEATS_SMEM>>>();
    gru_persist_kernel<<<NBLK, GNT, GRU_SMEM>>>(w_hh, w_ih, b_ih, b_hh);
    final_kernel<<<1, B>>>(fc_w, fc_b, out);
}

// round 8
// speedup vs baseline: 1.4969x; 1.4969x over previous
#include <cuda_runtime.h>
#include <cuda_bf16.h>
#include <math.h>

#define S   512
#define B   128
#define D   300
#define H   512
#define V   50257
#define NBLK 128
#define GNT  512   // GRU threads (16 warps)

// ---------------- device scratch ----------------
__device__ float    g_xn[(size_t)B * S * D];
__device__ float    g_feats[S * B];     // (s, b)
__device__ float    g_ha[H * B];        // dim-major h[d][b]
__device__ float    g_hb[H * B];
__device__ unsigned g_bar2[64];         // [0]: bt=0, [32]: bt=1

__global__ void reset_bar_kernel() { g_bar2[0] = 0u; g_bar2[32] = 0u; }
__global__ void zero_h_kernel() {
    int i = blockIdx.x * blockDim.x + threadIdx.x;
    if (i < H * B) g_ha[i] = 0.0f;
}

// ---------------- helpers ----------------
__device__ __forceinline__ void ffma2(unsigned long long& a,
                                      unsigned long long w,
                                      unsigned long long h) {
    asm("fma.rn.f32x2 %0, %1, %2, %0;" : "+l"(a) : "l"(w), "l"(h));
}
__device__ __forceinline__ unsigned long long dup2(float v) {
    unsigned long long r; unsigned u = __float_as_uint(v);
    asm("mov.b64 %0, {%1, %1};" : "=l"(r) : "r"(u));
    return r;
}
__device__ __forceinline__ float2 unpk(unsigned long long v) {
    unsigned lo, hi;
    asm("mov.b64 {%0, %1}, %2;" : "=r"(lo), "=r"(hi) : "l"(v));
    return make_float2(__uint_as_float(lo), __uint_as_float(hi));
}
__device__ __forceinline__ float sigmoidf_(float x) { return 1.0f / (1.0f + expf(-x)); }

// ---------------- kernel 1: gather + normalize ----------------
__global__ void gather_kernel(const int* __restrict__ ends,
                              const float* __restrict__ emb) {
    int w    = (blockIdx.x * blockDim.x + threadIdx.x) >> 5;
    int lane = threadIdx.x & 31;
    if (w >= S * B) return;
    int s = w >> 7, b = w & 127;
    const float* row = emb + (size_t)ends[s * B + b] * D;
    float v[10]; float ss = 0.0f;
#pragma unroll
    for (int i = 0; i < 10; ++i) {
        int d = lane + 32 * i;
        v[i] = (d < D) ? row[d] : 0.0f;
        ss += v[i] * v[i];
    }
#pragma unroll
    for (int m = 16; m; m >>= 1) ss += __shfl_xor_sync(0xffffffffu, ss, m);
    float inv = 1.0f / fmaxf(sqrtf(ss), 1e-8f);
    float* dst = g_xn + ((size_t)b * S + s) * D;
#pragma unroll
    for (int i = 0; i < 10; ++i) {
        int d = lane + 32 * i;
        if (d < D) dst[d] = v[i] * inv;
    }
}

// ---------------- kernel 2: causal max cosine sims ----------------
#define FP 68
#define FEATS_F (12 * 25 * FP + 2 * 25 * FP)
#define FEATS_SMEM (FEATS_F * 4)

__global__ void feats_kernel() {
    extern __shared__ float fsm[];
    float* At = fsm;
    float* Bt = fsm + 12 * 25 * FP;

    const int it = blockIdx.x, b = blockIdx.y;
    const float* Xb = g_xn + (size_t)b * S * D;
    const int tid = threadIdx.x, tx = tid & 15, ty = tid >> 4;
    const int wa = tid >> 5, lane = tid & 31;
    const int i0 = it * 64;

    if (lane < 25) {
        for (int kc = 0; kc < 12; ++kc)
#pragma unroll
            for (int i = 0; i < 8; ++i) {
                int row = wa * 8 + i;
                At[(kc * 25 + lane) * FP + row] =
                    Xb[(size_t)(i0 + row) * D + kc * 25 + lane];
            }
    }
    float rowmax[4] = { -INFINITY, -INFINITY, -INFINITY, -INFINITY };
    __syncthreads();

    for (int jt = 0; jt <= it; ++jt) {
        const int j0 = jt * 64;
        unsigned long long acc2[4][2];
#pragma unroll
        for (int r = 0; r < 4; ++r) { acc2[r][0] = 0ull; acc2[r][1] = 0ull; }

        if (lane < 25) {
#pragma unroll
            for (int i = 0; i < 8; ++i) {
                int row = wa * 8 + i;
                Bt[lane * FP + row] = Xb[(size_t)(j0 + row) * D + lane];
            }
        }
        __syncthreads();

        for (int kc = 0; kc < 12; ++kc) {
            const float* Bc = Bt + (kc & 1) * (25 * FP);
            if (kc < 11 && lane < 25) {
                float* Bn = Bt + ((kc + 1) & 1) * (25 * FP);
#pragma unroll
                for (int i = 0; i < 8; ++i) {
                    int row = wa * 8 + i;
                    Bn[lane * FP + row] =
                        Xb[(size_t)(j0 + row) * D + (kc + 1) * 25 + lane];
                }
            }
            const float* Ac = At + kc * 25 * FP;
#pragma unroll
            for (int kk = 0; kk < 25; ++kk) {
                const float4 a4 = *(const float4*)(Ac + kk * FP + ty * 4);
                const ulonglong2 cp = *(const ulonglong2*)(Bc + kk * FP + tx * 4);
                const unsigned long long a0 = dup2(a4.x), a1 = dup2(a4.y);
                const unsigned long long a2 = dup2(a4.z), a3 = dup2(a4.w);
                ffma2(acc2[0][0], a0, cp.x); ffma2(acc2[0][1], a0, cp.y);
                ffma2(acc2[1][0], a1, cp.x); ffma2(acc2[1][1], a1, cp.y);
                ffma2(acc2[2][0], a2, cp.x); ffma2(acc2[2][1], a2, cp.y);
                ffma2(acc2[3][0], a3, cp.x); ffma2(acc2[3][1], a3, cp.y);
            }
            __syncthreads();
        }
#pragma unroll
        for (int r = 0; r < 4; ++r) {
            int i = i0 + ty * 4 + r;
            float2 v01 = unpk(acc2[r][0]);
            float2 v23 = unpk(acc2[r][1]);
            int j = j0 + tx * 4;
            if (j + 0 < i) rowmax[r] = fmaxf(rowmax[r], v01.x);
            if (j + 1 < i) rowmax[r] = fmaxf(rowmax[r], v01.y);
            if (j + 2 < i) rowmax[r] = fmaxf(rowmax[r], v23.x);
            if (j + 3 < i) rowmax[r] = fmaxf(rowmax[r], v23.y);
        }
    }
#pragma unroll
    for (int m = 8; m; m >>= 1)
#pragma unroll
        for (int r = 0; r < 4; ++r)
            rowmax[r] = fmaxf(rowmax[r], __shfl_xor_sync(0xffffffffu, rowmax[r], m));
    if (tx == 0)
#pragma unroll
        for (int r = 0; r < 4; ++r) {
            int i = i0 + ty * 4 + r;
            g_feats[i * B + b] = (i == 0) ? 0.0f : rowmax[r];
        }
}

// ---------------- kernel 3: persistent GRU ----------------
// 128 blocks = 64 kt (8 k) x 2 bt (64 b); 512 threads = 16 warps x 32 dims.
// Per-bt global barrier (tid0 only). Register-held previous outputs.
#define WS_U64   (512 * 16)
#define PART_U64 (16 * 3 * 4 * 4 * 16)
#define GRU_SMEM ((WS_U64 + PART_U64) * 8)

__global__ void __launch_bounds__(GNT, 1)
gru_persist_kernel(const float* __restrict__ w_hh,
                   const float* __restrict__ w_ih,
                   const float* __restrict__ b_ih,
                   const float* __restrict__ b_hh) {
    extern __shared__ unsigned long long sm64[];
    unsigned long long* ws64 = sm64;            // [d*16 + g*4 + kpg]
    unsigned long long* part = sm64 + WS_U64;

    const int tid  = threadIdx.x;
    const int lane = tid & 31;
    const int w    = tid >> 5;           // warp 0..15 owns dims [w*32, w*32+32)
    const int kt   = blockIdx.x >> 1;    // 0..63, owns k in [kt*8, kt*8+8)
    const int bt   = blockIdx.x & 1;
    const int kh   = lane >> 4;          // k-half 0/1
    const int bq   = lane & 15;          // batch quad

    // ---- one-time: pack W as k-pair f32x2 ----
    for (int i = tid; i < 12 * 512; i += GNT) {
        int gk = i >> 9, d = i & 511;        // gk = g*4 + kpg
        int g = gk >> 2, kpg = gk & 3;
        int k0 = kt * 8 + kpg * 2;
        float lo = w_hh[((size_t)(g * H + k0)) * H + d];
        float hi = w_hh[((size_t)(g * H + k0 + 1)) * H + d];
        unsigned long long v;
        asm("mov.b64 %0, {%1, %2};" : "=l"(v)
            : "r"(__float_as_uint(lo)), "r"(__float_as_uint(hi)));
        ws64[d * 16 + gk] = v;
    }

    // ---- epilogue constants (tid<256: thread owns k-pair kpl, batch be) ----
    const int kpl  = (tid >> 6) & 3;
    const int bl   = tid & 63;
    const int k0   = kt * 8 + kpl * 2, k1 = k0 + 1;
    const int be   = bt * 64 + bl;
    const int bi_e = bl & 3, bq_e = bl >> 2;
    const float wir0 = w_ih[k0],         wir1 = w_ih[k1];
    const float wiz0 = w_ih[H + k0],     wiz1 = w_ih[H + k1];
    const float win0 = w_ih[2*H + k0],   win1 = w_ih[2*H + k1];
    const float brr0 = b_ih[k0] + b_hh[k0],         brr1 = b_ih[k1] + b_hh[k1];
    const float bzz0 = b_ih[H + k0] + b_hh[H + k0], bzz1 = b_ih[H + k1] + b_hh[H + k1];
    const float bin0 = b_ih[2*H + k0],   bin1 = b_ih[2*H + k1];
    const float bhn0 = b_hh[2*H + k0],   bhn1 = b_hh[2*H + k1];

    unsigned* barp = &g_bar2[bt * 32];
    float o0p = 0.0f, o1p = 0.0f;        // register-held h(t-1) for (k0,be),(k1,be)

    __syncthreads();

    for (int t = 0; t < S; ++t) {
        const float* __restrict__ h_in  = (t & 1) ? g_hb : g_ha;
        float*       __restrict__ h_out = (t & 1) ? g_ha : g_hb;

        // prefetch x (barrier-independent)
        float x = 0.0f;
        if (tid < 256) x = __ldcg(&g_feats[t * B + be]);

        unsigned long long acc[3][2][4];
#pragma unroll
        for (int g = 0; g < 3; ++g)
#pragma unroll
            for (int kp = 0; kp < 2; ++kp)
#pragma unroll
                for (int bi = 0; bi < 4; ++bi) acc[g][kp][bi] = 0ull;

        // ---- main loop: 8 chunks of 4 dims, double-buffered float4 loads ----
        const float* __restrict__ hrow =
            h_in + (size_t)(w * 32) * B + bt * 64 + bq * 4;
        float4 buf[2][4];
#pragma unroll
        for (int j = 0; j < 4; ++j)
            buf[0][j] = __ldcg((const float4*)(hrow + (size_t)j * B));

#pragma unroll
        for (int c = 0; c < 8; ++c) {
            const float4* cur = buf[c & 1];
            float4*       nxt = buf[(c + 1) & 1];
            if (c < 7) {
#pragma unroll
                for (int j = 0; j < 4; ++j)
                    nxt[j] = __ldcg((const float4*)(hrow + (size_t)((c + 1) * 4 + j) * B));
            }
#pragma unroll
            for (int j = 0; j < 4; ++j) {
                const int d = w * 32 + c * 4 + j;
                const unsigned long long h0 = dup2(cur[j].x);
                const unsigned long long h1 = dup2(cur[j].y);
                const unsigned long long h2 = dup2(cur[j].z);
                const unsigned long long h3 = dup2(cur[j].w);
                const ulonglong2* wp = (const ulonglong2*)(ws64 + d * 16 + kh * 2);
#pragma unroll
                for (int g = 0; g < 3; ++g) {
                    const ulonglong2 wv = wp[g * 2];
                    ffma2(acc[g][0][0], wv.x, h0); ffma2(acc[g][0][1], wv.x, h1);
                    ffma2(acc[g][0][2], wv.x, h2); ffma2(acc[g][0][3], wv.x, h3);
                    ffma2(acc[g][1][0], wv.y, h0); ffma2(acc[g][1][1], wv.y, h1);
                    ffma2(acc[g][1][2], wv.y, h2); ffma2(acc[g][1][3], wv.y, h3);
                }
            }
        }

        // ---- partials ----
#pragma unroll
        for (int g = 0; g < 3; ++g)
#pragma unroll
            for (int kp = 0; kp < 2; ++kp)
#pragma unroll
                for (int bi = 0; bi < 4; ++bi)
                    part[(((w * 3 + g) * 4 + (kh * 2 + kp)) * 4 + bi) * 16 + bq] =
                        acc[g][kp][bi];
        __syncthreads();

        if (tid < 256) {
            // ---- reduce across 16 warps with add.f32x2 ----
            unsigned long long ga2[3];
#pragma unroll
            for (int g = 0; g < 3; ++g) {
                unsigned long long s = part[((g * 4 + kpl) * 4 + bi_e) * 16 + bq_e];
#pragma unroll
                for (int ww = 1; ww < 16; ++ww) {
                    unsigned long long p =
                        part[(((ww * 3 + g) * 4 + kpl) * 4 + bi_e) * 16 + bq_e];
                    asm("add.rn.f32x2 %0, %0, %1;" : "+l"(s) : "l"(p));
                }
                ga2[g] = s;
            }
            const float2 gr = unpk(ga2[0]);
            const float2 gz = unpk(ga2[1]);
            const float2 gn = unpk(ga2[2]);

            // ---- epilogue (hold held in registers) ----
            {
                float r = sigmoidf_(fmaf(x, wir0, brr0) + gr.x);
                float z = sigmoidf_(fmaf(x, wiz0, bzz0) + gz.x);
                float n = tanhf(fmaf(x, win0, bin0) + r * (gn.x + bhn0));
                o0p = (1.0f - z) * n + z * o0p;
                h_out[(size_t)k0 * B + be] = o0p;
            }
            {
                float r = sigmoidf_(fmaf(x, wir1, brr1) + gr.y);
                float z = sigmoidf_(fmaf(x, wiz1, bzz1) + gz.y);
                float n = tanhf(fmaf(x, win1, bin1) + r * (gn.y + bhn1));
                o1p = (1.0f - z) * n + z * o1p;
                h_out[(size_t)k1 * B + be] = o1p;
            }
        }

        // ---- per-bt grid barrier: bar.sync + red.release / ld.acquire ----
        if (t < S - 1) {
            __syncthreads();
            if (tid == 0) {
                unsigned one = 1u;
                asm volatile("red.release.gpu.global.add.u32 [%0], %1;"
                             :: "l"(barp), "r"(one) : "memory");
                const unsigned target = (unsigned)(t + 1) * 64u;
                unsigned v;
                do {
                    asm volatile("ld.acquire.gpu.global.u32 %0, [%1];"
                                 : "=r"(v) : "l"(barp) : "memory");
                } while (v < target);
            }
            __syncthreads();
        }
    }
}

// ---------------- kernel 4: FC head ----------------
__global__ void final_kernel(const float* __restrict__ fcw,
                             const float* __restrict__ fcb,
                             float* __restrict__ out) {
    const float* __restrict__ h = g_ha;   // 512 steps -> last write in g_ha
    int b = threadIdx.x;
    float s = 0.0f;
#pragma unroll 8
    for (int d = 0; d < H; ++d) s += h[d * B + b] * fcw[d];
    out[b] = s + fcb[0];
}

// ---------------- launcher ----------------
extern "C" void kernel_launch(void* const* d_in, const int* in_sizes, int n_in,
                              void* d_out, int out_size) {
    const int*   ends = (const int*)  d_in[1];
    const float* emb  = (const float*)d_in[3];
    const float* w_ih = (const float*)d_in[4];
    const float* w_hh = (const float*)d_in[5];
    const float* b_ih = (const float*)d_in[6];
    const float* b_hh = (const float*)d_in[7];
    const float* fc_w = (const float*)d_in[8];
    const float* fc_b = (const float*)d_in[9];
    float* out = (float*)d_out;

    cudaFuncSetAttribute(gru_persist_kernel,
                         cudaFuncAttributeMaxDynamicSharedMemorySize, GRU_SMEM);
    cudaFuncSetAttribute(feats_kernel,
                         cudaFuncAttributeMaxDynamicSharedMemorySize, FEATS_SMEM);

    reset_bar_kernel<<<1, 1>>>();
    zero_h_kernel<<<(H * B + 1023) / 1024, 1024>>>();
    gather_kernel<<<(S * B) / 8, 256>>>(ends, emb);
    feats_kernel<<<dim3(8, 128), 256, FEATS_SMEM>>>();
    gru_persist_kernel<<<NBLK, GNT, GRU_SMEM>>>(w_hh, w_ih, b_ih, b_hh);
    final_kernel<<<1, B>>>(fc_w, fc_b, out);
}

// round 9
// speedup vs baseline: 1.7129x; 1.1444x over previous
#include <cuda_runtime.h>
#include <cuda_bf16.h>
#include <math.h>

#define S   512
#define B   128
#define D   300
#define H   512
#define V   50257
#define NBLK 128
#define GNT  256   // GRU threads (8 warps)

// ---------------- device scratch ----------------
__device__ float    g_xn[(size_t)B * S * D];
__device__ float    g_feats[S * B];     // (s, b)
__device__ unsigned g_featsi[S * B];    // atomic-max keys
__device__ float    g_ha[H * B];        // dim-major h[d][b]
__device__ float    g_hb[H * B];
__device__ unsigned g_bar2[64];         // [0]: bt=0, [32]: bt=1

__global__ void reset_bar_kernel() { g_bar2[0] = 0u; g_bar2[32] = 0u; }
__global__ void zero_h_kernel() {
    int i = blockIdx.x * blockDim.x + threadIdx.x;
    if (i < H * B) g_ha[i] = 0.0f;
}
__global__ void zero_featsi_kernel() {
    int i = blockIdx.x * blockDim.x + threadIdx.x;
    if (i < S * B) g_featsi[i] = 0u;
}

// ---------------- helpers ----------------
__device__ __forceinline__ void ffma2(unsigned long long& a,
                                      unsigned long long w,
                                      unsigned long long h) {
    asm("fma.rn.f32x2 %0, %1, %2, %0;" : "+l"(a) : "l"(w), "l"(h));
}
__device__ __forceinline__ unsigned long long dup2(float v) {
    unsigned long long r; unsigned u = __float_as_uint(v);
    asm("mov.b64 %0, {%1, %1};" : "=l"(r) : "r"(u));
    return r;
}
__device__ __forceinline__ float2 unpk(unsigned long long v) {
    unsigned lo, hi;
    asm("mov.b64 {%0, %1}, %2;" : "=r"(lo), "=r"(hi) : "l"(v));
    return make_float2(__uint_as_float(lo), __uint_as_float(hi));
}
__device__ __forceinline__ float sigmoidf_(float x) { return 1.0f / (1.0f + expf(-x)); }

// monotonic unsigned key for float atomicMax
__device__ __forceinline__ unsigned fkey(float f) {
    unsigned u = __float_as_uint(f);
    return (u & 0x80000000u) ? ~u : (u | 0x80000000u);
}
__device__ __forceinline__ float unkey(unsigned k) {
    unsigned u = (k & 0x80000000u) ? (k & 0x7fffffffu) : ~k;
    return __uint_as_float(u);
}

// ---------------- kernel 1: gather + normalize ----------------
__global__ void gather_kernel(const int* __restrict__ ends,
                              const float* __restrict__ emb) {
    int w    = (blockIdx.x * blockDim.x + threadIdx.x) >> 5;
    int lane = threadIdx.x & 31;
    if (w >= S * B) return;
    int s = w >> 7, b = w & 127;
    const float* row = emb + (size_t)ends[s * B + b] * D;
    float v[10]; float ss = 0.0f;
#pragma unroll
    for (int i = 0; i < 10; ++i) {
        int d = lane + 32 * i;
        v[i] = (d < D) ? row[d] : 0.0f;
        ss += v[i] * v[i];
    }
#pragma unroll
    for (int m = 16; m; m >>= 1) ss += __shfl_xor_sync(0xffffffffu, ss, m);
    float inv = 1.0f / fmaxf(sqrtf(ss), 1e-8f);
    float* dst = g_xn + ((size_t)b * S + s) * D;
#pragma unroll
    for (int i = 0; i < 10; ++i) {
        int d = lane + 32 * i;
        if (d < D) dst[d] = v[i] * inv;
    }
}

// ---------------- kernel 2: causal max cosine sims (flattened tiles) -------
// one block per (it, jt, b) tile-pass; 36 tile pairs x 128 b = 4608 blocks.
#define FP 68
__constant__ int c_it[36] = {0,1,1,2,2,2,3,3,3,3,4,4,4,4,4,5,5,5,5,5,5,
                             6,6,6,6,6,6,6,7,7,7,7,7,7,7,7};
__constant__ int c_jt[36] = {0,0,1,0,1,2,0,1,2,3,0,1,2,3,4,0,1,2,3,4,5,
                             0,1,2,3,4,5,6,0,1,2,3,4,5,6,7};

__global__ void feats_flat_kernel() {
    __shared__ __align__(16) float At[2][25 * FP];
    __shared__ __align__(16) float Bt[2][25 * FP];

    const int idx = blockIdx.x, b = blockIdx.y;
    const int it = c_it[idx], jt = c_jt[idx];
    const float* Xb = g_xn + (size_t)b * S * D;
    const int tid = threadIdx.x, tx = tid & 15, ty = tid >> 4;
    const int wa = tid >> 5, lane = tid & 31;
    const int i0 = it * 64, j0 = jt * 64;

    // prime kc=0
    if (lane < 25) {
#pragma unroll
        for (int i = 0; i < 8; ++i) {
            int row = wa * 8 + i;
            At[0][lane * FP + row] = Xb[(size_t)(i0 + row) * D + lane];
            Bt[0][lane * FP + row] = Xb[(size_t)(j0 + row) * D + lane];
        }
    }
    __syncthreads();

    unsigned long long acc2[4][2];
#pragma unroll
    for (int r = 0; r < 4; ++r) { acc2[r][0] = 0ull; acc2[r][1] = 0ull; }

    for (int kc = 0; kc < 12; ++kc) {
        const int cur = kc & 1;
        if (kc < 11 && lane < 25) {
#pragma unroll
            for (int i = 0; i < 8; ++i) {
                int row = wa * 8 + i;
                At[cur ^ 1][lane * FP + row] =
                    Xb[(size_t)(i0 + row) * D + (kc + 1) * 25 + lane];
                Bt[cur ^ 1][lane * FP + row] =
                    Xb[(size_t)(j0 + row) * D + (kc + 1) * 25 + lane];
            }
        }
#pragma unroll
        for (int kk = 0; kk < 25; ++kk) {
            const float4 a4 = *(const float4*)(&At[cur][kk * FP + ty * 4]);
            const ulonglong2 cp = *(const ulonglong2*)(&Bt[cur][kk * FP + tx * 4]);
            const unsigned long long a0 = dup2(a4.x), a1 = dup2(a4.y);
            const unsigned long long a2 = dup2(a4.z), a3 = dup2(a4.w);
            ffma2(acc2[0][0], a0, cp.x); ffma2(acc2[0][1], a0, cp.y);
            ffma2(acc2[1][0], a1, cp.x); ffma2(acc2[1][1], a1, cp.y);
            ffma2(acc2[2][0], a2, cp.x); ffma2(acc2[2][1], a2, cp.y);
            ffma2(acc2[3][0], a3, cp.x); ffma2(acc2[3][1], a3, cp.y);
        }
        __syncthreads();
    }

    // causal-masked tile row-max
    float rowmax[4] = { -INFINITY, -INFINITY, -INFINITY, -INFINITY };
#pragma unroll
    for (int r = 0; r < 4; ++r) {
        int i = i0 + ty * 4 + r;
        float2 v01 = unpk(acc2[r][0]);
        float2 v23 = unpk(acc2[r][1]);
        int j = j0 + tx * 4;
        if (j + 0 < i) rowmax[r] = fmaxf(rowmax[r], v01.x);
        if (j + 1 < i) rowmax[r] = fmaxf(rowmax[r], v01.y);
        if (j + 2 < i) rowmax[r] = fmaxf(rowmax[r], v23.x);
        if (j + 3 < i) rowmax[r] = fmaxf(rowmax[r], v23.y);
    }
#pragma unroll
    for (int m = 8; m; m >>= 1)
#pragma unroll
        for (int r = 0; r < 4; ++r)
            rowmax[r] = fmaxf(rowmax[r], __shfl_xor_sync(0xffffffffu, rowmax[r], m));
    if (tx == 0) {
#pragma unroll
        for (int r = 0; r < 4; ++r) {
            int i = i0 + ty * 4 + r;
            if (i > 0 && rowmax[r] > -INFINITY)
                atomicMax(&g_featsi[i * B + b], fkey(rowmax[r]));
        }
    }
}

// convert atomic keys -> float feats (row 0 forced to 0)
__global__ void feats_convert_kernel() {
    int i = blockIdx.x * blockDim.x + threadIdx.x;
    if (i < S * B) g_feats[i] = (i < B) ? 0.0f : unkey(g_featsi[i]);
}

// ---------------- kernel 3: persistent GRU (R6 config + micro-opts) --------
// 128 blocks = 64 kt (8 k) x 2 bt (64 b); 256 threads = 8 warps x 64 dims.
#define WS_U64   (512 * 16)
#define PART_U64 (8 * 3 * 4 * 4 * 16)
#define GRU_SMEM ((WS_U64 + PART_U64) * 8)

__global__ void __launch_bounds__(GNT, 1)
gru_persist_kernel(const float* __restrict__ w_hh,
                   const float* __restrict__ w_ih,
                   const float* __restrict__ b_ih,
                   const float* __restrict__ b_hh) {
    extern __shared__ unsigned long long sm64[];
    unsigned long long* ws64 = sm64;            // [d*16 + g*4 + kpg]
    unsigned long long* part = sm64 + WS_U64;

    const int tid  = threadIdx.x;
    const int lane = tid & 31;
    const int w    = tid >> 5;           // warp 0..7 owns dims [w*64, w*64+64)
    const int kt   = blockIdx.x >> 1;    // 0..63, owns k in [kt*8, kt*8+8)
    const int bt   = blockIdx.x & 1;
    const int kh   = lane >> 4;          // k-half 0/1
    const int bq   = lane & 15;          // batch quad

    // ---- one-time: pack W as k-pair f32x2 ----
    for (int i = tid; i < 12 * 512; i += GNT) {
        int gk = i >> 9, d = i & 511;        // gk = g*4 + kpg
        int g = gk >> 2, kpg = gk & 3;
        int k0 = kt * 8 + kpg * 2;
        float lo = w_hh[((size_t)(g * H + k0)) * H + d];
        float hi = w_hh[((size_t)(g * H + k0 + 1)) * H + d];
        unsigned long long v;
        asm("mov.b64 %0, {%1, %2};" : "=l"(v)
            : "r"(__float_as_uint(lo)), "r"(__float_as_uint(hi)));
        ws64[d * 16 + gk] = v;
    }

    // ---- epilogue constants: thread owns k-pair kpl, batch be ----
    const int kpl  = tid >> 6;           // 0..3
    const int bl   = tid & 63;
    const int k0   = kt * 8 + kpl * 2, k1 = k0 + 1;
    const int be   = bt * 64 + bl;
    const int bi_e = bl & 3, bq_e = bl >> 2;
    const float wir0 = w_ih[k0],         wir1 = w_ih[k1];
    const float wiz0 = w_ih[H + k0],     wiz1 = w_ih[H + k1];
    const float win0 = w_ih[2*H + k0],   win1 = w_ih[2*H + k1];
    const float brr0 = b_ih[k0] + b_hh[k0],         brr1 = b_ih[k1] + b_hh[k1];
    const float bzz0 = b_ih[H + k0] + b_hh[H + k0], bzz1 = b_ih[H + k1] + b_hh[H + k1];
    const float bin0 = b_ih[2*H + k0],   bin1 = b_ih[2*H + k1];
    const float bhn0 = b_hh[2*H + k0],   bhn1 = b_hh[2*H + k1];

    unsigned* barp = &g_bar2[bt * 32];
    float o0p = 0.0f, o1p = 0.0f;        // register-held h(t-1) for (k0,be),(k1,be)

    __syncthreads();

    for (int t = 0; t < S; ++t) {
        const float* __restrict__ h_in  = (t & 1) ? g_hb : g_ha;
        float*       __restrict__ h_out = (t & 1) ? g_ha : g_hb;

        // prefetch x (barrier-independent)
        const float x = __ldcg(&g_feats[t * B + be]);

        unsigned long long acc[3][2][4];
#pragma unroll
        for (int g = 0; g < 3; ++g)
#pragma unroll
            for (int kp = 0; kp < 2; ++kp)
#pragma unroll
                for (int bi = 0; bi < 4; ++bi) acc[g][kp][bi] = 0ull;

        // ---- main loop: 16 chunks of 4 dims, double-buffered float4 loads ----
        const float* __restrict__ hrow =
            h_in + (size_t)(w * 64) * B + bt * 64 + bq * 4;
        float4 buf[2][4];
#pragma unroll
        for (int j = 0; j < 4; ++j)
            buf[0][j] = __ldcg((const float4*)(hrow + (size_t)j * B));

#pragma unroll
        for (int c = 0; c < 16; ++c) {
            const float4* cur = buf[c & 1];
            float4*       nxt = buf[(c + 1) & 1];
            if (c < 15) {
#pragma unroll
                for (int j = 0; j < 4; ++j)
                    nxt[j] = __ldcg((const float4*)(hrow + (size_t)((c + 1) * 4 + j) * B));
            }
#pragma unroll
            for (int j = 0; j < 4; ++j) {
                const int d = w * 64 + c * 4 + j;
                const unsigned long long h0 = dup2(cur[j].x);
                const unsigned long long h1 = dup2(cur[j].y);
                const unsigned long long h2 = dup2(cur[j].z);
                const unsigned long long h3 = dup2(cur[j].w);
                const ulonglong2* wp = (const ulonglong2*)(ws64 + d * 16 + kh * 2);
#pragma unroll
                for (int g = 0; g < 3; ++g) {
                    const ulonglong2 wv = wp[g * 2];
                    ffma2(acc[g][0][0], wv.x, h0); ffma2(acc[g][0][1], wv.x, h1);
                    ffma2(acc[g][0][2], wv.x, h2); ffma2(acc[g][0][3], wv.x, h3);
                    ffma2(acc[g][1][0], wv.y, h0); ffma2(acc[g][1][1], wv.y, h1);
                    ffma2(acc[g][1][2], wv.y, h2); ffma2(acc[g][1][3], wv.y, h3);
                }
            }
        }

        // ---- partials ----
#pragma unroll
        for (int g = 0; g < 3; ++g)
#pragma unroll
            for (int kp = 0; kp < 2; ++kp)
#pragma unroll
                for (int bi = 0; bi < 4; ++bi)
                    part[(((w * 3 + g) * 4 + (kh * 2 + kp)) * 4 + bi) * 16 + bq] =
                        acc[g][kp][bi];
        __syncthreads();

        // ---- reduce across 8 warps with add.f32x2 ----
        unsigned long long ga2[3];
#pragma unroll
        for (int g = 0; g < 3; ++g) {
            unsigned long long s = part[((g * 4 + kpl) * 4 + bi_e) * 16 + bq_e];
#pragma unroll
            for (int ww = 1; ww < 8; ++ww) {
                unsigned long long p =
                    part[(((ww * 3 + g) * 4 + kpl) * 4 + bi_e) * 16 + bq_e];
                asm("add.rn.f32x2 %0, %0, %1;" : "+l"(s) : "l"(p));
            }
            ga2[g] = s;
        }
        const float2 gr = unpk(ga2[0]);
        const float2 gz = unpk(ga2[1]);
        const float2 gn = unpk(ga2[2]);

        // ---- epilogue (hold held in registers) ----
        {
            float r = sigmoidf_(fmaf(x, wir0, brr0) + gr.x);
            float z = sigmoidf_(fmaf(x, wiz0, bzz0) + gz.x);
            float n = tanhf(fmaf(x, win0, bin0) + r * (gn.x + bhn0));
            o0p = (1.0f - z) * n + z * o0p;
            h_out[(size_t)k0 * B + be] = o0p;
        }
        {
            float r = sigmoidf_(fmaf(x, wir1, brr1) + gr.y);
            float z = sigmoidf_(fmaf(x, wiz1, bzz1) + gz.y);
            float n = tanhf(fmaf(x, win1, bin1) + r * (gn.y + bhn1));
            o1p = (1.0f - z) * n + z * o1p;
            h_out[(size_t)k1 * B + be] = o1p;
        }

        // ---- per-bt grid barrier ----
        if (t < S - 1) {
            __syncthreads();
            if (tid == 0) {
                unsigned one = 1u;
                asm volatile("red.release.gpu.global.add.u32 [%0], %1;"
                             :: "l"(barp), "r"(one) : "memory");
                const unsigned target = (unsigned)(t + 1) * 64u;
                unsigned v;
                do {
                    asm volatile("ld.acquire.gpu.global.u32 %0, [%1];"
                                 : "=r"(v) : "l"(barp) : "memory");
                } while (v < target);
            }
            __syncthreads();
        }
    }
}

// ---------------- kernel 4: FC head ----------------
__global__ void final_kernel(const float* __restrict__ fcw,
                             const float* __restrict__ fcb,
                             float* __restrict__ out) {
    const float* __restrict__ h = g_ha;   // 512 steps -> last write in g_ha
    int b = threadIdx.x;
    float s = 0.0f;
#pragma unroll 8
    for (int d = 0; d < H; ++d) s += h[d * B + b] * fcw[d];
    out[b] = s + fcb[0];
}

// ---------------- launcher ----------------
extern "C" void kernel_launch(void* const* d_in, const int* in_sizes, int n_in,
                              void* d_out, int out_size) {
    const int*   ends = (const int*)  d_in[1];
    const float* emb  = (const float*)d_in[3];
    const float* w_ih = (const float*)d_in[4];
    const float* w_hh = (const float*)d_in[5];
    const float* b_ih = (const float*)d_in[6];
    const float* b_hh = (const float*)d_in[7];
    const float* fc_w = (const float*)d_in[8];
    const float* fc_b = (const float*)d_in[9];
    float* out = (float*)d_out;

    cudaFuncSetAttribute(gru_persist_kernel,
                         cudaFuncAttributeMaxDynamicSharedMemorySize, GRU_SMEM);

    reset_bar_kernel<<<1, 1>>>();
    zero_h_kernel<<<(H * B + 1023) / 1024, 1024>>>();
    zero_featsi_kernel<<<(S * B + 1023) / 1024, 1024>>>();
    gather_kernel<<<(S * B) / 8, 256>>>(ends, emb);
    feats_flat_kernel<<<dim3(36, 128), 256>>>();
    feats_convert_kernel<<<(S * B + 1023) / 1024, 1024>>>();
    gru_persist_kernel<<<NBLK, GNT, GRU_SMEM>>>(w_hh, w_ih, b_ih, b_hh);
    final_kernel<<<1, B>>>(fc_w, fc_b, out);
}

// round 10
// speedup vs baseline: 1.8155x; 1.0599x over previous
#include <cuda_runtime.h>
#include <cuda_bf16.h>
#include <math.h>

#define S   512
#define B   128
#define D   300
#define H   512
#define V   50257
#define NBLK 128
#define GNT  256   // GRU threads (8 warps)

// ---------------- device scratch ----------------
__device__ float    g_xn[(size_t)B * S * D];
__device__ float    g_feats[S * B];     // (s, b)
__device__ unsigned g_featsi[S * B];    // atomic-max keys
__device__ float    g_ha[H * B];        // dim-major h[d][b]
__device__ float    g_hb[H * B];
__device__ unsigned g_bar4[128];        // 4 groups, stride 32

__global__ void reset_bar_kernel() {
    g_bar4[0] = 0u; g_bar4[32] = 0u; g_bar4[64] = 0u; g_bar4[96] = 0u;
}
__global__ void zero_h_kernel() {
    int i = blockIdx.x * blockDim.x + threadIdx.x;
    if (i < H * B) g_ha[i] = 0.0f;
}
__global__ void zero_featsi_kernel() {
    int i = blockIdx.x * blockDim.x + threadIdx.x;
    if (i < S * B) g_featsi[i] = 0u;
}

// ---------------- helpers ----------------
__device__ __forceinline__ void ffma2(unsigned long long& a,
                                      unsigned long long w,
                                      unsigned long long h) {
    asm("fma.rn.f32x2 %0, %1, %2, %0;" : "+l"(a) : "l"(w), "l"(h));
}
__device__ __forceinline__ unsigned long long dup2(float v) {
    unsigned long long r; unsigned u = __float_as_uint(v);
    asm("mov.b64 %0, {%1, %1};" : "=l"(r) : "r"(u));
    return r;
}
__device__ __forceinline__ float2 unpk(unsigned long long v) {
    unsigned lo, hi;
    asm("mov.b64 {%0, %1}, %2;" : "=r"(lo), "=r"(hi) : "l"(v));
    return make_float2(__uint_as_float(lo), __uint_as_float(hi));
}
__device__ __forceinline__ float sigmoidf_(float x) { return 1.0f / (1.0f + expf(-x)); }

__device__ __forceinline__ unsigned fkey(float f) {
    unsigned u = __float_as_uint(f);
    return (u & 0x80000000u) ? ~u : (u | 0x80000000u);
}
__device__ __forceinline__ float unkey(unsigned k) {
    unsigned u = (k & 0x80000000u) ? (k & 0x7fffffffu) : ~k;
    return __uint_as_float(u);
}

// ---------------- kernel 1: gather + normalize ----------------
__global__ void gather_kernel(const int* __restrict__ ends,
                              const float* __restrict__ emb) {
    int w    = (blockIdx.x * blockDim.x + threadIdx.x) >> 5;
    int lane = threadIdx.x & 31;
    if (w >= S * B) return;
    int s = w >> 7, b = w & 127;
    const float* row = emb + (size_t)ends[s * B + b] * D;
    float v[10]; float ss = 0.0f;
#pragma unroll
    for (int i = 0; i < 10; ++i) {
        int d = lane + 32 * i;
        v[i] = (d < D) ? row[d] : 0.0f;
        ss += v[i] * v[i];
    }
#pragma unroll
    for (int m = 16; m; m >>= 1) ss += __shfl_xor_sync(0xffffffffu, ss, m);
    float inv = 1.0f / fmaxf(sqrtf(ss), 1e-8f);
    float* dst = g_xn + ((size_t)b * S + s) * D;
#pragma unroll
    for (int i = 0; i < 10; ++i) {
        int d = lane + 32 * i;
        if (d < D) dst[d] = v[i] * inv;
    }
}

// ---------------- kernel 2: causal max cosine sims (flattened tiles) -------
#define FP 68
__constant__ int c_it[36] = {0,1,1,2,2,2,3,3,3,3,4,4,4,4,4,5,5,5,5,5,5,
                             6,6,6,6,6,6,6,7,7,7,7,7,7,7,7};
__constant__ int c_jt[36] = {0,0,1,0,1,2,0,1,2,3,0,1,2,3,4,0,1,2,3,4,5,
                             0,1,2,3,4,5,6,0,1,2,3,4,5,6,7};

__global__ void feats_flat_kernel() {
    __shared__ __align__(16) float At[2][25 * FP];
    __shared__ __align__(16) float Bt[2][25 * FP];

    const int idx = blockIdx.x, b = blockIdx.y;
    const int it = c_it[idx], jt = c_jt[idx];
    const float* Xb = g_xn + (size_t)b * S * D;
    const int tid = threadIdx.x, tx = tid & 15, ty = tid >> 4;
    const int wa = tid >> 5, lane = tid & 31;
    const int i0 = it * 64, j0 = jt * 64;

    if (lane < 25) {
#pragma unroll
        for (int i = 0; i < 8; ++i) {
            int row = wa * 8 + i;
            At[0][lane * FP + row] = Xb[(size_t)(i0 + row) * D + lane];
            Bt[0][lane * FP + row] = Xb[(size_t)(j0 + row) * D + lane];
        }
    }
    __syncthreads();

    unsigned long long acc2[4][2];
#pragma unroll
    for (int r = 0; r < 4; ++r) { acc2[r][0] = 0ull; acc2[r][1] = 0ull; }

    for (int kc = 0; kc < 12; ++kc) {
        const int cur = kc & 1;
        if (kc < 11 && lane < 25) {
#pragma unroll
            for (int i = 0; i < 8; ++i) {
                int row = wa * 8 + i;
                At[cur ^ 1][lane * FP + row] =
                    Xb[(size_t)(i0 + row) * D + (kc + 1) * 25 + lane];
                Bt[cur ^ 1][lane * FP + row] =
                    Xb[(size_t)(j0 + row) * D + (kc + 1) * 25 + lane];
            }
        }
#pragma unroll
        for (int kk = 0; kk < 25; ++kk) {
            const float4 a4 = *(const float4*)(&At[cur][kk * FP + ty * 4]);
            const ulonglong2 cp = *(const ulonglong2*)(&Bt[cur][kk * FP + tx * 4]);
            const unsigned long long a0 = dup2(a4.x), a1 = dup2(a4.y);
            const unsigned long long a2 = dup2(a4.z), a3 = dup2(a4.w);
            ffma2(acc2[0][0], a0, cp.x); ffma2(acc2[0][1], a0, cp.y);
            ffma2(acc2[1][0], a1, cp.x); ffma2(acc2[1][1], a1, cp.y);
            ffma2(acc2[2][0], a2, cp.x); ffma2(acc2[2][1], a2, cp.y);
            ffma2(acc2[3][0], a3, cp.x); ffma2(acc2[3][1], a3, cp.y);
        }
        __syncthreads();
    }

    float rowmax[4] = { -INFINITY, -INFINITY, -INFINITY, -INFINITY };
#pragma unroll
    for (int r = 0; r < 4; ++r) {
        int i = i0 + ty * 4 + r;
        float2 v01 = unpk(acc2[r][0]);
        float2 v23 = unpk(acc2[r][1]);
        int j = j0 + tx * 4;
        if (j + 0 < i) rowmax[r] = fmaxf(rowmax[r], v01.x);
        if (j + 1 < i) rowmax[r] = fmaxf(rowmax[r], v01.y);
        if (j + 2 < i) rowmax[r] = fmaxf(rowmax[r], v23.x);
        if (j + 3 < i) rowmax[r] = fmaxf(rowmax[r], v23.y);
    }
#pragma unroll
    for (int m = 8; m; m >>= 1)
#pragma unroll
        for (int r = 0; r < 4; ++r)
            rowmax[r] = fmaxf(rowmax[r], __shfl_xor_sync(0xffffffffu, rowmax[r], m));
    if (tx == 0) {
#pragma unroll
        for (int r = 0; r < 4; ++r) {
            int i = i0 + ty * 4 + r;
            if (i > 0 && rowmax[r] > -INFINITY)
                atomicMax(&g_featsi[i * B + b], fkey(rowmax[r]));
        }
    }
}

__global__ void feats_convert_kernel() {
    int i = blockIdx.x * blockDim.x + threadIdx.x;
    if (i < S * B) g_feats[i] = (i < B) ? 0.0f : unkey(g_featsi[i]);
}

// ---------------- kernel 3: persistent GRU ----------------
// 128 blocks = 32 kt (16 k) x 4 bt (32 b); 256 threads = 8 warps x 64 dims.
// lane: kq = lane>>3 (k-quarter), bq = lane&7 (batch quad).
// Barrier degree 32 per bt-group; 8-dim prefetch chunks (384cyc > L2 RT).
#define WS_U64   (512 * 24)
#define PART_U64 (8 * 3 * 8 * 4 * 8)
#define GRU_SMEM ((WS_U64 + PART_U64) * 8)

__global__ void __launch_bounds__(GNT, 1)
gru_persist_kernel(const float* __restrict__ w_hh,
                   const float* __restrict__ w_ih,
                   const float* __restrict__ b_ih,
                   const float* __restrict__ b_hh) {
    extern __shared__ unsigned long long sm64[];
    unsigned long long* ws64 = sm64;            // [d*24 + g*8 + kp]
    unsigned long long* part = sm64 + WS_U64;

    const int tid  = threadIdx.x;
    const int lane = tid & 31;
    const int w    = tid >> 5;           // warp 0..7 owns dims [w*64, w*64+64)
    const int kt   = blockIdx.x >> 2;    // 0..31, owns k in [kt*16, kt*16+16)
    const int bt   = blockIdx.x & 3;     // 0..3, batches [bt*32, bt*32+32)
    const int kq   = lane >> 3;          // k-quarter 0..3
    const int bq   = lane & 7;           // batch quad 0..7

    // ---- one-time: pack W as k-pair f32x2: ws64[d*24 + g*8 + kp] ----
    for (int i = tid; i < 24 * 512; i += GNT) {
        int gk = i >> 9, d = i & 511;        // gk = g*8 + kp
        int g = gk >> 3, kp = gk & 7;
        int k0 = kt * 16 + kp * 2;
        float lo = w_hh[((size_t)(g * H + k0)) * H + d];
        float hi = w_hh[((size_t)(g * H + k0 + 1)) * H + d];
        unsigned long long v;
        asm("mov.b64 %0, {%1, %2};" : "=l"(v)
            : "r"(__float_as_uint(lo)), "r"(__float_as_uint(hi)));
        ws64[d * 24 + gk] = v;
    }

    // ---- epilogue constants: thread owns k-pair kpe (2 k), batch be ----
    const int kpe  = tid >> 5;           // 0..7
    const int bel  = tid & 31;
    const int k0   = kt * 16 + kpe * 2, k1 = k0 + 1;
    const int be   = bt * 32 + bel;
    const int bi_e = bel & 3, bq_e = bel >> 2;
    const float wir0 = w_ih[k0],         wir1 = w_ih[k1];
    const float wiz0 = w_ih[H + k0],     wiz1 = w_ih[H + k1];
    const float win0 = w_ih[2*H + k0],   win1 = w_ih[2*H + k1];
    const float brr0 = b_ih[k0] + b_hh[k0],         brr1 = b_ih[k1] + b_hh[k1];
    const float bzz0 = b_ih[H + k0] + b_hh[H + k0], bzz1 = b_ih[H + k1] + b_hh[H + k1];
    const float bin0 = b_ih[2*H + k0],   bin1 = b_ih[2*H + k1];
    const float bhn0 = b_hh[2*H + k0],   bhn1 = b_hh[2*H + k1];

    unsigned* barp = &g_bar4[bt * 32];
    float o0p = 0.0f, o1p = 0.0f;        // register-held h(t-1)

    __syncthreads();

    for (int t = 0; t < S; ++t) {
        const float* __restrict__ h_in  = (t & 1) ? g_hb : g_ha;
        float*       __restrict__ h_out = (t & 1) ? g_ha : g_hb;

        // prefetch x (barrier-independent)
        const float x = __ldcg(&g_feats[t * B + be]);

        unsigned long long acc[3][2][4];
#pragma unroll
        for (int g = 0; g < 3; ++g)
#pragma unroll
            for (int kp = 0; kp < 2; ++kp)
#pragma unroll
                for (int bi = 0; bi < 4; ++bi) acc[g][kp][bi] = 0ull;

        // ---- main loop: 8 chunks of 8 dims, double-buffered float4 loads ----
        const float* __restrict__ hrow =
            h_in + (size_t)(w * 64) * B + bt * 32 + bq * 4;
        float4 buf[2][8];
#pragma unroll
        for (int j = 0; j < 8; ++j)
            buf[0][j] = __ldcg((const float4*)(hrow + (size_t)j * B));

#pragma unroll
        for (int c = 0; c < 8; ++c) {
            const float4* cur = buf[c & 1];
            float4*       nxt = buf[(c + 1) & 1];
            if (c < 7) {
#pragma unroll
                for (int j = 0; j < 8; ++j)
                    nxt[j] = __ldcg((const float4*)(hrow + (size_t)((c + 1) * 8 + j) * B));
            }
#pragma unroll
            for (int j = 0; j < 8; ++j) {
                const int d = w * 64 + c * 8 + j;
                const unsigned long long h0 = dup2(cur[j].x);
                const unsigned long long h1 = dup2(cur[j].y);
                const unsigned long long h2 = dup2(cur[j].z);
                const unsigned long long h3 = dup2(cur[j].w);
                const ulonglong2* wp = (const ulonglong2*)(ws64 + d * 24);
#pragma unroll
                for (int g = 0; g < 3; ++g) {
                    const ulonglong2 wv = wp[g * 4 + kq];
                    ffma2(acc[g][0][0], wv.x, h0); ffma2(acc[g][0][1], wv.x, h1);
                    ffma2(acc[g][0][2], wv.x, h2); ffma2(acc[g][0][3], wv.x, h3);
                    ffma2(acc[g][1][0], wv.y, h0); ffma2(acc[g][1][1], wv.y, h1);
                    ffma2(acc[g][1][2], wv.y, h2); ffma2(acc[g][1][3], wv.y, h3);
                }
            }
        }

        // ---- partials: part[((w*3+g)*8 + kq*2+kp)*4 + bi)*8 + bq] ----
#pragma unroll
        for (int g = 0; g < 3; ++g)
#pragma unroll
            for (int kp = 0; kp < 2; ++kp)
#pragma unroll
                for (int bi = 0; bi < 4; ++bi)
                    part[((((w * 3 + g) * 8 + (kq * 2 + kp)) * 4 + bi) * 8) + bq] =
                        acc[g][kp][bi];
        __syncthreads();

        // ---- reduce across 8 warps with add.f32x2 ----
        unsigned long long ga2[3];
#pragma unroll
        for (int g = 0; g < 3; ++g) {
            unsigned long long s =
                part[(((g * 8 + kpe) * 4 + bi_e) * 8) + bq_e];
#pragma unroll
            for (int ww = 1; ww < 8; ++ww) {
                unsigned long long p =
                    part[((((ww * 3 + g) * 8 + kpe) * 4 + bi_e) * 8) + bq_e];
                asm("add.rn.f32x2 %0, %0, %1;" : "+l"(s) : "l"(p));
            }
            ga2[g] = s;
        }
        const float2 gr = unpk(ga2[0]);
        const float2 gz = unpk(ga2[1]);
        const float2 gn = unpk(ga2[2]);

        // ---- epilogue (hold held in registers) ----
        {
            float r = sigmoidf_(fmaf(x, wir0, brr0) + gr.x);
            float z = sigmoidf_(fmaf(x, wiz0, bzz0) + gz.x);
            float n = tanhf(fmaf(x, win0, bin0) + r * (gn.x + bhn0));
            o0p = (1.0f - z) * n + z * o0p;
            h_out[(size_t)k0 * B + be] = o0p;
        }
        {
            float r = sigmoidf_(fmaf(x, wir1, brr1) + gr.y);
            float z = sigmoidf_(fmaf(x, wiz1, bzz1) + gz.y);
            float n = tanhf(fmaf(x, win1, bin1) + r * (gn.y + bhn1));
            o1p = (1.0f - z) * n + z * o1p;
            h_out[(size_t)k1 * B + be] = o1p;
        }

        // ---- per-bt grid barrier (32 blocks) ----
        if (t < S - 1) {
            __syncthreads();
            if (tid == 0) {
                unsigned one = 1u;
                asm volatile("red.release.gpu.global.add.u32 [%0], %1;"
                             :: "l"(barp), "r"(one) : "memory");
                const unsigned target = (unsigned)(t + 1) * 32u;
                unsigned v;
                do {
                    asm volatile("ld.acquire.gpu.global.u32 %0, [%1];"
                                 : "=r"(v) : "l"(barp) : "memory");
                } while (v < target);
            }
            __syncthreads();
        }
    }
}

// ---------------- kernel 4: FC head ----------------
__global__ void final_kernel(const float* __restrict__ fcw,
                             const float* __restrict__ fcb,
                             float* __restrict__ out) {
    const float* __restrict__ h = g_ha;   // 512 steps -> last write in g_ha
    int b = threadIdx.x;
    float s = 0.0f;
#pragma unroll 8
    for (int d = 0; d < H; ++d) s += h[d * B + b] * fcw[d];
    out[b] = s + fcb[0];
}

// ---------------- launcher ----------------
extern "C" void kernel_launch(void* const* d_in, const int* in_sizes, int n_in,
                              void* d_out, int out_size) {
    const int*   ends = (const int*)  d_in[1];
    const float* emb  = (const float*)d_in[3];
    const float* w_ih = (const float*)d_in[4];
    const float* w_hh = (const float*)d_in[5];
    const float* b_ih = (const float*)d_in[6];
    const float* b_hh = (const float*)d_in[7];
    const float* fc_w = (const float*)d_in[8];
    const float* fc_b = (const float*)d_in[9];
    float* out = (float*)d_out;

    cudaFuncSetAttribute(gru_persist_kernel,
                         cudaFuncAttributeMaxDynamicSharedMemorySize, GRU_SMEM);

    reset_bar_kernel<<<1, 1>>>();
    zero_h_kernel<<<(H * B + 1023) / 1024, 1024>>>();
    zero_featsi_kernel<<<(S * B + 1023) / 1024, 1024>>>();
    gather_kernel<<<(S * B) / 8, 256>>>(ends, emb);
    feats_flat_kernel<<<dim3(36, 128), 256>>>();
    feats_convert_kernel<<<(S * B + 1023) / 1024, 1024>>>();
    gru_persist_kernel<<<NBLK, GNT, GRU_SMEM>>>(w_hh, w_ih, b_ih, b_hh);
    final_kernel<<<1, B>>>(fc_w, fc_b, out);
}

// round 11
// speedup vs baseline: 1.8371x; 1.0119x over previous
#include <cuda_runtime.h>
#include <cuda_bf16.h>
#include <math.h>

#define S   512
#define B   128
#define D   300
#define H   512
#define V   50257
#define NBLK 128
#define GNT  256   // GRU threads (8 warps)

// ---------------- device scratch ----------------
__device__ float    g_xn[(size_t)B * S * D];
__device__ float    g_feats[S * B];     // (s, b)
__device__ unsigned g_featsi[S * B];    // atomic-max keys
__device__ float    g_ha[H * B];        // dim-major h[d][b]
__device__ float    g_hb[H * B];
__device__ unsigned g_flagd[NBLK * 32]; // per-block step flag (128B stride)

__global__ void reset_flags_kernel() {
    int i = blockIdx.x * blockDim.x + threadIdx.x;
    if (i < NBLK * 32) g_flagd[i] = 0u;
}
__global__ void zero_h_kernel() {
    int i = blockIdx.x * blockDim.x + threadIdx.x;
    if (i < H * B) g_ha[i] = 0.0f;
}
__global__ void zero_featsi_kernel() {
    int i = blockIdx.x * blockDim.x + threadIdx.x;
    if (i < S * B) g_featsi[i] = 0u;
}

// ---------------- helpers ----------------
__device__ __forceinline__ void ffma2(unsigned long long& a,
                                      unsigned long long w,
                                      unsigned long long h) {
    asm("fma.rn.f32x2 %0, %1, %2, %0;" : "+l"(a) : "l"(w), "l"(h));
}
__device__ __forceinline__ unsigned long long dup2(float v) {
    unsigned long long r; unsigned u = __float_as_uint(v);
    asm("mov.b64 %0, {%1, %1};" : "=l"(r) : "r"(u));
    return r;
}
__device__ __forceinline__ float2 unpk(unsigned long long v) {
    unsigned lo, hi;
    asm("mov.b64 {%0, %1}, %2;" : "=r"(lo), "=r"(hi) : "l"(v));
    return make_float2(__uint_as_float(lo), __uint_as_float(hi));
}
// fast sigmoid: rcp(1 + 2^(-x*log2 e));  MUFU-accurate (~1e-7 rel)
__device__ __forceinline__ float fsig(float x) {
    float e, r;
    asm("ex2.approx.f32 %0, %1;" : "=f"(e) : "f"(x * -1.4426950408889634f));
    asm("rcp.approx.f32 %0, %1;" : "=f"(r) : "f"(e + 1.0f));
    return r;
}
// fast tanh: 1 - 2*rcp(2^(2x*log2 e) + 1);  branch-free, ~1e-6 rel
__device__ __forceinline__ float ftanh(float x) {
    float e, r;
    asm("ex2.approx.f32 %0, %1;" : "=f"(e) : "f"(x * 2.8853900817779268f));
    asm("rcp.approx.f32 %0, %1;" : "=f"(r) : "f"(e + 1.0f));
    return fmaf(-2.0f, r, 1.0f);
}

__device__ __forceinline__ unsigned fkey(float f) {
    unsigned u = __float_as_uint(f);
    return (u & 0x80000000u) ? ~u : (u | 0x80000000u);
}
__device__ __forceinline__ float unkey(unsigned k) {
    unsigned u = (k & 0x80000000u) ? (k & 0x7fffffffu) : ~k;
    return __uint_as_float(u);
}

// ---------------- kernel 1: gather + normalize ----------------
__global__ void gather_kernel(const int* __restrict__ ends,
                              const float* __restrict__ emb) {
    int w    = (blockIdx.x * blockDim.x + threadIdx.x) >> 5;
    int lane = threadIdx.x & 31;
    if (w >= S * B) return;
    int s = w >> 7, b = w & 127;
    const float* row = emb + (size_t)ends[s * B + b] * D;
    float v[10]; float ss = 0.0f;
#pragma unroll
    for (int i = 0; i < 10; ++i) {
        int d = lane + 32 * i;
        v[i] = (d < D) ? row[d] : 0.0f;
        ss += v[i] * v[i];
    }
#pragma unroll
    for (int m = 16; m; m >>= 1) ss += __shfl_xor_sync(0xffffffffu, ss, m);
    float inv = 1.0f / fmaxf(sqrtf(ss), 1e-8f);
    float* dst = g_xn + ((size_t)b * S + s) * D;
#pragma unroll
    for (int i = 0; i < 10; ++i) {
        int d = lane + 32 * i;
        if (d < D) dst[d] = v[i] * inv;
    }
}

// ---------------- kernel 2: causal max cosine sims (flattened tiles) -------
#define FP 68
__constant__ int c_it[36] = {0,1,1,2,2,2,3,3,3,3,4,4,4,4,4,5,5,5,5,5,5,
                             6,6,6,6,6,6,6,7,7,7,7,7,7,7,7};
__constant__ int c_jt[36] = {0,0,1,0,1,2,0,1,2,3,0,1,2,3,4,0,1,2,3,4,5,
                             0,1,2,3,4,5,6,0,1,2,3,4,5,6,7};

__global__ void feats_flat_kernel() {
    __shared__ __align__(16) float At[2][25 * FP];
    __shared__ __align__(16) float Bt[2][25 * FP];

    const int idx = blockIdx.x, b = blockIdx.y;
    const int it = c_it[idx], jt = c_jt[idx];
    const float* Xb = g_xn + (size_t)b * S * D;
    const int tid = threadIdx.x, tx = tid & 15, ty = tid >> 4;
    const int wa = tid >> 5, lane = tid & 31;
    const int i0 = it * 64, j0 = jt * 64;

    if (lane < 25) {
#pragma unroll
        for (int i = 0; i < 8; ++i) {
            int row = wa * 8 + i;
            At[0][lane * FP + row] = Xb[(size_t)(i0 + row) * D + lane];
            Bt[0][lane * FP + row] = Xb[(size_t)(j0 + row) * D + lane];
        }
    }
    __syncthreads();

    unsigned long long acc2[4][2];
#pragma unroll
    for (int r = 0; r < 4; ++r) { acc2[r][0] = 0ull; acc2[r][1] = 0ull; }

    for (int kc = 0; kc < 12; ++kc) {
        const int cur = kc & 1;
        if (kc < 11 && lane < 25) {
#pragma unroll
            for (int i = 0; i < 8; ++i) {
                int row = wa * 8 + i;
                At[cur ^ 1][lane * FP + row] =
                    Xb[(size_t)(i0 + row) * D + (kc + 1) * 25 + lane];
                Bt[cur ^ 1][lane * FP + row] =
                    Xb[(size_t)(j0 + row) * D + (kc + 1) * 25 + lane];
            }
        }
#pragma unroll
        for (int kk = 0; kk < 25; ++kk) {
            const float4 a4 = *(const float4*)(&At[cur][kk * FP + ty * 4]);
            const ulonglong2 cp = *(const ulonglong2*)(&Bt[cur][kk * FP + tx * 4]);
            const unsigned long long a0 = dup2(a4.x), a1 = dup2(a4.y);
            const unsigned long long a2 = dup2(a4.z), a3 = dup2(a4.w);
            ffma2(acc2[0][0], a0, cp.x); ffma2(acc2[0][1], a0, cp.y);
            ffma2(acc2[1][0], a1, cp.x); ffma2(acc2[1][1], a1, cp.y);
            ffma2(acc2[2][0], a2, cp.x); ffma2(acc2[2][1], a2, cp.y);
            ffma2(acc2[3][0], a3, cp.x); ffma2(acc2[3][1], a3, cp.y);
        }
        __syncthreads();
    }

    float rowmax[4] = { -INFINITY, -INFINITY, -INFINITY, -INFINITY };
#pragma unroll
    for (int r = 0; r < 4; ++r) {
        int i = i0 + ty * 4 + r;
        float2 v01 = unpk(acc2[r][0]);
        float2 v23 = unpk(acc2[r][1]);
        int j = j0 + tx * 4;
        if (j + 0 < i) rowmax[r] = fmaxf(rowmax[r], v01.x);
        if (j + 1 < i) rowmax[r] = fmaxf(rowmax[r], v01.y);
        if (j + 2 < i) rowmax[r] = fmaxf(rowmax[r], v23.x);
        if (j + 3 < i) rowmax[r] = fmaxf(rowmax[r], v23.y);
    }
#pragma unroll
    for (int m = 8; m; m >>= 1)
#pragma unroll
        for (int r = 0; r < 4; ++r)
            rowmax[r] = fmaxf(rowmax[r], __shfl_xor_sync(0xffffffffu, rowmax[r], m));
    if (tx == 0) {
#pragma unroll
        for (int r = 0; r < 4; ++r) {
            int i = i0 + ty * 4 + r;
            if (i > 0 && rowmax[r] > -INFINITY)
                atomicMax(&g_featsi[i * B + b], fkey(rowmax[r]));
        }
    }
}

__global__ void feats_convert_kernel() {
    int i = blockIdx.x * blockDim.x + threadIdx.x;
    if (i < S * B) g_feats[i] = (i < B) ? 0.0f : unkey(g_featsi[i]);
}

// ---------------- kernel 3: persistent GRU ----------------
// 128 blocks = 32 kt (16 k) x 4 bt (32 b); 256 threads = 8 warps x 64 dims.
// Distributed-flag step sync: block publishes its own flag (st.release),
// warp 0's 32 lanes each poll one producer flag of the same bt group.
#define WS_U64   (512 * 24)
#define PART_U64 (8 * 3 * 8 * 4 * 8)
#define GRU_SMEM ((WS_U64 + PART_U64) * 8)

__global__ void __launch_bounds__(GNT, 1)
gru_persist_kernel(const float* __restrict__ w_hh,
                   const float* __restrict__ w_ih,
                   const float* __restrict__ b_ih,
                   const float* __restrict__ b_hh) {
    extern __shared__ unsigned long long sm64[];
    unsigned long long* ws64 = sm64;            // [d*24 + g*8 + kp]
    unsigned long long* part = sm64 + WS_U64;

    const int tid  = threadIdx.x;
    const int lane = tid & 31;
    const int w    = tid >> 5;           // warp 0..7 owns dims [w*64, w*64+64)
    const int kt   = blockIdx.x >> 2;    // 0..31, owns k in [kt*16, kt*16+16)
    const int bt   = blockIdx.x & 3;     // 0..3, batches [bt*32, bt*32+32)
    const int kq   = lane >> 3;          // k-quarter 0..3
    const int bq   = lane & 7;           // batch quad 0..7

    // ---- one-time: pack W as k-pair f32x2: ws64[d*24 + g*8 + kp] ----
    for (int i = tid; i < 24 * 512; i += GNT) {
        int gk = i >> 9, d = i & 511;        // gk = g*8 + kp
        int g = gk >> 3, kp = gk & 7;
        int k0 = kt * 16 + kp * 2;
        float lo = w_hh[((size_t)(g * H + k0)) * H + d];
        float hi = w_hh[((size_t)(g * H + k0 + 1)) * H + d];
        unsigned long long v;
        asm("mov.b64 %0, {%1, %2};" : "=l"(v)
            : "r"(__float_as_uint(lo)), "r"(__float_as_uint(hi)));
        ws64[d * 24 + gk] = v;
    }

    // ---- epilogue constants: thread owns k-pair kpe (2 k), batch be ----
    const int kpe  = tid >> 5;           // 0..7
    const int bel  = tid & 31;
    const int k0   = kt * 16 + kpe * 2, k1 = k0 + 1;
    const int be   = bt * 32 + bel;
    const int bi_e = bel & 3, bq_e = bel >> 2;
    const float wir0 = w_ih[k0],         wir1 = w_ih[k1];
    const float wiz0 = w_ih[H + k0],     wiz1 = w_ih[H + k1];
    const float win0 = w_ih[2*H + k0],   win1 = w_ih[2*H + k1];
    const float brr0 = b_ih[k0] + b_hh[k0],         brr1 = b_ih[k1] + b_hh[k1];
    const float bzz0 = b_ih[H + k0] + b_hh[H + k0], bzz1 = b_ih[H + k1] + b_hh[H + k1];
    const float bin0 = b_ih[2*H + k0],   bin1 = b_ih[2*H + k1];
    const float bhn0 = b_hh[2*H + k0],   bhn1 = b_hh[2*H + k1];

    // flags: mine + the one this poll-lane watches (same bt group)
    unsigned* myflag = &g_flagd[blockIdx.x * 32];
    const unsigned* pollp = &g_flagd[((lane << 2) + bt) * 32];

    float o0p = 0.0f, o1p = 0.0f;        // register-held h(t-1)

    __syncthreads();

    for (int t = 0; t < S; ++t) {
        const float* __restrict__ h_in  = (t & 1) ? g_hb : g_ha;
        float*       __restrict__ h_out = (t & 1) ? g_ha : g_hb;

        // prefetch x (barrier-independent)
        const float x = __ldcg(&g_feats[t * B + be]);

        unsigned long long acc[3][2][4];
#pragma unroll
        for (int g = 0; g < 3; ++g)
#pragma unroll
            for (int kp = 0; kp < 2; ++kp)
#pragma unroll
                for (int bi = 0; bi < 4; ++bi) acc[g][kp][bi] = 0ull;

        // ---- main loop: 8 chunks of 8 dims, double-buffered float4 loads ----
        const float* __restrict__ hrow =
            h_in + (size_t)(w * 64) * B + bt * 32 + bq * 4;
        float4 buf[2][8];
#pragma unroll
        for (int j = 0; j < 8; ++j)
            buf[0][j] = __ldcg((const float4*)(hrow + (size_t)j * B));

#pragma unroll
        for (int c = 0; c < 8; ++c) {
            const float4* cur = buf[c & 1];
            float4*       nxt = buf[(c + 1) & 1];
            if (c < 7) {
#pragma unroll
                for (int j = 0; j < 8; ++j)
                    nxt[j] = __ldcg((const float4*)(hrow + (size_t)((c + 1) * 8 + j) * B));
            }
#pragma unroll
            for (int j = 0; j < 8; ++j) {
                const int d = w * 64 + c * 8 + j;
                const unsigned long long h0 = dup2(cur[j].x);
                const unsigned long long h1 = dup2(cur[j].y);
                const unsigned long long h2 = dup2(cur[j].z);
                const unsigned long long h3 = dup2(cur[j].w);
                const ulonglong2* wp = (const ulonglong2*)(ws64 + d * 24);
#pragma unroll
                for (int g = 0; g < 3; ++g) {
                    const ulonglong2 wv = wp[g * 4 + kq];
                    ffma2(acc[g][0][0], wv.x, h0); ffma2(acc[g][0][1], wv.x, h1);
                    ffma2(acc[g][0][2], wv.x, h2); ffma2(acc[g][0][3], wv.x, h3);
                    ffma2(acc[g][1][0], wv.y, h0); ffma2(acc[g][1][1], wv.y, h1);
                    ffma2(acc[g][1][2], wv.y, h2); ffma2(acc[g][1][3], wv.y, h3);
                }
            }
        }

        // ---- partials ----
#pragma unroll
        for (int g = 0; g < 3; ++g)
#pragma unroll
            for (int kp = 0; kp < 2; ++kp)
#pragma unroll
                for (int bi = 0; bi < 4; ++bi)
                    part[((((w * 3 + g) * 8 + (kq * 2 + kp)) * 4 + bi) * 8) + bq] =
                        acc[g][kp][bi];
        __syncthreads();

        // ---- reduce across 8 warps with add.f32x2 ----
        unsigned long long ga2[3];
#pragma unroll
        for (int g = 0; g < 3; ++g) {
            unsigned long long s =
                part[(((g * 8 + kpe) * 4 + bi_e) * 8) + bq_e];
#pragma unroll
            for (int ww = 1; ww < 8; ++ww) {
                unsigned long long p =
                    part[((((ww * 3 + g) * 8 + kpe) * 4 + bi_e) * 8) + bq_e];
                asm("add.rn.f32x2 %0, %0, %1;" : "+l"(s) : "l"(p));
            }
            ga2[g] = s;
        }
        const float2 gr = unpk(ga2[0]);
        const float2 gz = unpk(ga2[1]);
        const float2 gn = unpk(ga2[2]);

        // ---- epilogue (MUFU fast math, hold in registers) ----
        {
            float r = fsig(fmaf(x, wir0, brr0) + gr.x);
            float z = fsig(fmaf(x, wiz0, bzz0) + gz.x);
            float n = ftanh(fmaf(x, win0, bin0) + r * (gn.x + bhn0));
            o0p = (1.0f - z) * n + z * o0p;
            h_out[(size_t)k0 * B + be] = o0p;
        }
        {
            float r = fsig(fmaf(x, wir1, brr1) + gr.y);
            float z = fsig(fmaf(x, wiz1, bzz1) + gz.y);
            float n = ftanh(fmaf(x, win1, bin1) + r * (gn.y + bhn1));
            o1p = (1.0f - z) * n + z * o1p;
            h_out[(size_t)k1 * B + be] = o1p;
        }

        // ---- distributed-flag step sync (degree 32, single-writer flags) ----
        if (t < S - 1) {
            __syncthreads();
            if (tid == 0) {
                asm volatile("st.release.gpu.global.u32 [%0], %1;"
                             :: "l"(myflag), "r"((unsigned)(t + 1)) : "memory");
            }
            if (w == 0) {
                unsigned v;
                do {
                    asm volatile("ld.acquire.gpu.global.u32 %0, [%1];"
                                 : "=r"(v) : "l"(pollp) : "memory");
                } while (__any_sync(0xffffffffu, v < (unsigned)(t + 1)));
            }
            __syncthreads();
        }
    }
}

// ---------------- kernel 4: FC head ----------------
__global__ void final_kernel(const float* __restrict__ fcw,
                             const float* __restrict__ fcb,
                             float* __restrict__ out) {
    const float* __restrict__ h = g_ha;   // 512 steps -> last write in g_ha
    int b = threadIdx.x;
    float s = 0.0f;
#pragma unroll 8
    for (int d = 0; d < H; ++d) s += h[d * B + b] * fcw[d];
    out[b] = s + fcb[0];
}

// ---------------- launcher ----------------
extern "C" void kernel_launch(void* const* d_in, const int* in_sizes, int n_in,
                              void* d_out, int out_size) {
    const int*   ends = (const int*)  d_in[1];
    const float* emb  = (const float*)d_in[3];
    const float* w_ih = (const float*)d_in[4];
    const float* w_hh = (const float*)d_in[5];
    const float* b_ih = (const float*)d_in[6];
    const float* b_hh = (const float*)d_in[7];
    const float* fc_w = (const float*)d_in[8];
    const float* fc_b = (const float*)d_in[9];
    float* out = (float*)d_out;

    cudaFuncSetAttribute(gru_persist_kernel,
                         cudaFuncAttributeMaxDynamicSharedMemorySize, GRU_SMEM);

    reset_flags_kernel<<<4, 1024>>>();
    zero_h_kernel<<<(H * B + 1023) / 1024, 1024>>>();
    zero_featsi_kernel<<<(S * B + 1023) / 1024, 1024>>>();
    gather_kernel<<<(S * B) / 8, 256>>>(ends, emb);
    feats_flat_kernel<<<dim3(36, 128), 256>>>();
    feats_convert_kernel<<<(S * B + 1023) / 1024, 1024>>>();
    gru_persist_kernel<<<NBLK, GNT, GRU_SMEM>>>(w_hh, w_ih, b_ih, b_hh);
    final_kernel<<<1, B>>>(fc_w, fc_b, out);
}

// round 13
// speedup vs baseline: 1.9645x; 1.0694x over previous
#include <cuda_runtime.h>
#include <cuda_bf16.h>
#include <math.h>

#define S   512
#define B   128
#define D   300
#define H   512
#define GNB 128
#define GNT 256

// ---------------- device scratch ----------------
__device__ float    g_xn[(size_t)B * S * D];
__device__ float    g_feats[S * B];
__device__ unsigned g_featsi[S * B];
__device__ float    g_hf[H * B];                        // final h, dim-major
__device__ __align__(16) __nv_bfloat16 g_hhi[2][B * H]; // h hi split, [b][d]
__device__ __align__(16) __nv_bfloat16 g_hlo[2][B * H]; // h lo split
__device__ unsigned g_flagd[GNB * 32];

__global__ void reset_flags_kernel() {
    int i = blockIdx.x * blockDim.x + threadIdx.x;
    if (i < GNB * 32) g_flagd[i] = 0u;
}
__global__ void zero_hbf_kernel() {
    int i = blockIdx.x * blockDim.x + threadIdx.x;
    unsigned* a = (unsigned*)g_hhi;
    unsigned* b = (unsigned*)g_hlo;
    if (i < 65536) a[i] = 0u;
    else if (i < 131072) b[i - 65536] = 0u;
}
__global__ void zero_featsi_kernel() {
    int i = blockIdx.x * blockDim.x + threadIdx.x;
    if (i < S * B) g_featsi[i] = 0u;
}

// ---------------- helpers ----------------
__device__ __forceinline__ void ffma2(unsigned long long& a,
                                      unsigned long long w,
                                      unsigned long long h) {
    asm("fma.rn.f32x2 %0, %1, %2, %0;" : "+l"(a) : "l"(w), "l"(h));
}
__device__ __forceinline__ unsigned long long dup2(float v) {
    unsigned long long r; unsigned u = __float_as_uint(v);
    asm("mov.b64 %0, {%1, %1};" : "=l"(r) : "r"(u));
    return r;
}
__device__ __forceinline__ float2 unpk(unsigned long long v) {
    unsigned lo, hi;
    asm("mov.b64 {%0, %1}, %2;" : "=r"(lo), "=r"(hi) : "l"(v));
    return make_float2(__uint_as_float(lo), __uint_as_float(hi));
}
__device__ __forceinline__ float fsig(float x) {
    float e, r;
    asm("ex2.approx.f32 %0, %1;" : "=f"(e) : "f"(x * -1.4426950408889634f));
    asm("rcp.approx.f32 %0, %1;" : "=f"(r) : "f"(e + 1.0f));
    return r;
}
__device__ __forceinline__ float ftanh(float x) {
    float e, r;
    asm("ex2.approx.f32 %0, %1;" : "=f"(e) : "f"(x * 2.8853900817779268f));
    asm("rcp.approx.f32 %0, %1;" : "=f"(r) : "f"(e + 1.0f));
    return fmaf(-2.0f, r, 1.0f);
}
__device__ __forceinline__ unsigned fkey(float f) {
    unsigned u = __float_as_uint(f);
    return (u & 0x80000000u) ? ~u : (u | 0x80000000u);
}
__device__ __forceinline__ float unkey(unsigned k) {
    unsigned u = (k & 0x80000000u) ? (k & 0x7fffffffu) : ~k;
    return __uint_as_float(u);
}
__device__ __forceinline__ unsigned smem_u32(const void* p) {
    unsigned a;
    asm("{ .reg .u64 t; cvta.to.shared.u64 t, %1; cvt.u32.u64 %0, t; }"
        : "=r"(a) : "l"(p));
    return a;
}
__device__ __forceinline__ void ldsm_x4(unsigned* r, unsigned addr) {
    asm volatile("ldmatrix.sync.aligned.m8n8.x4.shared.b16 {%0,%1,%2,%3}, [%4];"
                 : "=r"(r[0]), "=r"(r[1]), "=r"(r[2]), "=r"(r[3]) : "r"(addr));
}
__device__ __forceinline__ void ldsm_x2(unsigned* r, unsigned addr) {
    asm volatile("ldmatrix.sync.aligned.m8n8.x2.shared.b16 {%0,%1}, [%2];"
                 : "=r"(r[0]), "=r"(r[1]) : "r"(addr));
}
__device__ __forceinline__ void mma_bf16(float* d, const unsigned* a,
                                         const unsigned* b) {
    asm volatile(
        "mma.sync.aligned.m16n8k16.row.col.f32.bf16.bf16.f32 "
        "{%0,%1,%2,%3}, {%4,%5,%6,%7}, {%8,%9}, {%0,%1,%2,%3};"
        : "+f"(d[0]), "+f"(d[1]), "+f"(d[2]), "+f"(d[3])
        : "r"(a[0]), "r"(a[1]), "r"(a[2]), "r"(a[3]), "r"(b[0]), "r"(b[1]));
}

// ---------------- kernel 1: gather + normalize ----------------
__global__ void gather_kernel(const int* __restrict__ ends,
                              const float* __restrict__ emb) {
    int w    = (blockIdx.x * blockDim.x + threadIdx.x) >> 5;
    int lane = threadIdx.x & 31;
    if (w >= S * B) return;
    int s = w >> 7, b = w & 127;
    const float* row = emb + (size_t)ends[s * B + b] * D;
    float v[10]; float ss = 0.0f;
#pragma unroll
    for (int i = 0; i < 10; ++i) {
        int d = lane + 32 * i;
        v[i] = (d < D) ? row[d] : 0.0f;
        ss += v[i] * v[i];
    }
#pragma unroll
    for (int m = 16; m; m >>= 1) ss += __shfl_xor_sync(0xffffffffu, ss, m);
    float inv = 1.0f / fmaxf(sqrtf(ss), 1e-8f);
    float* dst = g_xn + ((size_t)b * S + s) * D;
#pragma unroll
    for (int i = 0; i < 10; ++i) {
        int d = lane + 32 * i;
        if (d < D) dst[d] = v[i] * inv;
    }
}

// ---------------- kernel 2: causal max cosine sims ----------------
#define FP 68
__constant__ int c_it[36] = {0,1,1,2,2,2,3,3,3,3,4,4,4,4,4,5,5,5,5,5,5,
                             6,6,6,6,6,6,6,7,7,7,7,7,7,7,7};
__constant__ int c_jt[36] = {0,0,1,0,1,2,0,1,2,3,0,1,2,3,4,0,1,2,3,4,5,
                             0,1,2,3,4,5,6,0,1,2,3,4,5,6,7};

__global__ void feats_flat_kernel() {
    __shared__ __align__(16) float At[2][25 * FP];
    __shared__ __align__(16) float Bt[2][25 * FP];

    const int idx = blockIdx.x, b = blockIdx.y;
    const int it = c_it[idx], jt = c_jt[idx];
    const float* Xb = g_xn + (size_t)b * S * D;
    const int tid = threadIdx.x, tx = tid & 15, ty = tid >> 4;
    const int wa = tid >> 5, lane = tid & 31;
    const int i0 = it * 64, j0 = jt * 64;

    if (lane < 25) {
#pragma unroll
        for (int i = 0; i < 8; ++i) {
            int row = wa * 8 + i;
            At[0][lane * FP + row] = Xb[(size_t)(i0 + row) * D + lane];
            Bt[0][lane * FP + row] = Xb[(size_t)(j0 + row) * D + lane];
        }
    }
    __syncthreads();

    unsigned long long acc2[4][2];
#pragma unroll
    for (int r = 0; r < 4; ++r) { acc2[r][0] = 0ull; acc2[r][1] = 0ull; }

    for (int kc = 0; kc < 12; ++kc) {
        const int cur = kc & 1;
        if (kc < 11 && lane < 25) {
#pragma unroll
            for (int i = 0; i < 8; ++i) {
                int row = wa * 8 + i;
                At[cur ^ 1][lane * FP + row] =
                    Xb[(size_t)(i0 + row) * D + (kc + 1) * 25 + lane];
                Bt[cur ^ 1][lane * FP + row] =
                    Xb[(size_t)(j0 + row) * D + (kc + 1) * 25 + lane];
            }
        }
#pragma unroll
        for (int kk = 0; kk < 25; ++kk) {
            const float4 a4 = *(const float4*)(&At[cur][kk * FP + ty * 4]);
            const ulonglong2 cp = *(const ulonglong2*)(&Bt[cur][kk * FP + tx * 4]);
            const unsigned long long a0 = dup2(a4.x), a1 = dup2(a4.y);
            const unsigned long long a2 = dup2(a4.z), a3 = dup2(a4.w);
            ffma2(acc2[0][0], a0, cp.x); ffma2(acc2[0][1], a0, cp.y);
            ffma2(acc2[1][0], a1, cp.x); ffma2(acc2[1][1], a1, cp.y);
            ffma2(acc2[2][0], a2, cp.x); ffma2(acc2[2][1], a2, cp.y);
            ffma2(acc2[3][0], a3, cp.x); ffma2(acc2[3][1], a3, cp.y);
        }
        __syncthreads();
    }

    float rowmax[4] = { -INFINITY, -INFINITY, -INFINITY, -INFINITY };
#pragma unroll
    for (int r = 0; r < 4; ++r) {
        int i = i0 + ty * 4 + r;
        float2 v01 = unpk(acc2[r][0]);
        float2 v23 = unpk(acc2[r][1]);
        int j = j0 + tx * 4;
        if (j + 0 < i) rowmax[r] = fmaxf(rowmax[r], v01.x);
        if (j + 1 < i) rowmax[r] = fmaxf(rowmax[r], v01.y);
        if (j + 2 < i) rowmax[r] = fmaxf(rowmax[r], v23.x);
        if (j + 3 < i) rowmax[r] = fmaxf(rowmax[r], v23.y);
    }
#pragma unroll
    for (int m = 8; m; m >>= 1)
#pragma unroll
        for (int r = 0; r < 4; ++r)
            rowmax[r] = fmaxf(rowmax[r], __shfl_xor_sync(0xffffffffu, rowmax[r], m));
    if (tx == 0) {
#pragma unroll
        for (int r = 0; r < 4; ++r) {
            int i = i0 + ty * 4 + r;
            if (i > 0 && rowmax[r] > -INFINITY)
                atomicMax(&g_featsi[i * B + b], fkey(rowmax[r]));
        }
    }
}

__global__ void feats_convert_kernel() {
    int i = blockIdx.x * blockDim.x + threadIdx.x;
    if (i < S * B) g_feats[i] = (i < B) ? 0.0f : unkey(g_featsi[i]);
}

// ---------------- kernel 3: mma.sync persistent GRU ----------------
// 128 blocks = 32 kt (16 k) x 4 bt (32 b); 8 warps split K=512 (64 dims each).
// D[48 = 3g x 16k, 32 b] via m16n8k16 bf16 mma, 2-way bf16 split (3 products).
// smem bytes (all 16B aligned):
#define SW_HI  0u       // W hi: 48 rows x 520 bf16 (1040B stride) = 49920
#define SW_LO  49920u
#define SH_HI  99840u   // h hi: 32 rows x 1040B = 33280
#define SH_LO  133120u
#define SPART  166400u  // partials: 8 w x 48 x 34 f32 = 52224
#define SBIAS  218624u  // 16 k x 8 f32 = 512
#define SMTOT  219136

__global__ void __launch_bounds__(GNT, 1)
gru_mma_kernel(const float* __restrict__ w_hh,
               const float* __restrict__ w_ih,
               const float* __restrict__ b_ih,
               const float* __restrict__ b_hh) {
    extern __shared__ char smem[];
    const unsigned sbase = smem_u32(smem);
    const int tid  = threadIdx.x;
    const int lane = tid & 31;
    const int w    = tid >> 5;
    const int kt   = blockIdx.x >> 2;
    const int bt   = blockIdx.x & 3;
    const int k0   = kt * 16;
    const int b0   = bt * 32;

    // ---- one-time: W pack (48 rows x 512 dims, bf16 hi/lo, padded rows) ----
    for (int i = tid; i < 48 * 512; i += GNT) {
        int row = i >> 9, d = i & 511;
        int g = row >> 4, kl = row & 15;
        float wv = w_hh[((size_t)(g * H + k0 + kl)) * H + d];
        __nv_bfloat16 hi = __float2bfloat16(wv);
        __nv_bfloat16 lo = __float2bfloat16(wv - __bfloat162float(hi));
        *(__nv_bfloat16*)(smem + SW_HI + row * 1040 + d * 2) = hi;
        *(__nv_bfloat16*)(smem + SW_LO + row * 1040 + d * 2) = lo;
    }
    // ---- biases ----
    if (tid < 16) {
        int k = k0 + tid;
        float* bp = (float*)(smem + SBIAS + tid * 32);
        bp[0] = w_ih[k]; bp[1] = w_ih[H + k]; bp[2] = w_ih[2 * H + k];
        bp[3] = b_ih[k] + b_hh[k];
        bp[4] = b_ih[H + k] + b_hh[H + k];
        bp[5] = b_ih[2 * H + k]; bp[6] = b_hh[2 * H + k]; bp[7] = 0.0f;
    }

    // ---- per-lane ldmatrix base offsets ----
    // A (x4): m0 rows0-7@k0, m1 rows8-15@k0, m2 rows0-7@k+8, m3 rows8-15@k+8
    const unsigned a_row = (unsigned)((lane & 7) | (lane & 8));
    const unsigned a_off = a_row * 1040u + (unsigned)(lane >> 4) * 16u;
    // B (x2, non-trans from [b][d] storage): m0 n-rows@k0, m1 n-rows@k+8
    const int l4 = lane & 15;
    const unsigned b_off = (unsigned)(l4 & 7) * 1040u + (unsigned)((l4 >> 3) & 1) * 16u;
    // warp's K-slice starts at dim w*64 -> byte offset w*128
    const unsigned kslice = (unsigned)w * 128u;

    // ---- flags ----
    unsigned* myflag = &g_flagd[blockIdx.x * 32];
    const unsigned* pollp = &g_flagd[((lane << 2) + bt) * 32];

    // ---- epilogue ids ----
    const int kl_e = tid >> 4;          // 0..15
    const int bl_e = tid & 15;          // 0..15 -> 2 batches
    const int be0  = b0 + bl_e * 2;
    float oprev0 = 0.0f, oprev1 = 0.0f;

    __syncthreads();

    for (int t = 0; t < S; ++t) {
        const int sIn  = (t + 1) & 1;
        const int sOut = t & 1;

        const float2 xv = *(const float2*)&g_feats[t * B + be0];

        // ---- wait for producers (warp 0 polls 32 flags) ----
        if (t > 0 && w == 0) {
            unsigned v;
            do {
                asm volatile("ld.acquire.gpu.global.u32 %0, [%1];"
                             : "=r"(v) : "l"(pollp) : "memory");
            } while (__any_sync(0xffffffffu, v < (unsigned)t));
        }
        __syncthreads();

        // ---- stage h(t-1): 32 batches x 512 dims, hi+lo ----
        {
            const __nv_bfloat16* sH = g_hhi[sIn];
            const __nv_bfloat16* sL = g_hlo[sIn];
#pragma unroll
            for (int j = 0; j < 8; ++j) {
                int idx = j * GNT + tid;
                int row = idx >> 6, c16 = idx & 63;
                uint4 vh = *(const uint4*)(sH + (size_t)(b0 + row) * H + c16 * 8);
                *(uint4*)(smem + SH_HI + row * 1040 + c16 * 16) = vh;
                uint4 vl = *(const uint4*)(sL + (size_t)(b0 + row) * H + c16 * 8);
                *(uint4*)(smem + SH_LO + row * 1040 + c16 * 16) = vl;
            }
        }
        __syncthreads();

        // ---- mma over this warp's 64-dim K slice ----
        float acc[3][4][4];
#pragma unroll
        for (int mt = 0; mt < 3; ++mt)
#pragma unroll
            for (int nt = 0; nt < 4; ++nt)
#pragma unroll
                for (int e = 0; e < 4; ++e) acc[mt][nt][e] = 0.0f;

#pragma unroll
        for (int ks = 0; ks < 4; ++ks) {
            const unsigned kb = kslice + (unsigned)ks * 32u;
            unsigned Af[3][2][4];
#pragma unroll
            for (int mt = 0; mt < 3; ++mt) {
                ldsm_x4(Af[mt][0], sbase + SW_HI + (unsigned)mt * 16640u + kb + a_off);
                ldsm_x4(Af[mt][1], sbase + SW_LO + (unsigned)mt * 16640u + kb + a_off);
            }
            unsigned Bf[4][2][2];
#pragma unroll
            for (int nt = 0; nt < 4; ++nt) {
                ldsm_x2(Bf[nt][0], sbase + SH_HI + (unsigned)nt * 8320u + kb + b_off);
                ldsm_x2(Bf[nt][1], sbase + SH_LO + (unsigned)nt * 8320u + kb + b_off);
            }
#pragma unroll
            for (int mt = 0; mt < 3; ++mt)
#pragma unroll
                for (int nt = 0; nt < 4; ++nt) {
                    mma_bf16(acc[mt][nt], Af[mt][0], Bf[nt][0]);  // hi*hi
                    mma_bf16(acc[mt][nt], Af[mt][0], Bf[nt][1]);  // hi*lo
                    mma_bf16(acc[mt][nt], Af[mt][1], Bf[nt][0]);  // lo*hi
                }
        }

        // ---- store partials: part[w][48][34] ----
        {
            float* pw = (float*)(smem + SPART) + w * (48 * 34);
            const int r0 = lane >> 2, c0 = (lane & 3) * 2;
#pragma unroll
            for (int mt = 0; mt < 3; ++mt)
#pragma unroll
                for (int nt = 0; nt < 4; ++nt) {
                    int base = (mt * 16 + r0) * 34 + nt * 8 + c0;
                    pw[base]           = acc[mt][nt][0];
                    pw[base + 1]       = acc[mt][nt][1];
                    pw[base + 8 * 34]      = acc[mt][nt][2];
                    pw[base + 8 * 34 + 1]  = acc[mt][nt][3];
                }
        }
        __syncthreads();

        // ---- reduce 8 warps + epilogue (thread = 1 k x 2 batches) ----
        {
            const float* part = (const float*)(smem + SPART);
            float ga[3][2] = {{0.f,0.f},{0.f,0.f},{0.f,0.f}};
#pragma unroll
            for (int ww = 0; ww < 8; ++ww)
#pragma unroll
                for (int g = 0; g < 3; ++g) {
                    float2 p = *(const float2*)
                        &part[(ww * 48 + g * 16 + kl_e) * 34 + bl_e * 2];
                    ga[g][0] += p.x; ga[g][1] += p.y;
                }

            const float4 c1 = *(const float4*)(smem + SBIAS + kl_e * 32);
            const float4 c2 = *(const float4*)(smem + SBIAS + kl_e * 32 + 16);
            const int k = k0 + kl_e;

            {
                float r = fsig(fmaf(xv.x, c1.x, c1.w) + ga[0][0]);
                float z = fsig(fmaf(xv.x, c1.y, c2.x) + ga[1][0]);
                float n = ftanh(fmaf(xv.x, c1.z, c2.y) + r * (ga[2][0] + c2.z));
                oprev0 = (1.0f - z) * n + z * oprev0;
            }
            {
                float r = fsig(fmaf(xv.y, c1.x, c1.w) + ga[0][1]);
                float z = fsig(fmaf(xv.y, c1.y, c2.x) + ga[1][1]);
                float n = ftanh(fmaf(xv.y, c1.z, c2.y) + r * (ga[2][1] + c2.z));
                oprev1 = (1.0f - z) * n + z * oprev1;
            }
            __nv_bfloat16 h0 = __float2bfloat16(oprev0);
            __nv_bfloat16 l0 = __float2bfloat16(oprev0 - __bfloat162float(h0));
            __nv_bfloat16 h1 = __float2bfloat16(oprev1);
            __nv_bfloat16 l1 = __float2bfloat16(oprev1 - __bfloat162float(h1));
            g_hhi[sOut][(size_t)be0 * H + k]       = h0;
            g_hlo[sOut][(size_t)be0 * H + k]       = l0;
            g_hhi[sOut][(size_t)(be0 + 1) * H + k] = h1;
            g_hlo[sOut][(size_t)(be0 + 1) * H + k] = l1;
            if (t == S - 1) {
                g_hf[k * B + be0]     = oprev0;
                g_hf[k * B + be0 + 1] = oprev1;
            }
        }

        // ---- publish flag ----
        if (t < S - 1) {
            __syncthreads();
            if (tid == 0) {
                asm volatile("st.release.gpu.global.u32 [%0], %1;"
                             :: "l"(myflag), "r"((unsigned)(t + 1)) : "memory");
            }
        }
    }
}

// ---------------- kernel 4: FC head ----------------
__global__ void final_kernel(const float* __restrict__ fcw,
                             const float* __restrict__ fcb,
                             float* __restrict__ out) {
    const float* __restrict__ h = g_hf;
    int b = threadIdx.x;
    float s = 0.0f;
#pragma unroll 8
    for (int d = 0; d < H; ++d) s += h[d * B + b] * fcw[d];
    out[b] = s + fcb[0];
}

// ---------------- launcher ----------------
extern "C" void kernel_launch(void* const* d_in, const int* in_sizes, int n_in,
                              void* d_out, int out_size) {
    const int*   ends = (const int*)  d_in[1];
    const float* emb  = (const float*)d_in[3];
    const float* w_ih = (const float*)d_in[4];
    const float* w_hh = (const float*)d_in[5];
    const float* b_ih = (const float*)d_in[6];
    const float* b_hh = (const float*)d_in[7];
    const float* fc_w = (const float*)d_in[8];
    const float* fc_b = (const float*)d_in[9];
    float* out = (float*)d_out;

    cudaFuncSetAttribute(gru_mma_kernel,
                         cudaFuncAttributeMaxDynamicSharedMemorySize, SMTOT);

    reset_flags_kernel<<<4, 1024>>>();
    zero_hbf_kernel<<<128, 1024>>>();
    zero_featsi_kernel<<<(S * B + 1023) / 1024, 1024>>>();
    gather_kernel<<<(S * B) / 8, 256>>>(ends, emb);
    feats_flat_kernel<<<dim3(36, 128), 256>>>();
    feats_convert_kernel<<<(S * B + 1023) / 1024, 1024>>>();
    gru_mma_kernel<<<GNB, GNT, SMTOT>>>(w_hh, w_ih, b_ih, b_hh);
    final_kernel<<<1, B>>>(fc_w, fc_b, out);
}

// round 14
// speedup vs baseline: 2.0018x; 1.0190x over previous
#include <cuda_runtime.h>
#include <cuda_bf16.h>
#include <math.h>

#define S   512
#define B   128
#define D   300
#define H   512
#define GNB 128
#define GNT 256

// ---------------- device scratch ----------------
__device__ float    g_xn[(size_t)B * S * D];
__device__ float    g_feats[S * B];
__device__ unsigned g_featsi[S * B];
__device__ float    g_hf[H * B];                        // final h, dim-major
__device__ __align__(16) __nv_bfloat16 g_hhi[2][B * H]; // h hi split, [b][d]
__device__ __align__(16) __nv_bfloat16 g_hlo[2][B * H]; // h lo split
__device__ unsigned g_flagd[GNB * 32];

__global__ void reset_flags_kernel() {
    int i = blockIdx.x * blockDim.x + threadIdx.x;
    if (i < GNB * 32) g_flagd[i] = 0u;
}
__global__ void zero_hbf_kernel() {
    int i = blockIdx.x * blockDim.x + threadIdx.x;
    unsigned* a = (unsigned*)g_hhi;
    unsigned* b = (unsigned*)g_hlo;
    if (i < 65536) a[i] = 0u;
    else if (i < 131072) b[i - 65536] = 0u;
}
__global__ void zero_featsi_kernel() {
    int i = blockIdx.x * blockDim.x + threadIdx.x;
    if (i < S * B) g_featsi[i] = 0u;
}

// ---------------- helpers ----------------
__device__ __forceinline__ void ffma2(unsigned long long& a,
                                      unsigned long long w,
                                      unsigned long long h) {
    asm("fma.rn.f32x2 %0, %1, %2, %0;" : "+l"(a) : "l"(w), "l"(h));
}
__device__ __forceinline__ unsigned long long dup2(float v) {
    unsigned long long r; unsigned u = __float_as_uint(v);
    asm("mov.b64 %0, {%1, %1};" : "=l"(r) : "r"(u));
    return r;
}
__device__ __forceinline__ float2 unpk(unsigned long long v) {
    unsigned lo, hi;
    asm("mov.b64 {%0, %1}, %2;" : "=r"(lo), "=r"(hi) : "l"(v));
    return make_float2(__uint_as_float(lo), __uint_as_float(hi));
}
__device__ __forceinline__ float fsig(float x) {
    float e, r;
    asm("ex2.approx.f32 %0, %1;" : "=f"(e) : "f"(x * -1.4426950408889634f));
    asm("rcp.approx.f32 %0, %1;" : "=f"(r) : "f"(e + 1.0f));
    return r;
}
__device__ __forceinline__ float ftanh(float x) {
    float e, r;
    asm("ex2.approx.f32 %0, %1;" : "=f"(e) : "f"(x * 2.8853900817779268f));
    asm("rcp.approx.f32 %0, %1;" : "=f"(r) : "f"(e + 1.0f));
    return fmaf(-2.0f, r, 1.0f);
}
__device__ __forceinline__ unsigned fkey(float f) {
    unsigned u = __float_as_uint(f);
    return (u & 0x80000000u) ? ~u : (u | 0x80000000u);
}
__device__ __forceinline__ float unkey(unsigned k) {
    unsigned u = (k & 0x80000000u) ? (k & 0x7fffffffu) : ~k;
    return __uint_as_float(u);
}
__device__ __forceinline__ unsigned smem_u32(const void* p) {
    unsigned a;
    asm("{ .reg .u64 t; cvta.to.shared.u64 t, %1; cvt.u32.u64 %0, t; }"
        : "=r"(a) : "l"(p));
    return a;
}
__device__ __forceinline__ void ldsm_x4(unsigned* r, unsigned addr) {
    asm volatile("ldmatrix.sync.aligned.m8n8.x4.shared.b16 {%0,%1,%2,%3}, [%4];"
                 : "=r"(r[0]), "=r"(r[1]), "=r"(r[2]), "=r"(r[3]) : "r"(addr));
}
__device__ __forceinline__ void ldsm_x2(unsigned* r, unsigned addr) {
    asm volatile("ldmatrix.sync.aligned.m8n8.x2.shared.b16 {%0,%1}, [%2];"
                 : "=r"(r[0]), "=r"(r[1]) : "r"(addr));
}
__device__ __forceinline__ void mma_bf16(float* d, const unsigned* a,
                                         const unsigned* b) {
    asm volatile(
        "mma.sync.aligned.m16n8k16.row.col.f32.bf16.bf16.f32 "
        "{%0,%1,%2,%3}, {%4,%5,%6,%7}, {%8,%9}, {%0,%1,%2,%3};"
        : "+f"(d[0]), "+f"(d[1]), "+f"(d[2]), "+f"(d[3])
        : "r"(a[0]), "r"(a[1]), "r"(a[2]), "r"(a[3]), "r"(b[0]), "r"(b[1]));
}
__device__ __forceinline__ void cp16(unsigned dst, const void* src) {
    asm volatile("cp.async.cg.shared.global [%0], [%1], 16;"
                 :: "r"(dst), "l"(src));
}

// ---------------- kernel 1: gather + normalize ----------------
__global__ void gather_kernel(const int* __restrict__ ends,
                              const float* __restrict__ emb) {
    int w    = (blockIdx.x * blockDim.x + threadIdx.x) >> 5;
    int lane = threadIdx.x & 31;
    if (w >= S * B) return;
    int s = w >> 7, b = w & 127;
    const float* row = emb + (size_t)ends[s * B + b] * D;
    float v[10]; float ss = 0.0f;
#pragma unroll
    for (int i = 0; i < 10; ++i) {
        int d = lane + 32 * i;
        v[i] = (d < D) ? row[d] : 0.0f;
        ss += v[i] * v[i];
    }
#pragma unroll
    for (int m = 16; m; m >>= 1) ss += __shfl_xor_sync(0xffffffffu, ss, m);
    float inv = 1.0f / fmaxf(sqrtf(ss), 1e-8f);
    float* dst = g_xn + ((size_t)b * S + s) * D;
#pragma unroll
    for (int i = 0; i < 10; ++i) {
        int d = lane + 32 * i;
        if (d < D) dst[d] = v[i] * inv;
    }
}

// ---------------- kernel 2: causal max cosine sims ----------------
#define FP 68
__constant__ int c_it[36] = {0,1,1,2,2,2,3,3,3,3,4,4,4,4,4,5,5,5,5,5,5,
                             6,6,6,6,6,6,6,7,7,7,7,7,7,7,7};
__constant__ int c_jt[36] = {0,0,1,0,1,2,0,1,2,3,0,1,2,3,4,0,1,2,3,4,5,
                             0,1,2,3,4,5,6,0,1,2,3,4,5,6,7};

__global__ void feats_flat_kernel() {
    __shared__ __align__(16) float At[2][25 * FP];
    __shared__ __align__(16) float Bt[2][25 * FP];

    const int idx = blockIdx.x, b = blockIdx.y;
    const int it = c_it[idx], jt = c_jt[idx];
    const float* Xb = g_xn + (size_t)b * S * D;
    const int tid = threadIdx.x, tx = tid & 15, ty = tid >> 4;
    const int wa = tid >> 5, lane = tid & 31;
    const int i0 = it * 64, j0 = jt * 64;

    if (lane < 25) {
#pragma unroll
        for (int i = 0; i < 8; ++i) {
            int row = wa * 8 + i;
            At[0][lane * FP + row] = Xb[(size_t)(i0 + row) * D + lane];
            Bt[0][lane * FP + row] = Xb[(size_t)(j0 + row) * D + lane];
        }
    }
    __syncthreads();

    unsigned long long acc2[4][2];
#pragma unroll
    for (int r = 0; r < 4; ++r) { acc2[r][0] = 0ull; acc2[r][1] = 0ull; }

    for (int kc = 0; kc < 12; ++kc) {
        const int cur = kc & 1;
        if (kc < 11 && lane < 25) {
#pragma unroll
            for (int i = 0; i < 8; ++i) {
                int row = wa * 8 + i;
                At[cur ^ 1][lane * FP + row] =
                    Xb[(size_t)(i0 + row) * D + (kc + 1) * 25 + lane];
                Bt[cur ^ 1][lane * FP + row] =
                    Xb[(size_t)(j0 + row) * D + (kc + 1) * 25 + lane];
            }
        }
#pragma unroll
        for (int kk = 0; kk < 25; ++kk) {
            const float4 a4 = *(const float4*)(&At[cur][kk * FP + ty * 4]);
            const ulonglong2 cp = *(const ulonglong2*)(&Bt[cur][kk * FP + tx * 4]);
            const unsigned long long a0 = dup2(a4.x), a1 = dup2(a4.y);
            const unsigned long long a2 = dup2(a4.z), a3 = dup2(a4.w);
            ffma2(acc2[0][0], a0, cp.x); ffma2(acc2[0][1], a0, cp.y);
            ffma2(acc2[1][0], a1, cp.x); ffma2(acc2[1][1], a1, cp.y);
            ffma2(acc2[2][0], a2, cp.x); ffma2(acc2[2][1], a2, cp.y);
            ffma2(acc2[3][0], a3, cp.x); ffma2(acc2[3][1], a3, cp.y);
        }
        __syncthreads();
    }

    float rowmax[4] = { -INFINITY, -INFINITY, -INFINITY, -INFINITY };
#pragma unroll
    for (int r = 0; r < 4; ++r) {
        int i = i0 + ty * 4 + r;
        float2 v01 = unpk(acc2[r][0]);
        float2 v23 = unpk(acc2[r][1]);
        int j = j0 + tx * 4;
        if (j + 0 < i) rowmax[r] = fmaxf(rowmax[r], v01.x);
        if (j + 1 < i) rowmax[r] = fmaxf(rowmax[r], v01.y);
        if (j + 2 < i) rowmax[r] = fmaxf(rowmax[r], v23.x);
        if (j + 3 < i) rowmax[r] = fmaxf(rowmax[r], v23.y);
    }
#pragma unroll
    for (int m = 8; m; m >>= 1)
#pragma unroll
        for (int r = 0; r < 4; ++r)
            rowmax[r] = fmaxf(rowmax[r], __shfl_xor_sync(0xffffffffu, rowmax[r], m));
    if (tx == 0) {
#pragma unroll
        for (int r = 0; r < 4; ++r) {
            int i = i0 + ty * 4 + r;
            if (i > 0 && rowmax[r] > -INFINITY)
                atomicMax(&g_featsi[i * B + b], fkey(rowmax[r]));
        }
    }
}

__global__ void feats_convert_kernel() {
    int i = blockIdx.x * blockDim.x + threadIdx.x;
    if (i < S * B) g_feats[i] = (i < B) ? 0.0f : unkey(g_featsi[i]);
}

// ---------------- kernel 3: mma.sync persistent GRU ----------------
// 128 blocks = 32 kt (16 k) x 4 bt (32 b); 8 warps split K=512 (64 dims each).
// D[48 = 3g x 16k, 32 b] via m16n8k16 bf16 mma, 2-way bf16 split (3 products).
// cp.async staging (no LDG->STS dependency chains).
#define SW_HI  0u       // W hi: 48 rows x 520 bf16 (1040B stride) = 49920
#define SW_LO  49920u
#define SH_HI  99840u   // h hi: 32 rows x 1040B = 33280
#define SH_LO  133120u
#define SPART  166400u  // partials: 8 w x 48 x 34 f32 = 52224
#define SBIAS  218624u  // 16 k x 8 f32 = 512
#define SMTOT  219136

__global__ void __launch_bounds__(GNT, 1)
gru_mma_kernel(const float* __restrict__ w_hh,
               const float* __restrict__ w_ih,
               const float* __restrict__ b_ih,
               const float* __restrict__ b_hh) {
    extern __shared__ char smem[];
    const unsigned sbase = smem_u32(smem);
    const int tid  = threadIdx.x;
    const int lane = tid & 31;
    const int w    = tid >> 5;
    const int kt   = blockIdx.x >> 2;
    const int bt   = blockIdx.x & 3;
    const int k0   = kt * 16;
    const int b0   = bt * 32;

    // ---- one-time: W pack (48 rows x 512 dims, bf16 hi/lo, padded rows) ----
    for (int i = tid; i < 48 * 512; i += GNT) {
        int row = i >> 9, d = i & 511;
        int g = row >> 4, kl = row & 15;
        float wv = w_hh[((size_t)(g * H + k0 + kl)) * H + d];
        __nv_bfloat16 hi = __float2bfloat16(wv);
        __nv_bfloat16 lo = __float2bfloat16(wv - __bfloat162float(hi));
        *(__nv_bfloat16*)(smem + SW_HI + row * 1040 + d * 2) = hi;
        *(__nv_bfloat16*)(smem + SW_LO + row * 1040 + d * 2) = lo;
    }
    // ---- biases ----
    if (tid < 16) {
        int k = k0 + tid;
        float* bp = (float*)(smem + SBIAS + tid * 32);
        bp[0] = w_ih[k]; bp[1] = w_ih[H + k]; bp[2] = w_ih[2 * H + k];
        bp[3] = b_ih[k] + b_hh[k];
        bp[4] = b_ih[H + k] + b_hh[H + k];
        bp[5] = b_ih[2 * H + k]; bp[6] = b_hh[2 * H + k]; bp[7] = 0.0f;
    }

    // ---- per-lane ldmatrix base offsets ----
    const unsigned a_row = (unsigned)((lane & 7) | (lane & 8));
    const unsigned a_off = a_row * 1040u + (unsigned)(lane >> 4) * 16u;
    const int l4 = lane & 15;
    const unsigned b_off = (unsigned)(l4 & 7) * 1040u + (unsigned)((l4 >> 3) & 1) * 16u;
    const unsigned kslice = (unsigned)w * 128u;

    // ---- per-thread staging addresses (chunk-invariant) ----
    // idx = j*256+tid; row = idx>>6, c16 = idx&63
    unsigned st_dst[8];
    unsigned st_src[8];
#pragma unroll
    for (int j = 0; j < 8; ++j) {
        int idx = j * GNT + tid;
        int row = idx >> 6, c16 = idx & 63;
        st_dst[j] = (unsigned)(row * 1040 + c16 * 16);
        st_src[j] = (unsigned)((b0 + row) * H + c16 * 8);
    }

    // ---- flags ----
    unsigned* myflag = &g_flagd[blockIdx.x * 32];
    const unsigned* pollp = &g_flagd[((lane << 2) + bt) * 32];

    // ---- epilogue ids ----
    const int kl_e = tid >> 4;
    const int bl_e = tid & 15;
    const int be0  = b0 + bl_e * 2;
    float oprev0 = 0.0f, oprev1 = 0.0f;

    __syncthreads();

    for (int t = 0; t < S; ++t) {
        const int sIn  = (t + 1) & 1;
        const int sOut = t & 1;

        const float2 xv = *(const float2*)&g_feats[t * B + be0];

        // ---- wait for producers (warp 0 polls 32 flags) ----
        if (t > 0 && w == 0) {
            unsigned v;
            do {
                asm volatile("ld.acquire.gpu.global.u32 %0, [%1];"
                             : "=r"(v) : "l"(pollp) : "memory");
            } while (__any_sync(0xffffffffu, v < (unsigned)t));
        }
        __syncthreads();

        // ---- stage h(t-1) via cp.async (no LDG->STS dependency) ----
        {
            const __nv_bfloat16* sH = g_hhi[sIn];
            const __nv_bfloat16* sL = g_hlo[sIn];
#pragma unroll
            for (int j = 0; j < 8; ++j) {
                cp16(sbase + SH_HI + st_dst[j], sH + st_src[j]);
                cp16(sbase + SH_LO + st_dst[j], sL + st_src[j]);
            }
            asm volatile("cp.async.commit_group;");
            asm volatile("cp.async.wait_group 0;");
        }
        __syncthreads();

        // ---- mma over this warp's 64-dim K slice ----
        float acc[3][4][4];
#pragma unroll
        for (int mt = 0; mt < 3; ++mt)
#pragma unroll
            for (int nt = 0; nt < 4; ++nt)
#pragma unroll
                for (int e = 0; e < 4; ++e) acc[mt][nt][e] = 0.0f;

#pragma unroll
        for (int ks = 0; ks < 4; ++ks) {
            const unsigned kb = kslice + (unsigned)ks * 32u;
            unsigned Af[3][2][4];
#pragma unroll
            for (int mt = 0; mt < 3; ++mt) {
                ldsm_x4(Af[mt][0], sbase + SW_HI + (unsigned)mt * 16640u + kb + a_off);
                ldsm_x4(Af[mt][1], sbase + SW_LO + (unsigned)mt * 16640u + kb + a_off);
            }
            unsigned Bf[4][2][2];
#pragma unroll
            for (int nt = 0; nt < 4; ++nt) {
                ldsm_x2(Bf[nt][0], sbase + SH_HI + (unsigned)nt * 8320u + kb + b_off);
                ldsm_x2(Bf[nt][1], sbase + SH_LO + (unsigned)nt * 8320u + kb + b_off);
            }
#pragma unroll
            for (int mt = 0; mt < 3; ++mt)
#pragma unroll
                for (int nt = 0; nt < 4; ++nt) {
                    mma_bf16(acc[mt][nt], Af[mt][0], Bf[nt][0]);  // hi*hi
                    mma_bf16(acc[mt][nt], Af[mt][0], Bf[nt][1]);  // hi*lo
                    mma_bf16(acc[mt][nt], Af[mt][1], Bf[nt][0]);  // lo*hi
                }
        }

        // ---- store partials (float2): part[w][48][34] ----
        {
            float* pw = (float*)(smem + SPART) + w * (48 * 34);
            const int r0 = lane >> 2, c0 = (lane & 3) * 2;
#pragma unroll
            for (int mt = 0; mt < 3; ++mt)
#pragma unroll
                for (int nt = 0; nt < 4; ++nt) {
                    int base = (mt * 16 + r0) * 34 + nt * 8 + c0;
                    *(float2*)&pw[base] =
                        make_float2(acc[mt][nt][0], acc[mt][nt][1]);
                    *(float2*)&pw[base + 8 * 34] =
                        make_float2(acc[mt][nt][2], acc[mt][nt][3]);
                }
        }
        __syncthreads();

        // ---- reduce 8 warps + epilogue (thread = 1 k x 2 batches) ----
        {
            const float* part = (const float*)(smem + SPART);
            float ga[3][2] = {{0.f,0.f},{0.f,0.f},{0.f,0.f}};
#pragma unroll
            for (int ww = 0; ww < 8; ++ww)
#pragma unroll
                for (int g = 0; g < 3; ++g) {
                    float2 p = *(const float2*)
                        &part[(ww * 48 + g * 16 + kl_e) * 34 + bl_e * 2];
                    ga[g][0] += p.x; ga[g][1] += p.y;
                }

            const float4 c1 = *(const float4*)(smem + SBIAS + kl_e * 32);
            const float4 c2 = *(const float4*)(smem + SBIAS + kl_e * 32 + 16);
            const int k = k0 + kl_e;

            {
                float r = fsig(fmaf(xv.x, c1.x, c1.w) + ga[0][0]);
                float z = fsig(fmaf(xv.x, c1.y, c2.x) + ga[1][0]);
                float n = ftanh(fmaf(xv.x, c1.z, c2.y) + r * (ga[2][0] + c2.z));
                oprev0 = (1.0f - z) * n + z * oprev0;
            }
            {
                float r = fsig(fmaf(xv.y, c1.x, c1.w) + ga[0][1]);
                float z = fsig(fmaf(xv.y, c1.y, c2.x) + ga[1][1]);
                float n = ftanh(fmaf(xv.y, c1.z, c2.y) + r * (ga[2][1] + c2.z));
                oprev1 = (1.0f - z) * n + z * oprev1;
            }
            __nv_bfloat16 h0 = __float2bfloat16(oprev0);
            __nv_bfloat16 l0 = __float2bfloat16(oprev0 - __bfloat162float(h0));
            __nv_bfloat16 h1 = __float2bfloat16(oprev1);
            __nv_bfloat16 l1 = __float2bfloat16(oprev1 - __bfloat162float(h1));
            g_hhi[sOut][(size_t)be0 * H + k]       = h0;
            g_hlo[sOut][(size_t)be0 * H + k]       = l0;
            g_hhi[sOut][(size_t)(be0 + 1) * H + k] = h1;
            g_hlo[sOut][(size_t)(be0 + 1) * H + k] = l1;
            if (t == S - 1) {
                g_hf[k * B + be0]     = oprev0;
                g_hf[k * B + be0 + 1] = oprev1;
            }
        }

        // ---- publish flag ----
        if (t < S - 1) {
            __syncthreads();
            if (tid == 0) {
                asm volatile("st.release.gpu.global.u32 [%0], %1;"
                             :: "l"(myflag), "r"((unsigned)(t + 1)) : "memory");
            }
        }
    }
}

// ---------------- kernel 4: FC head ----------------
__global__ void final_kernel(const float* __restrict__ fcw,
                             const float* __restrict__ fcb,
                             float* __restrict__ out) {
    const float* __restrict__ h = g_hf;
    int b = threadIdx.x;
    float s = 0.0f;
#pragma unroll 8
    for (int d = 0; d < H; ++d) s += h[d * B + b] * fcw[d];
    out[b] = s + fcb[0];
}

// ---------------- launcher ----------------
extern "C" void kernel_launch(void* const* d_in, const int* in_sizes, int n_in,
                              void* d_out, int out_size) {
    const int*   ends = (const int*)  d_in[1];
    const float* emb  = (const float*)d_in[3];
    const float* w_ih = (const float*)d_in[4];
    const float* w_hh = (const float*)d_in[5];
    const float* b_ih = (const float*)d_in[6];
    const float* b_hh = (const float*)d_in[7];
    const float* fc_w = (const float*)d_in[8];
    const float* fc_b = (const float*)d_in[9];
    float* out = (float*)d_out;

    cudaFuncSetAttribute(gru_mma_kernel,
                         cudaFuncAttributeMaxDynamicSharedMemorySize, SMTOT);

    reset_flags_kernel<<<4, 1024>>>();
    zero_hbf_kernel<<<128, 1024>>>();
    zero_featsi_kernel<<<(S * B + 1023) / 1024, 1024>>>();
    gather_kernel<<<(S * B) / 8, 256>>>(ends, emb);
    feats_flat_kernel<<<dim3(36, 128), 256>>>();
    feats_convert_kernel<<<(S * B + 1023) / 1024, 1024>>>();
    gru_mma_kernel<<<GNB, GNT, SMTOT>>>(w_hh, w_ih, b_ih, b_hh);
    final_kernel<<<1, B>>>(fc_w, fc_b, out);
}

// round 15
// speedup vs baseline: 2.0714x; 1.0348x over previous
#include <cuda_runtime.h>
#include <cuda_bf16.h>
#include <math.h>

#define S   512
#define B   128
#define D   300
#define H   512
#define GNB 128
#define GNT 256

// ---------------- device scratch ----------------
__device__ float    g_xn[(size_t)B * S * D];
__device__ float    g_feats[S * B];
__device__ unsigned g_featsi[S * B];
__device__ float    g_hf[H * B];                        // final h, dim-major
__device__ __align__(16) __nv_bfloat16 g_hhi[2][B * H]; // h hi split, [b][d]
__device__ __align__(16) __nv_bfloat16 g_hlo[2][B * H]; // h lo split
__device__ unsigned g_flagd[GNB * 32];

__global__ void reset_flags_kernel() {
    int i = blockIdx.x * blockDim.x + threadIdx.x;
    if (i < GNB * 32) g_flagd[i] = 0u;
}
__global__ void zero_hbf_kernel() {
    int i = blockIdx.x * blockDim.x + threadIdx.x;
    unsigned* a = (unsigned*)g_hhi;
    unsigned* b = (unsigned*)g_hlo;
    if (i < 65536) a[i] = 0u;
    else if (i < 131072) b[i - 65536] = 0u;
}
__global__ void zero_featsi_kernel() {
    int i = blockIdx.x * blockDim.x + threadIdx.x;
    if (i < S * B) g_featsi[i] = 0u;
}

// ---------------- helpers ----------------
__device__ __forceinline__ void ffma2(unsigned long long& a,
                                      unsigned long long w,
                                      unsigned long long h) {
    asm("fma.rn.f32x2 %0, %1, %2, %0;" : "+l"(a) : "l"(w), "l"(h));
}
__device__ __forceinline__ unsigned long long dup2(float v) {
    unsigned long long r; unsigned u = __float_as_uint(v);
    asm("mov.b64 %0, {%1, %1};" : "=l"(r) : "r"(u));
    return r;
}
__device__ __forceinline__ float2 unpk(unsigned long long v) {
    unsigned lo, hi;
    asm("mov.b64 {%0, %1}, %2;" : "=r"(lo), "=r"(hi) : "l"(v));
    return make_float2(__uint_as_float(lo), __uint_as_float(hi));
}
__device__ __forceinline__ float fsig(float x) {
    float e, r;
    asm("ex2.approx.f32 %0, %1;" : "=f"(e) : "f"(x * -1.4426950408889634f));
    asm("rcp.approx.f32 %0, %1;" : "=f"(r) : "f"(e + 1.0f));
    return r;
}
__device__ __forceinline__ float ftanh(float x) {
    float e, r;
    asm("ex2.approx.f32 %0, %1;" : "=f"(e) : "f"(x * 2.8853900817779268f));
    asm("rcp.approx.f32 %0, %1;" : "=f"(r) : "f"(e + 1.0f));
    return fmaf(-2.0f, r, 1.0f);
}
__device__ __forceinline__ unsigned fkey(float f) {
    unsigned u = __float_as_uint(f);
    return (u & 0x80000000u) ? ~u : (u | 0x80000000u);
}
__device__ __forceinline__ float unkey(unsigned k) {
    unsigned u = (k & 0x80000000u) ? (k & 0x7fffffffu) : ~k;
    return __uint_as_float(u);
}
__device__ __forceinline__ unsigned smem_u32(const void* p) {
    unsigned a;
    asm("{ .reg .u64 t; cvta.to.shared.u64 t, %1; cvt.u32.u64 %0, t; }"
        : "=r"(a) : "l"(p));
    return a;
}
__device__ __forceinline__ void ldsm_x4(unsigned* r, unsigned addr) {
    asm volatile("ldmatrix.sync.aligned.m8n8.x4.shared.b16 {%0,%1,%2,%3}, [%4];"
                 : "=r"(r[0]), "=r"(r[1]), "=r"(r[2]), "=r"(r[3]) : "r"(addr));
}
__device__ __forceinline__ void ldsm_x2(unsigned* r, unsigned addr) {
    asm volatile("ldmatrix.sync.aligned.m8n8.x2.shared.b16 {%0,%1}, [%2];"
                 : "=r"(r[0]), "=r"(r[1]) : "r"(addr));
}
__device__ __forceinline__ void mma_bf16(float* d, const unsigned* a,
                                         const unsigned* b) {
    asm volatile(
        "mma.sync.aligned.m16n8k16.row.col.f32.bf16.bf16.f32 "
        "{%0,%1,%2,%3}, {%4,%5,%6,%7}, {%8,%9}, {%0,%1,%2,%3};"
        : "+f"(d[0]), "+f"(d[1]), "+f"(d[2]), "+f"(d[3])
        : "r"(a[0]), "r"(a[1]), "r"(a[2]), "r"(a[3]), "r"(b[0]), "r"(b[1]));
}
__device__ __forceinline__ void cp16(unsigned dst, const void* src) {
    asm volatile("cp.async.cg.shared.global [%0], [%1], 16;"
                 :: "r"(dst), "l"(src));
}

// ---------------- kernel 1: gather + normalize ----------------
__global__ void gather_kernel(const int* __restrict__ ends,
                              const float* __restrict__ emb) {
    int w    = (blockIdx.x * blockDim.x + threadIdx.x) >> 5;
    int lane = threadIdx.x & 31;
    if (w >= S * B) return;
    int s = w >> 7, b = w & 127;
    const float* row = emb + (size_t)ends[s * B + b] * D;
    float v[10]; float ss = 0.0f;
#pragma unroll
    for (int i = 0; i < 10; ++i) {
        int d = lane + 32 * i;
        v[i] = (d < D) ? row[d] : 0.0f;
        ss += v[i] * v[i];
    }
#pragma unroll
    for (int m = 16; m; m >>= 1) ss += __shfl_xor_sync(0xffffffffu, ss, m);
    float inv = 1.0f / fmaxf(sqrtf(ss), 1e-8f);
    float* dst = g_xn + ((size_t)b * S + s) * D;
#pragma unroll
    for (int i = 0; i < 10; ++i) {
        int d = lane + 32 * i;
        if (d < D) dst[d] = v[i] * inv;
    }
}

// ---------------- kernel 2: causal max cosine sims ----------------
#define FP 68
__constant__ int c_it[36] = {0,1,1,2,2,2,3,3,3,3,4,4,4,4,4,5,5,5,5,5,5,
                             6,6,6,6,6,6,6,7,7,7,7,7,7,7,7};
__constant__ int c_jt[36] = {0,0,1,0,1,2,0,1,2,3,0,1,2,3,4,0,1,2,3,4,5,
                             0,1,2,3,4,5,6,0,1,2,3,4,5,6,7};

__global__ void feats_flat_kernel() {
    __shared__ __align__(16) float At[2][25 * FP];
    __shared__ __align__(16) float Bt[2][25 * FP];

    const int idx = blockIdx.x, b = blockIdx.y;
    const int it = c_it[idx], jt = c_jt[idx];
    const float* Xb = g_xn + (size_t)b * S * D;
    const int tid = threadIdx.x, tx = tid & 15, ty = tid >> 4;
    const int wa = tid >> 5, lane = tid & 31;
    const int i0 = it * 64, j0 = jt * 64;

    if (lane < 25) {
#pragma unroll
        for (int i = 0; i < 8; ++i) {
            int row = wa * 8 + i;
            At[0][lane * FP + row] = Xb[(size_t)(i0 + row) * D + lane];
            Bt[0][lane * FP + row] = Xb[(size_t)(j0 + row) * D + lane];
        }
    }
    __syncthreads();

    unsigned long long acc2[4][2];
#pragma unroll
    for (int r = 0; r < 4; ++r) { acc2[r][0] = 0ull; acc2[r][1] = 0ull; }

    for (int kc = 0; kc < 12; ++kc) {
        const int cur = kc & 1;
        if (kc < 11 && lane < 25) {
#pragma unroll
            for (int i = 0; i < 8; ++i) {
                int row = wa * 8 + i;
                At[cur ^ 1][lane * FP + row] =
                    Xb[(size_t)(i0 + row) * D + (kc + 1) * 25 + lane];
                Bt[cur ^ 1][lane * FP + row] =
                    Xb[(size_t)(j0 + row) * D + (kc + 1) * 25 + lane];
            }
        }
#pragma unroll
        for (int kk = 0; kk < 25; ++kk) {
            const float4 a4 = *(const float4*)(&At[cur][kk * FP + ty * 4]);
            const ulonglong2 cp = *(const ulonglong2*)(&Bt[cur][kk * FP + tx * 4]);
            const unsigned long long a0 = dup2(a4.x), a1 = dup2(a4.y);
            const unsigned long long a2 = dup2(a4.z), a3 = dup2(a4.w);
            ffma2(acc2[0][0], a0, cp.x); ffma2(acc2[0][1], a0, cp.y);
            ffma2(acc2[1][0], a1, cp.x); ffma2(acc2[1][1], a1, cp.y);
            ffma2(acc2[2][0], a2, cp.x); ffma2(acc2[2][1], a2, cp.y);
            ffma2(acc2[3][0], a3, cp.x); ffma2(acc2[3][1], a3, cp.y);
        }
        __syncthreads();
    }

    float rowmax[4] = { -INFINITY, -INFINITY, -INFINITY, -INFINITY };
#pragma unroll
    for (int r = 0; r < 4; ++r) {
        int i = i0 + ty * 4 + r;
        float2 v01 = unpk(acc2[r][0]);
        float2 v23 = unpk(acc2[r][1]);
        int j = j0 + tx * 4;
        if (j + 0 < i) rowmax[r] = fmaxf(rowmax[r], v01.x);
        if (j + 1 < i) rowmax[r] = fmaxf(rowmax[r], v01.y);
        if (j + 2 < i) rowmax[r] = fmaxf(rowmax[r], v23.x);
        if (j + 3 < i) rowmax[r] = fmaxf(rowmax[r], v23.y);
    }
#pragma unroll
    for (int m = 8; m; m >>= 1)
#pragma unroll
        for (int r = 0; r < 4; ++r)
            rowmax[r] = fmaxf(rowmax[r], __shfl_xor_sync(0xffffffffu, rowmax[r], m));
    if (tx == 0) {
#pragma unroll
        for (int r = 0; r < 4; ++r) {
            int i = i0 + ty * 4 + r;
            if (i > 0 && rowmax[r] > -INFINITY)
                atomicMax(&g_featsi[i * B + b], fkey(rowmax[r]));
        }
    }
}

__global__ void feats_convert_kernel() {
    int i = blockIdx.x * blockDim.x + threadIdx.x;
    if (i < S * B) g_feats[i] = (i < B) ? 0.0f : unkey(g_featsi[i]);
}

// ---------------- kernel 3: mma.sync persistent GRU ----------------
// 128 blocks = 32 kt (16 k) x 4 bt (32 b); 8 warps split K=512 (64 dims each).
// Warp-local staging: each warp cp.asyncs only its own K-slice columns, so
// no block-wide barrier between staging and MMA (3 syncs/step, not 4).
#define SW_HI  0u       // W hi: 48 rows x 520 bf16 (1040B stride) = 49920
#define SW_LO  49920u
#define SH_HI  99840u   // h hi: 32 rows x 1040B = 33280
#define SH_LO  133120u
#define SPART  166400u  // partials: 8 w x 48 x 34 f32 = 52224
#define SBIAS  218624u  // 16 k x 8 f32 = 512
#define SMTOT  219136

__global__ void __launch_bounds__(GNT, 1)
gru_mma_kernel(const float* __restrict__ w_hh,
               const float* __restrict__ w_ih,
               const float* __restrict__ b_ih,
               const float* __restrict__ b_hh) {
    extern __shared__ char smem[];
    const unsigned sbase = smem_u32(smem);
    const int tid  = threadIdx.x;
    const int lane = tid & 31;
    const int w    = tid >> 5;
    const int kt   = blockIdx.x >> 2;
    const int bt   = blockIdx.x & 3;
    const int k0   = kt * 16;
    const int b0   = bt * 32;

    // ---- one-time: W pack (48 rows x 512 dims, bf16 hi/lo, padded rows) ----
    for (int i = tid; i < 48 * 512; i += GNT) {
        int row = i >> 9, d = i & 511;
        int g = row >> 4, kl = row & 15;
        float wv = w_hh[((size_t)(g * H + k0 + kl)) * H + d];
        __nv_bfloat16 hi = __float2bfloat16(wv);
        __nv_bfloat16 lo = __float2bfloat16(wv - __bfloat162float(hi));
        *(__nv_bfloat16*)(smem + SW_HI + row * 1040 + d * 2) = hi;
        *(__nv_bfloat16*)(smem + SW_LO + row * 1040 + d * 2) = lo;
    }
    // ---- biases ----
    if (tid < 16) {
        int k = k0 + tid;
        float* bp = (float*)(smem + SBIAS + tid * 32);
        bp[0] = w_ih[k]; bp[1] = w_ih[H + k]; bp[2] = w_ih[2 * H + k];
        bp[3] = b_ih[k] + b_hh[k];
        bp[4] = b_ih[H + k] + b_hh[H + k];
        bp[5] = b_ih[2 * H + k]; bp[6] = b_hh[2 * H + k]; bp[7] = 0.0f;
    }

    // ---- per-lane ldmatrix base offsets ----
    const unsigned a_row = (unsigned)((lane & 7) | (lane & 8));
    const unsigned a_off = a_row * 1040u + (unsigned)(lane >> 4) * 16u;
    const int l4 = lane & 15;
    const unsigned b_off = (unsigned)(l4 & 7) * 1040u + (unsigned)((l4 >> 3) & 1) * 16u;
    const unsigned kslice = (unsigned)w * 128u;

    // ---- warp-local staging addresses: warp w stages cols [w*128,w*128+128)
    //      of all 32 rows; lane covers 8 chunks of 16B per buffer ----
    unsigned st_dst[8];
    unsigned st_src[8];
#pragma unroll
    for (int j = 0; j < 8; ++j) {
        int idx = j * 32 + lane;          // 0..255
        int row = idx >> 3, c16 = idx & 7;
        st_dst[j] = (unsigned)(row * 1040 + w * 128 + c16 * 16);
        st_src[j] = (unsigned)((b0 + row) * H + w * 64 + c16 * 8);
    }

    // ---- flags ----
    unsigned* myflag = &g_flagd[blockIdx.x * 32];
    const unsigned* pollp = &g_flagd[((lane << 2) + bt) * 32];

    // ---- epilogue ids ----
    const int kl_e = tid >> 4;
    const int bl_e = tid & 15;
    const int be0  = b0 + bl_e * 2;
    float oprev0 = 0.0f, oprev1 = 0.0f;

    __syncthreads();

    for (int t = 0; t < S; ++t) {
        const int sIn  = (t + 1) & 1;
        const int sOut = t & 1;

        const float2 xv = *(const float2*)&g_feats[t * B + be0];

        // ---- wait for producers (warp 0 polls 32 flags) ----
        if (t > 0 && w == 0) {
            unsigned v;
            do {
                asm volatile("ld.acquire.gpu.global.u32 %0, [%1];"
                             : "=r"(v) : "l"(pollp) : "memory");
            } while (__any_sync(0xffffffffu, v < (unsigned)t));
        }
        __syncthreads();                   // sync #1: h(t-1) globally ready

        // ---- warp-local staging of this warp's K-slice ----
        {
            const __nv_bfloat16* sH = g_hhi[sIn];
            const __nv_bfloat16* sL = g_hlo[sIn];
#pragma unroll
            for (int j = 0; j < 8; ++j) {
                cp16(sbase + SH_HI + st_dst[j], sH + st_src[j]);
                cp16(sbase + SH_LO + st_dst[j], sL + st_src[j]);
            }
            asm volatile("cp.async.commit_group;");
        }

        float acc[3][4][4];
#pragma unroll
        for (int mt = 0; mt < 3; ++mt)
#pragma unroll
            for (int nt = 0; nt < 4; ++nt)
#pragma unroll
                for (int e = 0; e < 4; ++e) acc[mt][nt][e] = 0.0f;

        // ---- preload chunk-0 A fragments (independent of staging) ----
        unsigned Af[3][2][4];
#pragma unroll
        for (int mt = 0; mt < 3; ++mt) {
            ldsm_x4(Af[mt][0], sbase + SW_HI + (unsigned)mt * 16640u + kslice + a_off);
            ldsm_x4(Af[mt][1], sbase + SW_LO + (unsigned)mt * 16640u + kslice + a_off);
        }

        asm volatile("cp.async.wait_group 0;");
        __syncwarp();                      // warp-local: staged data visible

        // ---- mma over this warp's 64-dim K slice ----
#pragma unroll
        for (int ks = 0; ks < 4; ++ks) {
            const unsigned kb = kslice + (unsigned)ks * 32u;
            if (ks > 0) {
#pragma unroll
                for (int mt = 0; mt < 3; ++mt) {
                    ldsm_x4(Af[mt][0], sbase + SW_HI + (unsigned)mt * 16640u + kb + a_off);
                    ldsm_x4(Af[mt][1], sbase + SW_LO + (unsigned)mt * 16640u + kb + a_off);
                }
            }
            unsigned Bf[4][2][2];
#pragma unroll
            for (int nt = 0; nt < 4; ++nt) {
                ldsm_x2(Bf[nt][0], sbase + SH_HI + (unsigned)nt * 8320u + kb + b_off);
                ldsm_x2(Bf[nt][1], sbase + SH_LO + (unsigned)nt * 8320u + kb + b_off);
            }
#pragma unroll
            for (int mt = 0; mt < 3; ++mt)
#pragma unroll
                for (int nt = 0; nt < 4; ++nt) {
                    mma_bf16(acc[mt][nt], Af[mt][0], Bf[nt][0]);  // hi*hi
                    mma_bf16(acc[mt][nt], Af[mt][0], Bf[nt][1]);  // hi*lo
                    mma_bf16(acc[mt][nt], Af[mt][1], Bf[nt][0]);  // lo*hi
                }
        }

        // ---- store partials (float2): part[w][48][34] ----
        {
            float* pw = (float*)(smem + SPART) + w * (48 * 34);
            const int r0 = lane >> 2, c0 = (lane & 3) * 2;
#pragma unroll
            for (int mt = 0; mt < 3; ++mt)
#pragma unroll
                for (int nt = 0; nt < 4; ++nt) {
                    int base = (mt * 16 + r0) * 34 + nt * 8 + c0;
                    *(float2*)&pw[base] =
                        make_float2(acc[mt][nt][0], acc[mt][nt][1]);
                    *(float2*)&pw[base + 8 * 34] =
                        make_float2(acc[mt][nt][2], acc[mt][nt][3]);
                }
        }
        __syncthreads();                   // sync #2: partials ready

        // ---- reduce 8 warps + epilogue (thread = 1 k x 2 batches) ----
        {
            const float* part = (const float*)(smem + SPART);
            float ga[3][2] = {{0.f,0.f},{0.f,0.f},{0.f,0.f}};
#pragma unroll
            for (int ww = 0; ww < 8; ++ww)
#pragma unroll
                for (int g = 0; g < 3; ++g) {
                    float2 p = *(const float2*)
                        &part[(ww * 48 + g * 16 + kl_e) * 34 + bl_e * 2];
                    ga[g][0] += p.x; ga[g][1] += p.y;
                }

            const float4 c1 = *(const float4*)(smem + SBIAS + kl_e * 32);
            const float4 c2 = *(const float4*)(smem + SBIAS + kl_e * 32 + 16);
            const int k = k0 + kl_e;

            {
                float r = fsig(fmaf(xv.x, c1.x, c1.w) + ga[0][0]);
                float z = fsig(fmaf(xv.x, c1.y, c2.x) + ga[1][0]);
                float n = ftanh(fmaf(xv.x, c1.z, c2.y) + r * (ga[2][0] + c2.z));
                oprev0 = (1.0f - z) * n + z * oprev0;
            }
            {
                float r = fsig(fmaf(xv.y, c1.x, c1.w) + ga[0][1]);
                float z = fsig(fmaf(xv.y, c1.y, c2.x) + ga[1][1]);
                float n = ftanh(fmaf(xv.y, c1.z, c2.y) + r * (ga[2][1] + c2.z));
                oprev1 = (1.0f - z) * n + z * oprev1;
            }
            __nv_bfloat16 h0 = __float2bfloat16(oprev0);
            __nv_bfloat16 l0 = __float2bfloat16(oprev0 - __bfloat162float(h0));
            __nv_bfloat16 h1 = __float2bfloat16(oprev1);
            __nv_bfloat16 l1 = __float2bfloat16(oprev1 - __bfloat162float(h1));
            g_hhi[sOut][(size_t)be0 * H + k]       = h0;
            g_hlo[sOut][(size_t)be0 * H + k]       = l0;
            g_hhi[sOut][(size_t)(be0 + 1) * H + k] = h1;
            g_hlo[sOut][(size_t)(be0 + 1) * H + k] = l1;
            if (t == S - 1) {
                g_hf[k * B + be0]     = oprev0;
                g_hf[k * B + be0 + 1] = oprev1;
            }
        }

        // ---- publish flag ----
        if (t < S - 1) {
            __syncthreads();               // sync #3: h(t) stores done
            if (tid == 0) {
                asm volatile("st.release.gpu.global.u32 [%0], %1;"
                             :: "l"(myflag), "r"((unsigned)(t + 1)) : "memory");
            }
        }
    }
}

// ---------------- kernel 4: FC head ----------------
__global__ void final_kernel(const float* __restrict__ fcw,
                             const float* __restrict__ fcb,
                             float* __restrict__ out) {
    const float* __restrict__ h = g_hf;
    int b = threadIdx.x;
    float s = 0.0f;
#pragma unroll 8
    for (int d = 0; d < H; ++d) s += h[d * B + b] * fcw[d];
    out[b] = s + fcb[0];
}

// ---------------- launcher ----------------
extern "C" void kernel_launch(void* const* d_in, const int* in_sizes, int n_in,
                              void* d_out, int out_size) {
    const int*   ends = (const int*)  d_in[1];
    const float* emb  = (const float*)d_in[3];
    const float* w_ih = (const float*)d_in[4];
    const float* w_hh = (const float*)d_in[5];
    const float* b_ih = (const float*)d_in[6];
    const float* b_hh = (const float*)d_in[7];
    const float* fc_w = (const float*)d_in[8];
    const float* fc_b = (const float*)d_in[9];
    float* out = (float*)d_out;

    cudaFuncSetAttribute(gru_mma_kernel,
                         cudaFuncAttributeMaxDynamicSharedMemorySize, SMTOT);

    reset_flags_kernel<<<4, 1024>>>();
    zero_hbf_kernel<<<128, 1024>>>();
    zero_featsi_kernel<<<(S * B + 1023) / 1024, 1024>>>();
    gather_kernel<<<(S * B) / 8, 256>>>(ends, emb);
    feats_flat_kernel<<<dim3(36, 128), 256>>>();
    feats_convert_kernel<<<(S * B + 1023) / 1024, 1024>>>();
    gru_mma_kernel<<<GNB, GNT, SMTOT>>>(w_hh, w_ih, b_ih, b_hh);
    final_kernel<<<1, B>>>(fc_w, fc_b, out);
}

// round 16
// speedup vs baseline: 2.2120x; 1.0679x over previous
#include <cuda_runtime.h>
#include <cuda_bf16.h>
#include <math.h>

#define S   512
#define B   128
#define D   300
#define H   512
#define XK  304     // padded feats K (19 k-chunks of 16)
#define GNB 128
#define GNT 256

// ---------------- device scratch ----------------
__device__ float    g_feats[S * B];
__device__ unsigned g_featsi[S * B];
__device__ float    g_hf[H * B];                        // final h, dim-major
__device__ __align__(16) __nv_bfloat16 g_xhi[(size_t)B * S * XK]; // xn hi
__device__ __align__(16) __nv_bfloat16 g_xlo[(size_t)B * S * XK]; // xn lo
__device__ __align__(16) __nv_bfloat16 g_hhi[2][B * H]; // h hi split, [b][d]
__device__ __align__(16) __nv_bfloat16 g_hlo[2][B * H]; // h lo split
__device__ unsigned g_flagd[GNB * 32];

__global__ void reset_flags_kernel() {
    int i = blockIdx.x * blockDim.x + threadIdx.x;
    if (i < GNB * 32) g_flagd[i] = 0u;
}
__global__ void zero_hbf_kernel() {
    int i = blockIdx.x * blockDim.x + threadIdx.x;
    unsigned* a = (unsigned*)g_hhi;
    unsigned* b = (unsigned*)g_hlo;
    if (i < 65536) a[i] = 0u;
    else if (i < 131072) b[i - 65536] = 0u;
}
__global__ void zero_featsi_kernel() {
    int i = blockIdx.x * blockDim.x + threadIdx.x;
    if (i < S * B) g_featsi[i] = 0u;
}

// ---------------- helpers ----------------
__device__ __forceinline__ float fsig(float x) {
    float e, r;
    asm("ex2.approx.f32 %0, %1;" : "=f"(e) : "f"(x * -1.4426950408889634f));
    asm("rcp.approx.f32 %0, %1;" : "=f"(r) : "f"(e + 1.0f));
    return r;
}
__device__ __forceinline__ float ftanh(float x) {
    float e, r;
    asm("ex2.approx.f32 %0, %1;" : "=f"(e) : "f"(x * 2.8853900817779268f));
    asm("rcp.approx.f32 %0, %1;" : "=f"(r) : "f"(e + 1.0f));
    return fmaf(-2.0f, r, 1.0f);
}
__device__ __forceinline__ unsigned fkey(float f) {
    unsigned u = __float_as_uint(f);
    return (u & 0x80000000u) ? ~u : (u | 0x80000000u);
}
__device__ __forceinline__ float unkey(unsigned k) {
    unsigned u = (k & 0x80000000u) ? (k & 0x7fffffffu) : ~k;
    return __uint_as_float(u);
}
__device__ __forceinline__ unsigned smem_u32(const void* p) {
    unsigned a;
    asm("{ .reg .u64 t; cvta.to.shared.u64 t, %1; cvt.u32.u64 %0, t; }"
        : "=r"(a) : "l"(p));
    return a;
}
__device__ __forceinline__ void ldsm_x4(unsigned* r, unsigned addr) {
    asm volatile("ldmatrix.sync.aligned.m8n8.x4.shared.b16 {%0,%1,%2,%3}, [%4];"
                 : "=r"(r[0]), "=r"(r[1]), "=r"(r[2]), "=r"(r[3]) : "r"(addr));
}
__device__ __forceinline__ void ldsm_x2(unsigned* r, unsigned addr) {
    asm volatile("ldmatrix.sync.aligned.m8n8.x2.shared.b16 {%0,%1}, [%2];"
                 : "=r"(r[0]), "=r"(r[1]) : "r"(addr));
}
__device__ __forceinline__ void mma_bf16(float* d, const unsigned* a,
                                         const unsigned* b) {
    asm volatile(
        "mma.sync.aligned.m16n8k16.row.col.f32.bf16.bf16.f32 "
        "{%0,%1,%2,%3}, {%4,%5,%6,%7}, {%8,%9}, {%0,%1,%2,%3};"
        : "+f"(d[0]), "+f"(d[1]), "+f"(d[2]), "+f"(d[3])
        : "r"(a[0]), "r"(a[1]), "r"(a[2]), "r"(a[3]), "r"(b[0]), "r"(b[1]));
}
__device__ __forceinline__ void cp16(unsigned dst, const void* src) {
    asm volatile("cp.async.cg.shared.global [%0], [%1], 16;"
                 :: "r"(dst), "l"(src));
}

// ---------------- kernel 1: gather + normalize -> bf16 hi/lo ----------------
__global__ void gather_kernel(const int* __restrict__ ends,
                              const float* __restrict__ emb) {
    int w    = (blockIdx.x * blockDim.x + threadIdx.x) >> 5;
    int lane = threadIdx.x & 31;
    if (w >= S * B) return;
    int s = w >> 7, b = w & 127;
    const float* row = emb + (size_t)ends[s * B + b] * D;
    float v[10]; float ss = 0.0f;
#pragma unroll
    for (int i = 0; i < 10; ++i) {
        int d = lane + 32 * i;
        v[i] = (d < D) ? row[d] : 0.0f;
        ss += v[i] * v[i];
    }
#pragma unroll
    for (int m = 16; m; m >>= 1) ss += __shfl_xor_sync(0xffffffffu, ss, m);
    float inv = 1.0f / fmaxf(sqrtf(ss), 1e-8f);
    __nv_bfloat16* dh = g_xhi + ((size_t)b * S + s) * XK;
    __nv_bfloat16* dl = g_xlo + ((size_t)b * S + s) * XK;
#pragma unroll
    for (int i = 0; i < 10; ++i) {
        int d = lane + 32 * i;
        if (d < XK) {
            float val = v[i] * inv;           // 0 for padded dims
            __nv_bfloat16 hi = __float2bfloat16(val);
            __nv_bfloat16 lo = __float2bfloat16(val - __bfloat162float(hi));
            dh[d] = hi;
            dl[d] = lo;
        }
    }
}

// ---------------- kernel 2: causal max cosine sims via mma.sync ------------
#define FSTR 624                  // smem row stride (conflict-free ldsm phases)
#define SA_HI 0u
#define SA_LO 39936u
#define SB_HI 79872u
#define SB_LO 119808u
#define FMSMEM 159744

__constant__ int c_it[36] = {0,1,1,2,2,2,3,3,3,3,4,4,4,4,4,5,5,5,5,5,5,
                             6,6,6,6,6,6,6,7,7,7,7,7,7,7,7};
__constant__ int c_jt[36] = {0,0,1,0,1,2,0,1,2,3,0,1,2,3,4,0,1,2,3,4,5,
                             0,1,2,3,4,5,6,0,1,2,3,4,5,6,7};

__global__ void __launch_bounds__(256, 1)
feats_mma_kernel() {
    extern __shared__ char smem[];
    const unsigned sbase = smem_u32(smem);
    const int idx = blockIdx.x, b = blockIdx.y;
    const int it = c_it[idx], jt = c_jt[idx];
    const int tid = threadIdx.x, lane = tid & 31, w = tid >> 5;
    const int i0 = it * 64, j0 = jt * 64;
    const bool diag = (it == jt);

    // ---- stage A tile (64 rows x 304 bf16, hi+lo) via cp.async ----
    {
        const __nv_bfloat16* sAh = g_xhi + ((size_t)b * S + i0) * XK;
        const __nv_bfloat16* sAl = g_xlo + ((size_t)b * S + i0) * XK;
        for (int i = tid; i < 64 * 38; i += 256) {
            int row = i / 38, c = i - row * 38;
            unsigned off = (unsigned)(row * FSTR + c * 16);
            cp16(sbase + SA_HI + off, sAh + (size_t)row * XK + c * 8);
            cp16(sbase + SA_LO + off, sAl + (size_t)row * XK + c * 8);
        }
        if (!diag) {
            const __nv_bfloat16* sBh = g_xhi + ((size_t)b * S + j0) * XK;
            const __nv_bfloat16* sBl = g_xlo + ((size_t)b * S + j0) * XK;
            for (int i = tid; i < 64 * 38; i += 256) {
                int row = i / 38, c = i - row * 38;
                unsigned off = (unsigned)(row * FSTR + c * 16);
                cp16(sbase + SB_HI + off, sBh + (size_t)row * XK + c * 8);
                cp16(sbase + SB_LO + off, sBl + (size_t)row * XK + c * 8);
            }
        }
        asm volatile("cp.async.commit_group;");
        asm volatile("cp.async.wait_group 0;");
    }
    __syncthreads();

    const unsigned bBH = diag ? SA_HI : SB_HI;
    const unsigned bBL = diag ? SA_LO : SB_LO;

    // ---- warp tiling: mt = w&3 (16 i-rows), ntq = w>>2 (32 j-cols) ----
    const int mt  = w & 3;
    const int ntq = w >> 2;
    // A frag addressing (R13-validated): rows 0-15 x two 16B k-halves
    const unsigned a_row = (unsigned)((lane & 7) | (lane & 8));
    const unsigned a_off = (unsigned)(mt * 16) * FSTR + a_row * FSTR
                         + (unsigned)(lane >> 4) * 16u;
    // B frag addressing (x4 = 2 nt tiles): nrow 0-15, k-half by lane>>3 bit
    const unsigned b_nrow = (unsigned)((lane & 7) + ((lane >> 4) & 1) * 8);
    const unsigned b_off  = (unsigned)(ntq * 32) * FSTR + b_nrow * FSTR
                          + (unsigned)((lane >> 3) & 1) * 16u;

    float acc[4][4];
#pragma unroll
    for (int nt = 0; nt < 4; ++nt)
#pragma unroll
        for (int e = 0; e < 4; ++e) acc[nt][e] = 0.0f;

    for (int kc = 0; kc < 19; ++kc) {
        const unsigned kb = (unsigned)kc * 32u;
        unsigned Ah[4], Al[4];
        ldsm_x4(Ah, sbase + SA_HI + kb + a_off);
        ldsm_x4(Al, sbase + SA_LO + kb + a_off);
        unsigned Bh[8], Bl[8];
        ldsm_x4(Bh,     sbase + bBH + kb + b_off);             // nt 0,1
        ldsm_x4(Bh + 4, sbase + bBH + kb + b_off + 16u * FSTR); // nt 2,3
        ldsm_x4(Bl,     sbase + bBL + kb + b_off);
        ldsm_x4(Bl + 4, sbase + bBL + kb + b_off + 16u * FSTR);
#pragma unroll
        for (int nt = 0; nt < 4; ++nt) {
            mma_bf16(acc[nt], Ah, Bh + nt * 2);   // hi*hi
            mma_bf16(acc[nt], Ah, Bl + nt * 2);   // hi*lo
            mma_bf16(acc[nt], Al, Bh + nt * 2);   // lo*hi
        }
    }

    // ---- causal row-max from D fragments ----
    const int i_lo = i0 + mt * 16 + (lane >> 2);
    const int i_hi = i_lo + 8;
    float rlo = -INFINITY, rhi = -INFINITY;
#pragma unroll
    for (int nt = 0; nt < 4; ++nt) {
        const int jb = j0 + (ntq * 4 + nt) * 8 + (lane & 3) * 2;
        if (jb     < i_lo) rlo = fmaxf(rlo, acc[nt][0]);
        if (jb + 1 < i_lo) rlo = fmaxf(rlo, acc[nt][1]);
        if (jb     < i_hi) rhi = fmaxf(rhi, acc[nt][2]);
        if (jb + 1 < i_hi) rhi = fmaxf(rhi, acc[nt][3]);
    }
#pragma unroll
    for (int m = 1; m <= 2; m <<= 1) {
        rlo = fmaxf(rlo, __shfl_xor_sync(0xffffffffu, rlo, m));
        rhi = fmaxf(rhi, __shfl_xor_sync(0xffffffffu, rhi, m));
    }
    if ((lane & 3) == 0) {
        if (i_lo > 0 && rlo > -INFINITY)
            atomicMax(&g_featsi[i_lo * B + b], fkey(rlo));
        if (rhi > -INFINITY)
            atomicMax(&g_featsi[i_hi * B + b], fkey(rhi));
    }
}

__global__ void feats_convert_kernel() {
    int i = blockIdx.x * blockDim.x + threadIdx.x;
    if (i < S * B) g_feats[i] = (i < B) ? 0.0f : unkey(g_featsi[i]);
}

// ---------------- kernel 3: mma.sync persistent GRU (R15, unchanged) -------
#define SW_HI  0u
#define SW_LO  49920u
#define SH_HI  99840u
#define SH_LO  133120u
#define SPART  166400u
#define SBIAS  218624u
#define SMTOT  219136

__global__ void __launch_bounds__(GNT, 1)
gru_mma_kernel(const float* __restrict__ w_hh,
               const float* __restrict__ w_ih,
               const float* __restrict__ b_ih,
               const float* __restrict__ b_hh) {
    extern __shared__ char smem[];
    const unsigned sbase = smem_u32(smem);
    const int tid  = threadIdx.x;
    const int lane = tid & 31;
    const int w    = tid >> 5;
    const int kt   = blockIdx.x >> 2;
    const int bt   = blockIdx.x & 3;
    const int k0   = kt * 16;
    const int b0   = bt * 32;

    for (int i = tid; i < 48 * 512; i += GNT) {
        int row = i >> 9, d = i & 511;
        int g = row >> 4, kl = row & 15;
        float wv = w_hh[((size_t)(g * H + k0 + kl)) * H + d];
        __nv_bfloat16 hi = __float2bfloat16(wv);
        __nv_bfloat16 lo = __float2bfloat16(wv - __bfloat162float(hi));
        *(__nv_bfloat16*)(smem + SW_HI + row * 1040 + d * 2) = hi;
        *(__nv_bfloat16*)(smem + SW_LO + row * 1040 + d * 2) = lo;
    }
    if (tid < 16) {
        int k = k0 + tid;
        float* bp = (float*)(smem + SBIAS + tid * 32);
        bp[0] = w_ih[k]; bp[1] = w_ih[H + k]; bp[2] = w_ih[2 * H + k];
        bp[3] = b_ih[k] + b_hh[k];
        bp[4] = b_ih[H + k] + b_hh[H + k];
        bp[5] = b_ih[2 * H + k]; bp[6] = b_hh[2 * H + k]; bp[7] = 0.0f;
    }

    const unsigned a_row = (unsigned)((lane & 7) | (lane & 8));
    const unsigned a_off = a_row * 1040u + (unsigned)(lane >> 4) * 16u;
    const int l4 = lane & 15;
    const unsigned b_off = (unsigned)(l4 & 7) * 1040u + (unsigned)((l4 >> 3) & 1) * 16u;
    const unsigned kslice = (unsigned)w * 128u;

    unsigned st_dst[8];
    unsigned st_src[8];
#pragma unroll
    for (int j = 0; j < 8; ++j) {
        int idx = j * 32 + lane;
        int row = idx >> 3, c16 = idx & 7;
        st_dst[j] = (unsigned)(row * 1040 + w * 128 + c16 * 16);
        st_src[j] = (unsigned)((b0 + row) * H + w * 64 + c16 * 8);
    }

    unsigned* myflag = &g_flagd[blockIdx.x * 32];
    const unsigned* pollp = &g_flagd[((lane << 2) + bt) * 32];

    const int kl_e = tid >> 4;
    const int bl_e = tid & 15;
    const int be0  = b0 + bl_e * 2;
    float oprev0 = 0.0f, oprev1 = 0.0f;

    __syncthreads();

    for (int t = 0; t < S; ++t) {
        const int sIn  = (t + 1) & 1;
        const int sOut = t & 1;

        const float2 xv = *(const float2*)&g_feats[t * B + be0];

        if (t > 0 && w == 0) {
            unsigned v;
            do {
                asm volatile("ld.acquire.gpu.global.u32 %0, [%1];"
                             : "=r"(v) : "l"(pollp) : "memory");
            } while (__any_sync(0xffffffffu, v < (unsigned)t));
        }
        __syncthreads();

        {
            const __nv_bfloat16* sH = g_hhi[sIn];
            const __nv_bfloat16* sL = g_hlo[sIn];
#pragma unroll
            for (int j = 0; j < 8; ++j) {
                cp16(sbase + SH_HI + st_dst[j], sH + st_src[j]);
                cp16(sbase + SH_LO + st_dst[j], sL + st_src[j]);
            }
            asm volatile("cp.async.commit_group;");
        }

        float acc[3][4][4];
#pragma unroll
        for (int mt = 0; mt < 3; ++mt)
#pragma unroll
            for (int nt = 0; nt < 4; ++nt)
#pragma unroll
                for (int e = 0; e < 4; ++e) acc[mt][nt][e] = 0.0f;

        unsigned Af[3][2][4];
#pragma unroll
        for (int mt = 0; mt < 3; ++mt) {
            ldsm_x4(Af[mt][0], sbase + SW_HI + (unsigned)mt * 16640u + kslice + a_off);
            ldsm_x4(Af[mt][1], sbase + SW_LO + (unsigned)mt * 16640u + kslice + a_off);
        }

        asm volatile("cp.async.wait_group 0;");
        __syncwarp();

#pragma unroll
        for (int ks = 0; ks < 4; ++ks) {
            const unsigned kb = kslice + (unsigned)ks * 32u;
            if (ks > 0) {
#pragma unroll
                for (int mt = 0; mt < 3; ++mt) {
                    ldsm_x4(Af[mt][0], sbase + SW_HI + (unsigned)mt * 16640u + kb + a_off);
                    ldsm_x4(Af[mt][1], sbase + SW_LO + (unsigned)mt * 16640u + kb + a_off);
                }
            }
            unsigned Bf[4][2][2];
#pragma unroll
            for (int nt = 0; nt < 4; ++nt) {
                ldsm_x2(Bf[nt][0], sbase + SH_HI + (unsigned)nt * 8320u + kb + b_off);
                ldsm_x2(Bf[nt][1], sbase + SH_LO + (unsigned)nt * 8320u + kb + b_off);
            }
#pragma unroll
            for (int mt = 0; mt < 3; ++mt)
#pragma unroll
                for (int nt = 0; nt < 4; ++nt) {
                    mma_bf16(acc[mt][nt], Af[mt][0], Bf[nt][0]);
                    mma_bf16(acc[mt][nt], Af[mt][0], Bf[nt][1]);
                    mma_bf16(acc[mt][nt], Af[mt][1], Bf[nt][0]);
                }
        }

        {
            float* pw = (float*)(smem + SPART) + w * (48 * 34);
            const int r0 = lane >> 2, c0 = (lane & 3) * 2;
#pragma unroll
            for (int mt = 0; mt < 3; ++mt)
#pragma unroll
                for (int nt = 0; nt < 4; ++nt) {
                    int base = (mt * 16 + r0) * 34 + nt * 8 + c0;
                    *(float2*)&pw[base] =
                        make_float2(acc[mt][nt][0], acc[mt][nt][1]);
                    *(float2*)&pw[base + 8 * 34] =
                        make_float2(acc[mt][nt][2], acc[mt][nt][3]);
                }
        }
        __syncthreads();

        {
            const float* part = (const float*)(smem + SPART);
            float ga[3][2] = {{0.f,0.f},{0.f,0.f},{0.f,0.f}};
#pragma unroll
            for (int ww = 0; ww < 8; ++ww)
#pragma unroll
                for (int g = 0; g < 3; ++g) {
                    float2 p = *(const float2*)
                        &part[(ww * 48 + g * 16 + kl_e) * 34 + bl_e * 2];
                    ga[g][0] += p.x; ga[g][1] += p.y;
                }

            const float4 c1 = *(const float4*)(smem + SBIAS + kl_e * 32);
            const float4 c2 = *(const float4*)(smem + SBIAS + kl_e * 32 + 16);
            const int k = k0 + kl_e;

            {
                float r = fsig(fmaf(xv.x, c1.x, c1.w) + ga[0][0]);
                float z = fsig(fmaf(xv.x, c1.y, c2.x) + ga[1][0]);
                float n = ftanh(fmaf(xv.x, c1.z, c2.y) + r * (ga[2][0] + c2.z));
                oprev0 = (1.0f - z) * n + z * oprev0;
            }
            {
                float r = fsig(fmaf(xv.y, c1.x, c1.w) + ga[0][1]);
                float z = fsig(fmaf(xv.y, c1.y, c2.x) + ga[1][1]);
                float n = ftanh(fmaf(xv.y, c1.z, c2.y) + r * (ga[2][1] + c2.z));
                oprev1 = (1.0f - z) * n + z * oprev1;
            }
            __nv_bfloat16 h0 = __float2bfloat16(oprev0);
            __nv_bfloat16 l0 = __float2bfloat16(oprev0 - __bfloat162float(h0));
            __nv_bfloat16 h1 = __float2bfloat16(oprev1);
            __nv_bfloat16 l1 = __float2bfloat16(oprev1 - __bfloat162float(h1));
            g_hhi[sOut][(size_t)be0 * H + k]       = h0;
            g_hlo[sOut][(size_t)be0 * H + k]       = l0;
            g_hhi[sOut][(size_t)(be0 + 1) * H + k] = h1;
            g_hlo[sOut][(size_t)(be0 + 1) * H + k] = l1;
            if (t == S - 1) {
                g_hf[k * B + be0]     = oprev0;
                g_hf[k * B + be0 + 1] = oprev1;
            }
        }

        if (t < S - 1) {
            __syncthreads();
            if (tid == 0) {
                asm volatile("st.release.gpu.global.u32 [%0], %1;"
                             :: "l"(myflag), "r"((unsigned)(t + 1)) : "memory");
            }
        }
    }
}

// ---------------- kernel 4: FC head ----------------
__global__ void final_kernel(const float* __restrict__ fcw,
                             const float* __restrict__ fcb,
                             float* __restrict__ out) {
    const float* __restrict__ h = g_hf;
    int b = threadIdx.x;
    float s = 0.0f;
#pragma unroll 8
    for (int d = 0; d < H; ++d) s += h[d * B + b] * fcw[d];
    out[b] = s + fcb[0];
}

// ---------------- launcher ----------------
extern "C" void kernel_launch(void* const* d_in, const int* in_sizes, int n_in,
                              void* d_out, int out_size) {
    const int*   ends = (const int*)  d_in[1];
    const float* emb  = (const float*)d_in[3];
    const float* w_ih = (const float*)d_in[4];
    const float* w_hh = (const float*)d_in[5];
    const float* b_ih = (const float*)d_in[6];
    const float* b_hh = (const float*)d_in[7];
    const float* fc_w = (const float*)d_in[8];
    const float* fc_b = (const float*)d_in[9];
    float* out = (float*)d_out;

    cudaFuncSetAttribute(gru_mma_kernel,
                         cudaFuncAttributeMaxDynamicSharedMemorySize, SMTOT);
    cudaFuncSetAttribute(feats_mma_kernel,
                         cudaFuncAttributeMaxDynamicSharedMemorySize, FMSMEM);

    reset_flags_kernel<<<4, 1024>>>();
    zero_hbf_kernel<<<128, 1024>>>();
    zero_featsi_kernel<<<(S * B + 1023) / 1024, 1024>>>();
    gather_kernel<<<(S * B) / 8, 256>>>(ends, emb);
    feats_mma_kernel<<<dim3(36, 128), 256, FMSMEM>>>();
    feats_convert_kernel<<<(S * B + 1023) / 1024, 1024>>>();
    gru_mma_kernel<<<GNB, GNT, SMTOT>>>(w_hh, w_ih, b_ih, b_hh);
    final_kernel<<<1, B>>>(fc_w, fc_b, out);
}

// round 17
// speedup vs baseline: 2.4017x; 1.0858x over previous
#include <cuda_runtime.h>
#include <cuda_bf16.h>
#include <math.h>

#define S   512
#define B   128
#define D   300
#define H   512
#define XK  304     // padded feats K (19 k-chunks of 16)
#define GNB 128
#define GNT 256

// ---------------- device scratch ----------------
__device__ float    g_feats[S * B];
__device__ unsigned g_featsi[S * B];
__device__ float    g_hf[H * B];                        // final h, dim-major
__device__ __align__(16) __nv_bfloat16 g_xhi[(size_t)B * S * XK]; // xn hi
__device__ __align__(16) __nv_bfloat16 g_xlo[(size_t)B * S * XK]; // xn lo
__device__ __align__(16) __nv_bfloat16 g_hhi[2][B * H]; // h hi split, [b][d]
__device__ __align__(16) __nv_bfloat16 g_hlo[2][B * H]; // h lo split
__device__ unsigned g_flagd[GNB * 32];

__global__ void reset_flags_kernel() {
    int i = blockIdx.x * blockDim.x + threadIdx.x;
    if (i < GNB * 32) g_flagd[i] = 0u;
}
__global__ void zero_hbf_kernel() {
    int i = blockIdx.x * blockDim.x + threadIdx.x;
    unsigned* a = (unsigned*)g_hhi;
    unsigned* b = (unsigned*)g_hlo;
    if (i < 65536) a[i] = 0u;
    else if (i < 131072) b[i - 65536] = 0u;
}
__global__ void zero_featsi_kernel() {
    int i = blockIdx.x * blockDim.x + threadIdx.x;
    if (i < S * B) g_featsi[i] = 0u;
}

// ---------------- helpers ----------------
__device__ __forceinline__ float fsig(float x) {
    float e, r;
    asm("ex2.approx.f32 %0, %1;" : "=f"(e) : "f"(x * -1.4426950408889634f));
    asm("rcp.approx.f32 %0, %1;" : "=f"(r) : "f"(e + 1.0f));
    return r;
}
__device__ __forceinline__ float ftanh(float x) {
    float e, r;
    asm("ex2.approx.f32 %0, %1;" : "=f"(e) : "f"(x * 2.8853900817779268f));
    asm("rcp.approx.f32 %0, %1;" : "=f"(r) : "f"(e + 1.0f));
    return fmaf(-2.0f, r, 1.0f);
}
__device__ __forceinline__ unsigned fkey(float f) {
    unsigned u = __float_as_uint(f);
    return (u & 0x80000000u) ? ~u : (u | 0x80000000u);
}
__device__ __forceinline__ float unkey(unsigned k) {
    unsigned u = (k & 0x80000000u) ? (k & 0x7fffffffu) : ~k;
    return __uint_as_float(u);
}
__device__ __forceinline__ unsigned smem_u32(const void* p) {
    unsigned a;
    asm("{ .reg .u64 t; cvta.to.shared.u64 t, %1; cvt.u32.u64 %0, t; }"
        : "=r"(a) : "l"(p));
    return a;
}
__device__ __forceinline__ void ldsm_x4(unsigned* r, unsigned addr) {
    asm volatile("ldmatrix.sync.aligned.m8n8.x4.shared.b16 {%0,%1,%2,%3}, [%4];"
                 : "=r"(r[0]), "=r"(r[1]), "=r"(r[2]), "=r"(r[3]) : "r"(addr));
}
__device__ __forceinline__ void ldsm_x2(unsigned* r, unsigned addr) {
    asm volatile("ldmatrix.sync.aligned.m8n8.x2.shared.b16 {%0,%1}, [%2];"
                 : "=r"(r[0]), "=r"(r[1]) : "r"(addr));
}
__device__ __forceinline__ void mma_bf16(float* d, const unsigned* a,
                                         const unsigned* b) {
    asm volatile(
        "mma.sync.aligned.m16n8k16.row.col.f32.bf16.bf16.f32 "
        "{%0,%1,%2,%3}, {%4,%5,%6,%7}, {%8,%9}, {%0,%1,%2,%3};"
        : "+f"(d[0]), "+f"(d[1]), "+f"(d[2]), "+f"(d[3])
        : "r"(a[0]), "r"(a[1]), "r"(a[2]), "r"(a[3]), "r"(b[0]), "r"(b[1]));
}
__device__ __forceinline__ void cp16(unsigned dst, const void* src) {
    asm volatile("cp.async.cg.shared.global [%0], [%1], 16;"
                 :: "r"(dst), "l"(src));
}

// ---------------- kernel 1: gather + normalize -> bf16 hi/lo ----------------
__global__ void gather_kernel(const int* __restrict__ ends,
                              const float* __restrict__ emb) {
    int w    = (blockIdx.x * blockDim.x + threadIdx.x) >> 5;
    int lane = threadIdx.x & 31;
    if (w >= S * B) return;
    int s = w >> 7, b = w & 127;
    const float* row = emb + (size_t)ends[s * B + b] * D;
    float v[10]; float ss = 0.0f;
#pragma unroll
    for (int i = 0; i < 10; ++i) {
        int d = lane + 32 * i;
        v[i] = (d < D) ? row[d] : 0.0f;
        ss += v[i] * v[i];
    }
#pragma unroll
    for (int m = 16; m; m >>= 1) ss += __shfl_xor_sync(0xffffffffu, ss, m);
    float inv = 1.0f / fmaxf(sqrtf(ss), 1e-8f);
    __nv_bfloat16* dh = g_xhi + ((size_t)b * S + s) * XK;
    __nv_bfloat16* dl = g_xlo + ((size_t)b * S + s) * XK;
#pragma unroll
    for (int i = 0; i < 10; ++i) {
        int d = lane + 32 * i;
        if (d < XK) {
            float val = v[i] * inv;
            __nv_bfloat16 hi = __float2bfloat16(val);
            __nv_bfloat16 lo = __float2bfloat16(val - __bfloat162float(hi));
            dh[d] = hi;
            dl[d] = lo;
        }
    }
}

// ---------------- kernel 2: causal max cosine sims via mma.sync ------------
#define FSTR 624
#define SA_HI 0u
#define SA_LO 39936u
#define SB_HI 79872u
#define SB_LO 119808u
#define FMSMEM 159744

__constant__ int c_it[36] = {0,1,1,2,2,2,3,3,3,3,4,4,4,4,4,5,5,5,5,5,5,
                             6,6,6,6,6,6,6,7,7,7,7,7,7,7,7};
__constant__ int c_jt[36] = {0,0,1,0,1,2,0,1,2,3,0,1,2,3,4,0,1,2,3,4,5,
                             0,1,2,3,4,5,6,0,1,2,3,4,5,6,7};

__global__ void __launch_bounds__(256, 1)
feats_mma_kernel() {
    extern __shared__ char smem[];
    const unsigned sbase = smem_u32(smem);
    const int idx = blockIdx.x, b = blockIdx.y;
    const int it = c_it[idx], jt = c_jt[idx];
    const int tid = threadIdx.x, lane = tid & 31, w = tid >> 5;
    const int i0 = it * 64, j0 = jt * 64;
    const bool diag = (it == jt);

    {
        const __nv_bfloat16* sAh = g_xhi + ((size_t)b * S + i0) * XK;
        const __nv_bfloat16* sAl = g_xlo + ((size_t)b * S + i0) * XK;
        for (int i = tid; i < 64 * 38; i += 256) {
            int row = i / 38, c = i - row * 38;
            unsigned off = (unsigned)(row * FSTR + c * 16);
            cp16(sbase + SA_HI + off, sAh + (size_t)row * XK + c * 8);
            cp16(sbase + SA_LO + off, sAl + (size_t)row * XK + c * 8);
        }
        if (!diag) {
            const __nv_bfloat16* sBh = g_xhi + ((size_t)b * S + j0) * XK;
            const __nv_bfloat16* sBl = g_xlo + ((size_t)b * S + j0) * XK;
            for (int i = tid; i < 64 * 38; i += 256) {
                int row = i / 38, c = i - row * 38;
                unsigned off = (unsigned)(row * FSTR + c * 16);
                cp16(sbase + SB_HI + off, sBh + (size_t)row * XK + c * 8);
                cp16(sbase + SB_LO + off, sBl + (size_t)row * XK + c * 8);
            }
        }
        asm volatile("cp.async.commit_group;");
        asm volatile("cp.async.wait_group 0;");
    }
    __syncthreads();

    const unsigned bBH = diag ? SA_HI : SB_HI;
    const unsigned bBL = diag ? SA_LO : SB_LO;

    const int mt  = w & 3;
    const int ntq = w >> 2;
    const unsigned a_row = (unsigned)((lane & 7) | (lane & 8));
    const unsigned a_off = (unsigned)(mt * 16) * FSTR + a_row * FSTR
                         + (unsigned)(lane >> 4) * 16u;
    const unsigned b_nrow = (unsigned)((lane & 7) + ((lane >> 4) & 1) * 8);
    const unsigned b_off  = (unsigned)(ntq * 32) * FSTR + b_nrow * FSTR
                          + (unsigned)((lane >> 3) & 1) * 16u;

    float acc[4][4];
#pragma unroll
    for (int nt = 0; nt < 4; ++nt)
#pragma unroll
        for (int e = 0; e < 4; ++e) acc[nt][e] = 0.0f;

    for (int kc = 0; kc < 19; ++kc) {
        const unsigned kb = (unsigned)kc * 32u;
        unsigned Ah[4], Al[4];
        ldsm_x4(Ah, sbase + SA_HI + kb + a_off);
        ldsm_x4(Al, sbase + SA_LO + kb + a_off);
        unsigned Bh[8], Bl[8];
        ldsm_x4(Bh,     sbase + bBH + kb + b_off);
        ldsm_x4(Bh + 4, sbase + bBH + kb + b_off + 16u * FSTR);
        ldsm_x4(Bl,     sbase + bBL + kb + b_off);
        ldsm_x4(Bl + 4, sbase + bBL + kb + b_off + 16u * FSTR);
#pragma unroll
        for (int nt = 0; nt < 4; ++nt) {
            mma_bf16(acc[nt], Ah, Bh + nt * 2);
            mma_bf16(acc[nt], Ah, Bl + nt * 2);
            mma_bf16(acc[nt], Al, Bh + nt * 2);
        }
    }

    const int i_lo = i0 + mt * 16 + (lane >> 2);
    const int i_hi = i_lo + 8;
    float rlo = -INFINITY, rhi = -INFINITY;
#pragma unroll
    for (int nt = 0; nt < 4; ++nt) {
        const int jb = j0 + (ntq * 4 + nt) * 8 + (lane & 3) * 2;
        if (jb     < i_lo) rlo = fmaxf(rlo, acc[nt][0]);
        if (jb + 1 < i_lo) rlo = fmaxf(rlo, acc[nt][1]);
        if (jb     < i_hi) rhi = fmaxf(rhi, acc[nt][2]);
        if (jb + 1 < i_hi) rhi = fmaxf(rhi, acc[nt][3]);
    }
#pragma unroll
    for (int m = 1; m <= 2; m <<= 1) {
        rlo = fmaxf(rlo, __shfl_xor_sync(0xffffffffu, rlo, m));
        rhi = fmaxf(rhi, __shfl_xor_sync(0xffffffffu, rhi, m));
    }
    if ((lane & 3) == 0) {
        if (i_lo > 0 && rlo > -INFINITY)
            atomicMax(&g_featsi[i_lo * B + b], fkey(rlo));
        if (rhi > -INFINITY)
            atomicMax(&g_featsi[i_hi * B + b], fkey(rhi));
    }
}

__global__ void feats_convert_kernel() {
    int i = blockIdx.x * blockDim.x + threadIdx.x;
    if (i < S * B) g_feats[i] = (i < B) ? 0.0f : unkey(g_featsi[i]);
}

// ---------------- kernel 3: mma.sync persistent GRU, per-chunk pipeline ----
// 128 blocks = 32 kt (16 k) x 4 bt (32 b); 8 warps split K=512 (64 dims each).
// Chunk ks (16 dims) of warp w is produced exactly by block kt=4w+ks: each
// warp polls per-chunk flags and pipelines staging of chunk ks with the MMA
// of chunk ks-1. Only 2 block-wide syncs per step.
#define SW_HI  0u
#define SW_LO  49920u
#define SH_HI  99840u
#define SH_LO  133120u
#define SPART  166400u
#define SBIAS  218624u
#define SMTOT  219136

__global__ void __launch_bounds__(GNT, 1)
gru_mma_kernel(const float* __restrict__ w_hh,
               const float* __restrict__ w_ih,
               const float* __restrict__ b_ih,
               const float* __restrict__ b_hh) {
    extern __shared__ char smem[];
    const unsigned sbase = smem_u32(smem);
    const int tid  = threadIdx.x;
    const int lane = tid & 31;
    const int w    = tid >> 5;
    const int kt   = blockIdx.x >> 2;
    const int bt   = blockIdx.x & 3;
    const int k0   = kt * 16;
    const int b0   = bt * 32;

    for (int i = tid; i < 48 * 512; i += GNT) {
        int row = i >> 9, d = i & 511;
        int g = row >> 4, kl = row & 15;
        float wv = w_hh[((size_t)(g * H + k0 + kl)) * H + d];
        __nv_bfloat16 hi = __float2bfloat16(wv);
        __nv_bfloat16 lo = __float2bfloat16(wv - __bfloat162float(hi));
        *(__nv_bfloat16*)(smem + SW_HI + row * 1040 + d * 2) = hi;
        *(__nv_bfloat16*)(smem + SW_LO + row * 1040 + d * 2) = lo;
    }
    if (tid < 16) {
        int k = k0 + tid;
        float* bp = (float*)(smem + SBIAS + tid * 32);
        bp[0] = w_ih[k]; bp[1] = w_ih[H + k]; bp[2] = w_ih[2 * H + k];
        bp[3] = b_ih[k] + b_hh[k];
        bp[4] = b_ih[H + k] + b_hh[H + k];
        bp[5] = b_ih[2 * H + k]; bp[6] = b_hh[2 * H + k]; bp[7] = 0.0f;
    }

    const unsigned a_row = (unsigned)((lane & 7) | (lane & 8));
    const unsigned a_off = a_row * 1040u + (unsigned)(lane >> 4) * 16u;
    const int l4 = lane & 15;
    const unsigned b_off = (unsigned)(l4 & 7) * 1040u + (unsigned)((l4 >> 3) & 1) * 16u;
    const unsigned kslice = (unsigned)w * 128u;

    // per-chunk staging addresses: chunk ks covers dims [w*64+ks*16, +16)
    // lane handles 2x 16B per buffer per chunk: idx = j*32+lane, row=idx>>1
    unsigned st_dst[2], st_src[2];
#pragma unroll
    for (int j = 0; j < 2; ++j) {
        int idx = j * 32 + lane;
        int row = idx >> 1, c = idx & 1;
        st_dst[j] = (unsigned)(row * 1040 + w * 128 + c * 16);
        st_src[j] = (unsigned)((b0 + row) * H + w * 64 + c * 8);
    }
    // per-chunk producer flags: block kt_p = 4w+ks, flag index (kt_p*4+bt)*32
    const unsigned* cflag[4];
#pragma unroll
    for (int ks = 0; ks < 4; ++ks)
        cflag[ks] = &g_flagd[(((w << 2) + ks) * 4 + bt) * 32];

    unsigned* myflag = &g_flagd[blockIdx.x * 32];

    const int kl_e = tid >> 4;
    const int bl_e = tid & 15;
    const int be0  = b0 + bl_e * 2;
    float oprev0 = 0.0f, oprev1 = 0.0f;

    __syncthreads();

    for (int t = 0; t < S; ++t) {
        const int sIn  = (t + 1) & 1;
        const int sOut = t & 1;
        const float2 xv = *(const float2*)&g_feats[t * B + be0];
        const __nv_bfloat16* sH = g_hhi[sIn];
        const __nv_bfloat16* sL = g_hlo[sIn];

        float acc[3][4][4];
#pragma unroll
        for (int mt = 0; mt < 3; ++mt)
#pragma unroll
            for (int nt = 0; nt < 4; ++nt)
#pragma unroll
                for (int e = 0; e < 4; ++e) acc[mt][nt][e] = 0.0f;

        // ---- per-chunk pipeline: poll+stage chunk ks, mma chunk ks-1 ----
#pragma unroll
        for (int ks = 0; ks < 4; ++ks) {
            // poll this chunk's single producer flag
            if (t > 0) {
                unsigned v;
                do {
                    asm volatile("ld.acquire.gpu.global.u32 %0, [%1];"
                                 : "=r"(v) : "l"(cflag[ks]) : "memory");
                } while (v < (unsigned)t);
            }
            // stage chunk ks (1KB per buffer: 2 cp16/lane/buffer)
            const unsigned coff_d = (unsigned)ks * 32u;
            const unsigned coff_s = (unsigned)ks * 16u;
#pragma unroll
            for (int j = 0; j < 2; ++j) {
                cp16(sbase + SH_HI + st_dst[j] + coff_d, sH + st_src[j] + coff_s);
                cp16(sbase + SH_LO + st_dst[j] + coff_d, sL + st_src[j] + coff_s);
            }
            asm volatile("cp.async.commit_group;");

            if (ks > 0) {
                // A fragments for chunk ks-1 (static W; overlaps cp.async)
                const unsigned kbp = kslice + (unsigned)(ks - 1) * 32u;
                unsigned Af[3][2][4];
#pragma unroll
                for (int mt = 0; mt < 3; ++mt) {
                    ldsm_x4(Af[mt][0], sbase + SW_HI + (unsigned)mt * 16640u + kbp + a_off);
                    ldsm_x4(Af[mt][1], sbase + SW_LO + (unsigned)mt * 16640u + kbp + a_off);
                }
                asm volatile("cp.async.wait_group 1;");
                __syncwarp();
                unsigned Bf[4][2][2];
#pragma unroll
                for (int nt = 0; nt < 4; ++nt) {
                    ldsm_x2(Bf[nt][0], sbase + SH_HI + (unsigned)nt * 8320u + kbp + b_off);
                    ldsm_x2(Bf[nt][1], sbase + SH_LO + (unsigned)nt * 8320u + kbp + b_off);
                }
#pragma unroll
                for (int mt = 0; mt < 3; ++mt)
#pragma unroll
                    for (int nt = 0; nt < 4; ++nt) {
                        mma_bf16(acc[mt][nt], Af[mt][0], Bf[nt][0]);
                        mma_bf16(acc[mt][nt], Af[mt][0], Bf[nt][1]);
                        mma_bf16(acc[mt][nt], Af[mt][1], Bf[nt][0]);
                    }
            }
        }
        // ---- tail: chunk 3 ----
        {
            const unsigned kbp = kslice + 96u;
            unsigned Af[3][2][4];
#pragma unroll
            for (int mt = 0; mt < 3; ++mt) {
                ldsm_x4(Af[mt][0], sbase + SW_HI + (unsigned)mt * 16640u + kbp + a_off);
                ldsm_x4(Af[mt][1], sbase + SW_LO + (unsigned)mt * 16640u + kbp + a_off);
            }
            asm volatile("cp.async.wait_group 0;");
            __syncwarp();
            unsigned Bf[4][2][2];
#pragma unroll
            for (int nt = 0; nt < 4; ++nt) {
                ldsm_x2(Bf[nt][0], sbase + SH_HI + (unsigned)nt * 8320u + kbp + b_off);
                ldsm_x2(Bf[nt][1], sbase + SH_LO + (unsigned)nt * 8320u + kbp + b_off);
            }
#pragma unroll
            for (int mt = 0; mt < 3; ++mt)
#pragma unroll
                for (int nt = 0; nt < 4; ++nt) {
                    mma_bf16(acc[mt][nt], Af[mt][0], Bf[nt][0]);
                    mma_bf16(acc[mt][nt], Af[mt][0], Bf[nt][1]);
                    mma_bf16(acc[mt][nt], Af[mt][1], Bf[nt][0]);
                }
        }

        // ---- store partials (float2): part[w][48][34] ----
        {
            float* pw = (float*)(smem + SPART) + w * (48 * 34);
            const int r0 = lane >> 2, c0 = (lane & 3) * 2;
#pragma unroll
            for (int mt = 0; mt < 3; ++mt)
#pragma unroll
                for (int nt = 0; nt < 4; ++nt) {
                    int base = (mt * 16 + r0) * 34 + nt * 8 + c0;
                    *(float2*)&pw[base] =
                        make_float2(acc[mt][nt][0], acc[mt][nt][1]);
                    *(float2*)&pw[base + 8 * 34] =
                        make_float2(acc[mt][nt][2], acc[mt][nt][3]);
                }
        }
        __syncthreads();                   // sync #1: partials ready

        // ---- reduce 8 warps + epilogue (thread = 1 k x 2 batches) ----
        {
            const float* part = (const float*)(smem + SPART);
            float ga[3][2] = {{0.f,0.f},{0.f,0.f},{0.f,0.f}};
#pragma unroll
            for (int ww = 0; ww < 8; ++ww)
#pragma unroll
                for (int g = 0; g < 3; ++g) {
                    float2 p = *(const float2*)
                        &part[(ww * 48 + g * 16 + kl_e) * 34 + bl_e * 2];
                    ga[g][0] += p.x; ga[g][1] += p.y;
                }

            const float4 c1 = *(const float4*)(smem + SBIAS + kl_e * 32);
            const float4 c2 = *(const float4*)(smem + SBIAS + kl_e * 32 + 16);
            const int k = k0 + kl_e;

            {
                float r = fsig(fmaf(xv.x, c1.x, c1.w) + ga[0][0]);
                float z = fsig(fmaf(xv.x, c1.y, c2.x) + ga[1][0]);
                float n = ftanh(fmaf(xv.x, c1.z, c2.y) + r * (ga[2][0] + c2.z));
                oprev0 = (1.0f - z) * n + z * oprev0;
            }
            {
                float r = fsig(fmaf(xv.y, c1.x, c1.w) + ga[0][1]);
                float z = fsig(fmaf(xv.y, c1.y, c2.x) + ga[1][1]);
                float n = ftanh(fmaf(xv.y, c1.z, c2.y) + r * (ga[2][1] + c2.z));
                oprev1 = (1.0f - z) * n + z * oprev1;
            }
            __nv_bfloat16 h0 = __float2bfloat16(oprev0);
            __nv_bfloat16 l0 = __float2bfloat16(oprev0 - __bfloat162float(h0));
            __nv_bfloat16 h1 = __float2bfloat16(oprev1);
            __nv_bfloat16 l1 = __float2bfloat16(oprev1 - __bfloat162float(h1));
            g_hhi[sOut][(size_t)be0 * H + k]       = h0;
            g_hlo[sOut][(size_t)be0 * H + k]       = l0;
            g_hhi[sOut][(size_t)(be0 + 1) * H + k] = h1;
            g_hlo[sOut][(size_t)(be0 + 1) * H + k] = l1;
            if (t == S - 1) {
                g_hf[k * B + be0]     = oprev0;
                g_hf[k * B + be0 + 1] = oprev1;
            }
        }

        // ---- publish flag ----
        if (t < S - 1) {
            __syncthreads();               // sync #2: h(t) stores done
            if (tid == 0) {
                asm volatile("st.release.gpu.global.u32 [%0], %1;"
                             :: "l"(myflag), "r"((unsigned)(t + 1)) : "memory");
            }
        }
    }
}

// ---------------- kernel 4: FC head ----------------
__global__ void final_kernel(const float* __restrict__ fcw,
                             const float* __restrict__ fcb,
                             float* __restrict__ out) {
    const float* __restrict__ h = g_hf;
    int b = threadIdx.x;
    float s = 0.0f;
#pragma unroll 8
    for (int d = 0; d < H; ++d) s += h[d * B + b] * fcw[d];
    out[b] = s + fcb[0];
}

// ---------------- launcher ----------------
extern "C" void kernel_launch(void* const* d_in, const int* in_sizes, int n_in,
                              void* d_out, int out_size) {
    const int*   ends = (const int*)  d_in[1];
    const float* emb  = (const float*)d_in[3];
    const float* w_ih = (const float*)d_in[4];
    const float* w_hh = (const float*)d_in[5];
    const float* b_ih = (const float*)d_in[6];
    const float* b_hh = (const float*)d_in[7];
    const float* fc_w = (const float*)d_in[8];
    const float* fc_b = (const float*)d_in[9];
    float* out = (float*)d_out;

    cudaFuncSetAttribute(gru_mma_kernel,
                         cudaFuncAttributeMaxDynamicSharedMemorySize, SMTOT);
    cudaFuncSetAttribute(feats_mma_kernel,
                         cudaFuncAttributeMaxDynamicSharedMemorySize, FMSMEM);

    reset_flags_kernel<<<4, 1024>>>();
    zero_hbf_kernel<<<128, 1024>>>();
    zero_featsi_kernel<<<(S * B + 1023) / 1024, 1024>>>();
    gather_kernel<<<(S * B) / 8, 256>>>(ends, emb);
    feats_mma_kernel<<<dim3(36, 128), 256, FMSMEM>>>();
    feats_convert_kernel<<<(S * B + 1023) / 1024, 1024>>>();
    gru_mma_kernel<<<GNB, GNT, SMTOT>>>(w_hh, w_ih, b_ih, b_hh);
    final_kernel<<<1, B>>>(fc_w, fc_b, out);
}